// round 1
// baseline (speedup 1.0000x reference)
#include <cuda_runtime.h>
#include <cuda_bf16.h>
#include <math_constants.h>

// Problem constants (fixed shapes)
#define NN 100000
#define EE 800000
#define IN_DIM 128
#define OUT_DIM 128
#define MSG_DIM 64
#define TDIM 32
#define HEADS 2
#define CH 64
#define EDGE_DIM 96
#define WC 768   // fused weight cols: [q 128][k 128][v 128][skip 128][p0 96][p1 96][pad 64]

// ------------------------- device scratch -------------------------
__device__ float g_nodes[(size_t)NN * WC];      // q,k,v,(skip unused),p per node
__device__ float g_wcat[IN_DIM * WC];
__device__ float g_bias[WC];
__device__ float g_alpha[(size_t)EE * 2];       // logits, then exp()
__device__ float g_m[NN * 2];
__device__ float g_denom[NN * 2];
__device__ float g_s[(size_t)NN * 192];         // s[n][d][h], d<96, h<2

// ------------------------- helpers -------------------------
__device__ __forceinline__ unsigned long long pk2(float lo, float hi) {
    unsigned long long r;
    asm("mov.b64 %0, {%1,%2};" : "=l"(r) : "f"(lo), "f"(hi));
    return r;
}
__device__ __forceinline__ float2 upk2(unsigned long long v) {
    float2 r;
    asm("mov.b64 {%0,%1}, %2;" : "=f"(r.x), "=f"(r.y) : "l"(v));
    return r;
}
__device__ __forceinline__ unsigned long long ffma2(unsigned long long a, unsigned long long b,
                                                    unsigned long long c) {
    unsigned long long d;
    asm("fma.rn.f32x2 %0, %1, %2, %3;" : "=l"(d) : "l"(a), "l"(b), "l"(c));
    return d;
}
__device__ __forceinline__ void atomicMaxF(float* addr, float v) {
    if (v >= 0.0f) atomicMax((int*)addr, __float_as_int(v));
    else           atomicMin((unsigned int*)addr, __float_as_uint(v));
}

// ------------------------- kernel 0: init scratch -------------------------
__global__ void k_init() {
    int i = blockIdx.x * blockDim.x + threadIdx.x;
    if (i < NN * 192) g_s[i] = 0.0f;
    if (i < NN * 2) {
        g_denom[i] = 0.0f;
        g_m[i] = -CUDART_INF_F;
    }
}

// ------------------------- kernel 1: build fused weights -------------------------
// Wcat[i][c]: c<128 Wq, <256 Wk, <384 Wv, <512 Wskip, <704 M (p = x@M + pb), else 0.
// M_h[i][d] = sum_c Wq[i][h*64+c] * We[d][h*64+c]
__global__ void k_prep(const float* __restrict__ Wq, const float* __restrict__ bq,
                       const float* __restrict__ Wk, const float* __restrict__ bk,
                       const float* __restrict__ Wv, const float* __restrict__ bv,
                       const float* __restrict__ We,
                       const float* __restrict__ Ws, const float* __restrict__ bs) {
    int i = blockIdx.x;  // 0..127 (input dim)
    for (int c = threadIdx.x; c < WC; c += blockDim.x) {
        float w = 0.0f, b = 0.0f;
        if (c < 128)      { w = Wq[i * 128 + c];        b = bq[c]; }
        else if (c < 256) { w = Wk[i * 128 + (c - 128)]; b = bk[c - 128]; }
        else if (c < 384) { w = Wv[i * 128 + (c - 256)]; b = bv[c - 256]; }
        else if (c < 512) { w = Ws[i * 128 + (c - 384)]; b = bs[c - 384]; }
        else if (c < 704) {
            int hd = c - 512;
            int h = hd / 96, d = hd % 96;
            float acc = 0.0f, accb = 0.0f;
            #pragma unroll 8
            for (int cc = 0; cc < 64; ++cc) {
                float we = We[d * 128 + h * 64 + cc];
                acc = fmaf(Wq[i * 128 + h * 64 + cc], we, acc);
                accb = fmaf(bq[h * 64 + cc], we, accb);
            }
            w = acc; b = accb;
        }
        g_wcat[i * WC + c] = w;
        if (i == 0) g_bias[c] = b;
    }
}

// ------------------------- kernel 2: fused node GEMM -------------------------
// Y[N, 768] = x[N,128] @ Wcat[128,768] + bias ; skip cols (384..511) go straight to out.
// 128x128 block tile, 256 threads, 8x8 per thread, packed f32x2 FMA.
__global__ void k_gemm_nodes(const float* __restrict__ x, float* __restrict__ out) {
    extern __shared__ float sm[];
    float* xT = sm;               // [k][r] 128x128
    float* wT = sm + 128 * 128;   // [k][c] 128x128
    const int row0 = blockIdx.x * 128;
    const int col0 = blockIdx.y * 128;
    const int t = threadIdx.x;

    // load x tile, transposed
    for (int i = t; i < 128 * 32; i += 256) {
        int r = i >> 5, k4 = (i & 31) << 2;
        int row = row0 + r;
        float4 v = (row < NN) ? *(const float4*)(x + (size_t)row * 128 + k4)
                              : make_float4(0.f, 0.f, 0.f, 0.f);
        xT[(k4 + 0) * 128 + r] = v.x;
        xT[(k4 + 1) * 128 + r] = v.y;
        xT[(k4 + 2) * 128 + r] = v.z;
        xT[(k4 + 3) * 128 + r] = v.w;
    }
    // load W tile
    for (int i = t; i < 128 * 32; i += 256) {
        int k = i >> 5, c4 = (i & 31) << 2;
        *(float4*)(wT + k * 128 + c4) = *(const float4*)(g_wcat + k * WC + col0 + c4);
    }
    __syncthreads();

    const int tx = t & 15, ty = t >> 4;
    const int r0 = ty * 8, c0 = tx * 8;

    unsigned long long acc[4][8];
    #pragma unroll
    for (int i = 0; i < 4; ++i)
        #pragma unroll
        for (int j = 0; j < 8; ++j) acc[i][j] = 0ULL;

    #pragma unroll 4
    for (int k = 0; k < 128; ++k) {
        float4 a0 = *(float4*)(xT + k * 128 + r0);
        float4 a1 = *(float4*)(xT + k * 128 + r0 + 4);
        float4 b0 = *(float4*)(wT + k * 128 + c0);
        float4 b1 = *(float4*)(wT + k * 128 + c0 + 4);
        unsigned long long A[4] = {pk2(a0.x, a0.y), pk2(a0.z, a0.w),
                                   pk2(a1.x, a1.y), pk2(a1.z, a1.w)};
        float bs8[8] = {b0.x, b0.y, b0.z, b0.w, b1.x, b1.y, b1.z, b1.w};
        #pragma unroll
        for (int j = 0; j < 8; ++j) {
            unsigned long long B = pk2(bs8[j], bs8[j]);
            #pragma unroll
            for (int i = 0; i < 4; ++i) acc[i][j] = ffma2(A[i], B, acc[i][j]);
        }
    }

    #pragma unroll
    for (int j = 0; j < 8; ++j) {
        int col = col0 + c0 + j;
        float bias = g_bias[col];
        #pragma unroll
        for (int i = 0; i < 4; ++i) {
            float2 v = upk2(acc[i][j]);
            v.x += bias; v.y += bias;
            int r = row0 + r0 + 2 * i;
            if (col < 384 || (col >= 512 && col < 704)) {
                if (r < NN)     g_nodes[(size_t)r * WC + col] = v.x;
                if (r + 1 < NN) g_nodes[(size_t)(r + 1) * WC + col] = v.y;
            } else if (col < 512) {
                int oc = col - 384;
                if (r < NN)     out[(size_t)r * 128 + oc] = v.x;
                if (r + 1 < NN) out[(size_t)(r + 1) * 128 + oc] = v.y;
            }
        }
    }
}

// ------------------------- kernel 3: per-edge logits + segment max -------------------------
// alpha[e,h] = ( q[dst]·k[src] |_h + p[dst,h,:]·edge_attr[e,:] ) / 8
__global__ void k_alpha(const int* __restrict__ ei, const float* __restrict__ last_update,
                        const float* __restrict__ tvec, const float* __restrict__ msg,
                        const float* __restrict__ time_w, const float* __restrict__ time_b) {
    int wid = (blockIdx.x * blockDim.x + threadIdx.x) >> 5;
    int lane = threadIdx.x & 31;
    if (wid >= EE) return;
    int src = ei[wid];
    int dst = ei[EE + wid];
    float rel_t = last_update[src] - tvec[wid];

    const float* qp = g_nodes + (size_t)dst * WC;
    const float* kp = g_nodes + (size_t)src * WC + 128;
    float4 q4 = *(const float4*)(qp + lane * 4);
    float4 k4 = *(const float4*)(kp + lane * 4);
    float qk = q4.x * k4.x + q4.y * k4.y + q4.z * k4.z + q4.w * k4.w;
    #pragma unroll
    for (int o = 8; o; o >>= 1) qk += __shfl_xor_sync(0xffffffffu, qk, o);
    // lanes 0..15 now hold head-0 sum, lanes 16..31 head-1 sum

    float ea0 = cosf(fmaf(rel_t, time_w[lane], time_b[lane]));
    float ea1 = msg[(size_t)wid * 64 + lane];
    float ea2 = msg[(size_t)wid * 64 + 32 + lane];

    const float* pp = g_nodes + (size_t)dst * WC + 512;
    float pe0 = ea0 * pp[lane] + ea1 * pp[lane + 32] + ea2 * pp[lane + 64];
    float pe1 = ea0 * pp[96 + lane] + ea1 * pp[96 + lane + 32] + ea2 * pp[96 + lane + 64];
    #pragma unroll
    for (int o = 16; o; o >>= 1) {
        pe0 += __shfl_xor_sync(0xffffffffu, pe0, o);
        pe1 += __shfl_xor_sync(0xffffffffu, pe1, o);
    }

    if ((lane & 15) == 0) {
        int h = lane >> 4;
        float pea = h ? pe1 : pe0;
        float alpha = (qk + pea) * 0.125f;
        g_alpha[(size_t)wid * 2 + h] = alpha;
        atomicMaxF(&g_m[dst * 2 + h], alpha);
    }
}

// ------------------------- kernel 4: exp + denom -------------------------
__global__ void k_expdenom(const int* __restrict__ ei) {
    int i = blockIdx.x * blockDim.x + threadIdx.x;
    if (i >= EE * 2) return;
    int e = i >> 1, h = i & 1;
    int dst = ei[EE + e];
    float m = g_m[dst * 2 + h];
    float ex = expf(g_alpha[i] - m);
    g_alpha[i] = ex;
    atomicAdd(&g_denom[dst * 2 + h], ex);
}

// ------------------------- kernel 5: weighted scatter -------------------------
// out[dst] += a_h * v[src]   and   s[dst,d,h] += a_h * edge_attr[d]
__global__ void k_scatter(const int* __restrict__ ei, const float* __restrict__ last_update,
                          const float* __restrict__ tvec, const float* __restrict__ msg,
                          const float* __restrict__ time_w, const float* __restrict__ time_b,
                          float* __restrict__ out) {
    int wid = (blockIdx.x * blockDim.x + threadIdx.x) >> 5;
    int lane = threadIdx.x & 31;
    if (wid >= EE) return;
    int src = ei[wid];
    int dst = ei[EE + wid];
    float rel_t = last_update[src] - tvec[wid];

    float2 ex = *(const float2*)(g_alpha + (size_t)wid * 2);
    float2 dn = *(const float2*)(g_denom + (size_t)dst * 2);
    float a0 = ex.x / (dn.x + 1e-16f);
    float a1 = ex.y / (dn.y + 1e-16f);

    float4 v4 = *(const float4*)(g_nodes + (size_t)src * WC + 256 + lane * 4);
    float ah = (lane < 16) ? a0 : a1;
    atomicAdd((float4*)(out + (size_t)dst * 128 + lane * 4),
              make_float4(v4.x * ah, v4.y * ah, v4.z * ah, v4.w * ah));

    float ea0 = cosf(fmaf(rel_t, time_w[lane], time_b[lane]));
    float ea1 = msg[(size_t)wid * 64 + lane];
    float ea2 = msg[(size_t)wid * 64 + 32 + lane];
    float* sp = g_s + (size_t)dst * 192;
    atomicAdd((float2*)(sp + lane * 2),        make_float2(ea0 * a0, ea0 * a1));
    atomicAdd((float2*)(sp + (lane + 32) * 2), make_float2(ea1 * a0, ea1 * a1));
    atomicAdd((float2*)(sp + (lane + 64) * 2), make_float2(ea2 * a0, ea2 * a1));
}

// ------------------------- kernel 6: out += s @ We -------------------------
// out[n,c] += sum_d s[n,d,h(c)] * We[d,c], h(c)=c/64. 128-row tile, 256 threads, 8x8/thread.
__global__ void k_final(const float* __restrict__ We, float* __restrict__ out) {
    extern __shared__ float sm[];
    float* sS = sm;              // [d][h][r]: 96*2*128
    float* sW = sm + 96 * 256;   // [d][c]:   96*128
    const int row0 = blockIdx.x * 128;
    const int t = threadIdx.x;

    for (int i = t; i < 96 * 32; i += 256) {
        int d = i >> 5, c4 = (i & 31) << 2;
        *(float4*)(sW + d * 128 + c4) = *(const float4*)(We + d * 128 + c4);
    }
    for (int i = t; i < 128 * 96; i += 256) {
        int r = i / 96, d = i % 96;
        int row = row0 + r;
        float2 v = (row < NN) ? *(const float2*)(g_s + (size_t)row * 192 + d * 2)
                              : make_float2(0.f, 0.f);
        sS[d * 256 + r] = v.x;
        sS[d * 256 + 128 + r] = v.y;
    }
    __syncthreads();

    const int tx = t & 15, ty = t >> 4;
    const int r0 = ty * 8, c0 = tx * 8;
    const int h = c0 >> 6;

    unsigned long long acc[4][8];
    #pragma unroll
    for (int i = 0; i < 4; ++i)
        #pragma unroll
        for (int j = 0; j < 8; ++j) acc[i][j] = 0ULL;

    #pragma unroll 4
    for (int d = 0; d < 96; ++d) {
        float4 a0 = *(float4*)(sS + d * 256 + h * 128 + r0);
        float4 a1 = *(float4*)(sS + d * 256 + h * 128 + r0 + 4);
        float4 b0 = *(float4*)(sW + d * 128 + c0);
        float4 b1 = *(float4*)(sW + d * 128 + c0 + 4);
        unsigned long long A[4] = {pk2(a0.x, a0.y), pk2(a0.z, a0.w),
                                   pk2(a1.x, a1.y), pk2(a1.z, a1.w)};
        float bs8[8] = {b0.x, b0.y, b0.z, b0.w, b1.x, b1.y, b1.z, b1.w};
        #pragma unroll
        for (int j = 0; j < 8; ++j) {
            unsigned long long B = pk2(bs8[j], bs8[j]);
            #pragma unroll
            for (int i = 0; i < 4; ++i) acc[i][j] = ffma2(A[i], B, acc[i][j]);
        }
    }

    #pragma unroll
    for (int j = 0; j < 8; ++j) {
        int col = c0 + j;
        #pragma unroll
        for (int i = 0; i < 4; ++i) {
            float2 v = upk2(acc[i][j]);
            int r = row0 + r0 + 2 * i;
            if (r < NN)     out[(size_t)r * 128 + col] += v.x;
            if (r + 1 < NN) out[(size_t)(r + 1) * 128 + col] += v.y;
        }
    }
}

// ------------------------- launch -------------------------
extern "C" void kernel_launch(void* const* d_in, const int* in_sizes, int n_in,
                              void* d_out, int out_size) {
    const float* x   = (const float*)d_in[0];
    const float* lu  = (const float*)d_in[1];
    const float* tv  = (const float*)d_in[2];
    const float* msg = (const float*)d_in[3];
    const int*   ei  = (const int*)d_in[4];
    const float* tw  = (const float*)d_in[5];
    const float* tb  = (const float*)d_in[6];
    const float* Wq  = (const float*)d_in[7];
    const float* bq  = (const float*)d_in[8];
    const float* Wk  = (const float*)d_in[9];
    const float* bk  = (const float*)d_in[10];
    const float* Wv  = (const float*)d_in[11];
    const float* bv  = (const float*)d_in[12];
    const float* We  = (const float*)d_in[13];
    const float* Ws  = (const float*)d_in[14];
    const float* bs  = (const float*)d_in[15];
    float* out = (float*)d_out;

    static bool attr_done = false;
    if (!attr_done) {
        cudaFuncSetAttribute(k_gemm_nodes, cudaFuncAttributeMaxDynamicSharedMemorySize,
                             128 * 128 * 2 * 4);
        cudaFuncSetAttribute(k_final, cudaFuncAttributeMaxDynamicSharedMemorySize,
                             (96 * 256 + 96 * 128) * 4);
        attr_done = true;
    }

    // 1) init scratch (m=-inf, denom=0, s=0)
    {
        int total = NN * 192;
        k_init<<<(total + 255) / 256, 256>>>();
    }
    // 2) fused weights
    k_prep<<<128, 256>>>(Wq, bq, Wk, bk, Wv, bv, We, Ws, bs);
    // 3) node GEMM (also writes skip -> out)
    {
        dim3 grid((NN + 127) / 128, WC / 128);
        k_gemm_nodes<<<grid, 256, 128 * 128 * 2 * 4>>>(x, out);
    }
    // 4) logits + segment max
    k_alpha<<<EE / 8, 256>>>(ei, lu, tv, msg, tw, tb);
    // 5) exp + denom
    k_expdenom<<<(EE * 2 + 255) / 256, 256>>>(ei);
    // 6) scatter
    k_scatter<<<EE / 8, 256>>>(ei, lu, tv, msg, tw, tb, out);
    // 7) out += s @ We
    k_final<<<(NN + 127) / 128, 256, (96 * 256 + 96 * 128) * 4>>>(We, out);
}

// round 3
// speedup vs baseline: 1.5283x; 1.5283x over previous
#include <cuda_runtime.h>
#include <cuda_bf16.h>
#include <math_constants.h>
#include <cstdint>

// Problem constants (fixed shapes)
#define NN 100000
#define EE 800000
#define WC 768   // fused weight cols: [q 128][k 128][v 128][skip 128][p0 96][p1 96][pad 64]

// ------------------------- device scratch -------------------------
__device__ float g_dst[(size_t)NN * 320];            // per-node dst data: q[128], p[192]
__device__ float g_src[(size_t)NN * 256];            // per-node src data: k[128], v[128]
__device__ __nv_bfloat16 g_whT[WC * 128];            // W^T hi (bf16), [col][k]
__device__ __nv_bfloat16 g_wlT[WC * 128];            // W^T lo (bf16)
__device__ float g_bias[WC];
__device__ float g_alpha[(size_t)EE * 2];            // logits, then exp()
__device__ float g_m[NN * 2];
__device__ float g_denom[NN * 2];
__device__ float g_s[(size_t)NN * 192];              // s[n][d][h], d<96, h<2

// ------------------------- generic helpers -------------------------
__device__ __forceinline__ unsigned long long pk2(float lo, float hi) {
    unsigned long long r;
    asm("mov.b64 %0, {%1,%2};" : "=l"(r) : "f"(lo), "f"(hi));
    return r;
}
__device__ __forceinline__ float2 upk2(unsigned long long v) {
    float2 r;
    asm("mov.b64 {%0,%1}, %2;" : "=f"(r.x), "=f"(r.y) : "l"(v));
    return r;
}
__device__ __forceinline__ unsigned long long ffma2(unsigned long long a, unsigned long long b,
                                                    unsigned long long c) {
    unsigned long long d;
    asm("fma.rn.f32x2 %0, %1, %2, %3;" : "=l"(d) : "l"(a), "l"(b), "l"(c));
    return d;
}
__device__ __forceinline__ void atomicMaxF(float* addr, float v) {
    if (v >= 0.0f) atomicMax((int*)addr, __float_as_int(v));
    else           atomicMin((unsigned int*)addr, __float_as_uint(v));
}
__device__ __forceinline__ uint32_t smem_u32(const void* p) {
    uint32_t a;
    asm("{ .reg .u64 t; cvta.to.shared.u64 t, %1; cvt.u32.u64 %0, t; }" : "=r"(a) : "l"(p));
    return a;
}
__device__ __forceinline__ void ldsm4(uint32_t* r, uint32_t addr) {
    asm volatile("ldmatrix.sync.aligned.m8n8.x4.shared.b16 {%0,%1,%2,%3}, [%4];"
                 : "=r"(r[0]), "=r"(r[1]), "=r"(r[2]), "=r"(r[3]) : "r"(addr));
}
__device__ __forceinline__ void mma16816(float* c, const uint32_t* a, uint32_t b0, uint32_t b1) {
    asm volatile(
        "mma.sync.aligned.m16n8k16.row.col.f32.bf16.bf16.f32 "
        "{%0,%1,%2,%3}, {%4,%5,%6,%7}, {%8,%9}, {%0,%1,%2,%3};"
        : "+f"(c[0]), "+f"(c[1]), "+f"(c[2]), "+f"(c[3])
        : "r"(a[0]), "r"(a[1]), "r"(a[2]), "r"(a[3]), "r"(b0), "r"(b1));
}

// ------------------------- kernel 0: init scratch -------------------------
__global__ void k_init() {
    int i = blockIdx.x * blockDim.x + threadIdx.x;
    if (i < NN * 192) g_s[i] = 0.0f;
    if (i < NN * 2) {
        g_denom[i] = 0.0f;
        g_m[i] = -CUDART_INF_F;
    }
}

// ------------------------- kernel 1: fused weights (transposed, bf16 hi/lo) ----
// Wcat[k][c]: c<128 Wq, <256 Wk, <384 Wv, <512 Wskip, <704 M (p = x@M + pb), else 0.
// M_h[k][d] = sum_c Wq[k][h*64+c] * We[d][h*64+c]
__global__ void k_prep(const float* __restrict__ Wq, const float* __restrict__ bq,
                       const float* __restrict__ Wk, const float* __restrict__ bk,
                       const float* __restrict__ Wv, const float* __restrict__ bv,
                       const float* __restrict__ We,
                       const float* __restrict__ Ws, const float* __restrict__ bs) {
    int i = blockIdx.x;  // 0..127 (input dim k)
    for (int c = threadIdx.x; c < WC; c += blockDim.x) {
        float w = 0.0f, b = 0.0f;
        if (c < 128)      { w = Wq[i * 128 + c];         b = bq[c]; }
        else if (c < 256) { w = Wk[i * 128 + (c - 128)]; b = bk[c - 128]; }
        else if (c < 384) { w = Wv[i * 128 + (c - 256)]; b = bv[c - 256]; }
        else if (c < 512) { w = Ws[i * 128 + (c - 384)]; b = bs[c - 384]; }
        else if (c < 704) {
            int hd = c - 512;
            int h = hd / 96, d = hd % 96;
            float acc = 0.0f, accb = 0.0f;
            #pragma unroll 8
            for (int cc = 0; cc < 64; ++cc) {
                float we = We[d * 128 + h * 64 + cc];
                acc = fmaf(Wq[i * 128 + h * 64 + cc], we, acc);
                accb = fmaf(bq[h * 64 + cc], we, accb);
            }
            w = acc; b = accb;
        }
        __nv_bfloat16 hi = __float2bfloat16(w);
        __nv_bfloat16 lo = __float2bfloat16(w - __bfloat162float(hi));
        g_whT[c * 128 + i] = hi;
        g_wlT[c * 128 + i] = lo;
        if (i == 0) g_bias[c] = b;
    }
}

// ------------------------- kernel 2: HMMA node GEMM -------------------------
// Y[N,768] = x[N,128] @ Wcat + bias, 3-term bf16 split on mma.sync.m16n8k16.
// CTA = 128 rows x all 768 cols. A resident in smem; B streamed per 128-col chunk
// in two K-halves of 64. 8 warps, warp tile 64x32.
#define A_STRIDE 136                      // bf16 elems per row (128 + 8 pad)
#define B_STRIDE 72                       // bf16 elems per row (64 + 8 pad)
#define SZ_A (128 * A_STRIDE * 2)         // 34816 bytes
#define SZ_B (128 * B_STRIDE * 2)         // 18432 bytes
#define SM_A_HI 0
#define SM_A_LO (SZ_A)
#define SM_B_HI (2 * SZ_A)
#define SM_B_LO (2 * SZ_A + SZ_B)
#define SM_BIAS (2 * SZ_A + 2 * SZ_B)
#define SM_TOT  (SM_BIAS + WC * 4)        // 112640 bytes

__global__ void __launch_bounds__(256, 1) k_gemm_mma(const float* __restrict__ x,
                                                     float* __restrict__ out) {
    extern __shared__ char smem[];
    const uint32_t sb = smem_u32(smem);
    const int tid = threadIdx.x, wid = tid >> 5, lane = tid & 31;
    const int row0 = blockIdx.x * 128;

    float* sbias = (float*)(smem + SM_BIAS);
    for (int i = tid; i < WC; i += 256) sbias[i] = g_bias[i];

    // Load x tile [128 x 128], split bf16 hi/lo into padded smem.
    for (int i = tid; i < 128 * 32; i += 256) {
        int r = i >> 5, k4 = (i & 31) << 2;
        int row = row0 + r;
        float4 v = (row < NN) ? *(const float4*)(x + (size_t)row * 128 + k4)
                              : make_float4(0.f, 0.f, 0.f, 0.f);
        __nv_bfloat16 h0 = __float2bfloat16(v.x), h1 = __float2bfloat16(v.y);
        __nv_bfloat16 h2 = __float2bfloat16(v.z), h3 = __float2bfloat16(v.w);
        __nv_bfloat16 l0 = __float2bfloat16(v.x - __bfloat162float(h0));
        __nv_bfloat16 l1 = __float2bfloat16(v.y - __bfloat162float(h1));
        __nv_bfloat16 l2 = __float2bfloat16(v.z - __bfloat162float(h2));
        __nv_bfloat16 l3 = __float2bfloat16(v.w - __bfloat162float(h3));
        __nv_bfloat162 ph0(h0, h1), ph1(h2, h3), pl0(l0, l1), pl1(l2, l3);
        uint32_t off = (uint32_t)(r * (A_STRIDE * 2) + k4 * 2);
        *(uint2*)(smem + SM_A_HI + off) = make_uint2(*(uint32_t*)&ph0, *(uint32_t*)&ph1);
        *(uint2*)(smem + SM_A_LO + off) = make_uint2(*(uint32_t*)&pl0, *(uint32_t*)&pl1);
    }

    const int wm = wid & 1, wn = wid >> 1;       // warp grid 2 x 4
    const int rw = wm * 64, cw = wn * 32;
    // ldmatrix per-thread row offsets
    const uint32_t a_off = (uint32_t)((rw + (lane & 15)) * (A_STRIDE * 2) + (lane >> 4) * 16);
    const uint32_t b_off = (uint32_t)((cw + (lane & 15)) * (B_STRIDE * 2) + (lane >> 4) * 16);

    const int trow = lane >> 2;                   // 0..7
    const int tcol = (lane & 3) * 2;

    for (int chunk = 0; chunk < 6; ++chunk) {
        float acc[4][4][4];
        #pragma unroll
        for (int i = 0; i < 4; ++i)
            #pragma unroll
            for (int j = 0; j < 4; ++j)
                #pragma unroll
                for (int q = 0; q < 4; ++q) acc[i][j][q] = 0.0f;

        #pragma unroll
        for (int kh = 0; kh < 2; ++kh) {
            __syncthreads();   // previous users of B smem done
            // Load B K-half: 128 cols x 64 k, hi + lo
            for (int i = tid; i < 128 * 8; i += 256) {
                int c = i >> 3, seg = i & 7;
                size_t gsrc = (size_t)(chunk * 128 + c) * 128 + kh * 64 + seg * 8;
                uint32_t doff = (uint32_t)(c * (B_STRIDE * 2) + seg * 16);
                *(uint4*)(smem + SM_B_HI + doff) = *(const uint4*)(g_whT + gsrc);
                *(uint4*)(smem + SM_B_LO + doff) = *(const uint4*)(g_wlT + gsrc);
            }
            __syncthreads();

            #pragma unroll
            for (int term = 0; term < 3; ++term) {
                const uint32_t sA = sb + ((term == 2) ? SM_A_LO : SM_A_HI) + kh * 128;
                const uint32_t sB = sb + ((term == 1) ? SM_B_LO : SM_B_HI);
                #pragma unroll
                for (int ks = 0; ks < 4; ++ks) {
                    uint32_t a[4][4], b[2][4];
                    #pragma unroll
                    for (int i = 0; i < 4; ++i)
                        ldsm4(a[i], sA + a_off + i * (16 * A_STRIDE * 2) + ks * 32);
                    #pragma unroll
                    for (int j16 = 0; j16 < 2; ++j16)
                        ldsm4(b[j16], sB + b_off + j16 * (16 * B_STRIDE * 2) + ks * 32);
                    #pragma unroll
                    for (int i = 0; i < 4; ++i) {
                        mma16816(acc[i][0], a[i], b[0][0], b[0][2]);
                        mma16816(acc[i][1], a[i], b[0][1], b[0][3]);
                        mma16816(acc[i][2], a[i], b[1][0], b[1][2]);
                        mma16816(acc[i][3], a[i], b[1][1], b[1][3]);
                    }
                }
            }
        }

        // Epilogue: route chunk's 128 cols. bases: q|k|v|skip|p
        float* bp; int stride, sub;
        switch (chunk) {
            case 0:  bp = g_dst; stride = 320; sub = 0;   break;
            case 1:
            case 2:  bp = g_src; stride = 256; sub = 128; break;
            case 3:  bp = out;   stride = 128; sub = 384; break;
            default: bp = g_dst; stride = 320; sub = 384; break;  // p region (offset 128..319)
        }
        #pragma unroll
        for (int i = 0; i < 4; ++i) {
            int r = row0 + rw + i * 16 + trow;
            #pragma unroll
            for (int j = 0; j < 4; ++j) {
                int G = chunk * 128 + cw + j * 8 + tcol;
                if (G >= 704) continue;
                float b0 = sbias[G], b1 = sbias[G + 1];
                if (r < NN) {
                    float2 v = make_float2(acc[i][j][0] + b0, acc[i][j][1] + b1);
                    *(float2*)(bp + (size_t)r * stride + (G - sub)) = v;
                }
                if (r + 8 < NN) {
                    float2 v = make_float2(acc[i][j][2] + b0, acc[i][j][3] + b1);
                    *(float2*)(bp + (size_t)(r + 8) * stride + (G - sub)) = v;
                }
            }
        }
    }
}

// ------------------------- kernel 3: per-edge logits + segment max -------------------------
__global__ void k_alpha(const int* __restrict__ ei, const float* __restrict__ last_update,
                        const float* __restrict__ tvec, const float* __restrict__ msg,
                        const float* __restrict__ time_w, const float* __restrict__ time_b) {
    int wid = (blockIdx.x * blockDim.x + threadIdx.x) >> 5;
    int lane = threadIdx.x & 31;
    if (wid >= EE) return;
    int src = ei[wid];
    int dst = ei[EE + wid];
    float rel_t = last_update[src] - tvec[wid];

    const float* qp = g_dst + (size_t)dst * 320;
    const float* kp = g_src + (size_t)src * 256;
    float4 q4 = *(const float4*)(qp + lane * 4);
    float4 k4 = *(const float4*)(kp + lane * 4);
    float qk = q4.x * k4.x + q4.y * k4.y + q4.z * k4.z + q4.w * k4.w;
    #pragma unroll
    for (int o = 8; o; o >>= 1) qk += __shfl_xor_sync(0xffffffffu, qk, o);
    // lanes 0..15 hold head-0 sum, lanes 16..31 head-1 sum

    float ea0 = cosf(fmaf(rel_t, time_w[lane], time_b[lane]));
    float ea1 = msg[(size_t)wid * 64 + lane];
    float ea2 = msg[(size_t)wid * 64 + 32 + lane];

    const float* pp = g_dst + (size_t)dst * 320 + 128;
    float pe0 = ea0 * pp[lane] + ea1 * pp[lane + 32] + ea2 * pp[lane + 64];
    float pe1 = ea0 * pp[96 + lane] + ea1 * pp[96 + lane + 32] + ea2 * pp[96 + lane + 64];
    #pragma unroll
    for (int o = 16; o; o >>= 1) {
        pe0 += __shfl_xor_sync(0xffffffffu, pe0, o);
        pe1 += __shfl_xor_sync(0xffffffffu, pe1, o);
    }

    if ((lane & 15) == 0) {
        int h = lane >> 4;
        float pea = h ? pe1 : pe0;
        float alpha = (qk + pea) * 0.125f;
        g_alpha[(size_t)wid * 2 + h] = alpha;
        atomicMaxF(&g_m[dst * 2 + h], alpha);
    }
}

// ------------------------- kernel 4: exp + denom -------------------------
__global__ void k_expdenom(const int* __restrict__ ei) {
    int i = blockIdx.x * blockDim.x + threadIdx.x;
    if (i >= EE * 2) return;
    int e = i >> 1, h = i & 1;
    int dst = ei[EE + e];
    float m = g_m[dst * 2 + h];
    float ex = expf(g_alpha[i] - m);
    g_alpha[i] = ex;
    atomicAdd(&g_denom[dst * 2 + h], ex);
}

// ------------------------- kernel 5: weighted scatter -------------------------
__global__ void k_scatter(const int* __restrict__ ei, const float* __restrict__ last_update,
                          const float* __restrict__ tvec, const float* __restrict__ msg,
                          const float* __restrict__ time_w, const float* __restrict__ time_b,
                          float* __restrict__ out) {
    int wid = (blockIdx.x * blockDim.x + threadIdx.x) >> 5;
    int lane = threadIdx.x & 31;
    if (wid >= EE) return;
    int src = ei[wid];
    int dst = ei[EE + wid];
    float rel_t = last_update[src] - tvec[wid];

    float2 ex = *(const float2*)(g_alpha + (size_t)wid * 2);
    float2 dn = *(const float2*)(g_denom + (size_t)dst * 2);
    float a0 = ex.x / (dn.x + 1e-16f);
    float a1 = ex.y / (dn.y + 1e-16f);

    float4 v4 = *(const float4*)(g_src + (size_t)src * 256 + 128 + lane * 4);
    float ah = (lane < 16) ? a0 : a1;
    atomicAdd((float4*)(out + (size_t)dst * 128 + lane * 4),
              make_float4(v4.x * ah, v4.y * ah, v4.z * ah, v4.w * ah));

    float ea0 = cosf(fmaf(rel_t, time_w[lane], time_b[lane]));
    float ea1 = msg[(size_t)wid * 64 + lane];
    float ea2 = msg[(size_t)wid * 64 + 32 + lane];
    float* sp = g_s + (size_t)dst * 192;
    atomicAdd((float2*)(sp + lane * 2),        make_float2(ea0 * a0, ea0 * a1));
    atomicAdd((float2*)(sp + (lane + 32) * 2), make_float2(ea1 * a0, ea1 * a1));
    atomicAdd((float2*)(sp + (lane + 64) * 2), make_float2(ea2 * a0, ea2 * a1));
}

// ------------------------- kernel 6: out += s @ We -------------------------
__global__ void k_final(const float* __restrict__ We, float* __restrict__ out) {
    extern __shared__ float sm[];
    float* sS = sm;              // [d][h][r]: 96*2*128
    float* sW = sm + 96 * 256;   // [d][c]:   96*128
    const int row0 = blockIdx.x * 128;
    const int t = threadIdx.x;

    for (int i = t; i < 96 * 32; i += 256) {
        int d = i >> 5, c4 = (i & 31) << 2;
        *(float4*)(sW + d * 128 + c4) = *(const float4*)(We + d * 128 + c4);
    }
    for (int i = t; i < 128 * 96; i += 256) {
        int r = i / 96, d = i % 96;
        int row = row0 + r;
        float2 v = (row < NN) ? *(const float2*)(g_s + (size_t)row * 192 + d * 2)
                              : make_float2(0.f, 0.f);
        sS[d * 256 + r] = v.x;
        sS[d * 256 + 128 + r] = v.y;
    }
    __syncthreads();

    const int tx = t & 15, ty = t >> 4;
    const int r0 = ty * 8, c0 = tx * 8;
    const int h = c0 >> 6;

    unsigned long long acc[4][8];
    #pragma unroll
    for (int i = 0; i < 4; ++i)
        #pragma unroll
        for (int j = 0; j < 8; ++j) acc[i][j] = 0ULL;

    #pragma unroll 4
    for (int d = 0; d < 96; ++d) {
        float4 a0 = *(float4*)(sS + d * 256 + h * 128 + r0);
        float4 a1 = *(float4*)(sS + d * 256 + h * 128 + r0 + 4);
        float4 b0 = *(float4*)(sW + d * 128 + c0);
        float4 b1 = *(float4*)(sW + d * 128 + c0 + 4);
        unsigned long long A[4] = {pk2(a0.x, a0.y), pk2(a0.z, a0.w),
                                   pk2(a1.x, a1.y), pk2(a1.z, a1.w)};
        float bs8[8] = {b0.x, b0.y, b0.z, b0.w, b1.x, b1.y, b1.z, b1.w};
        #pragma unroll
        for (int j = 0; j < 8; ++j) {
            unsigned long long B = pk2(bs8[j], bs8[j]);
            #pragma unroll
            for (int i = 0; i < 4; ++i) acc[i][j] = ffma2(A[i], B, acc[i][j]);
        }
    }

    #pragma unroll
    for (int j = 0; j < 8; ++j) {
        int col = c0 + j;
        #pragma unroll
        for (int i = 0; i < 4; ++i) {
            float2 v = upk2(acc[i][j]);
            int r = row0 + r0 + 2 * i;
            if (r < NN)     out[(size_t)r * 128 + col] += v.x;
            if (r + 1 < NN) out[(size_t)(r + 1) * 128 + col] += v.y;
        }
    }
}

// ------------------------- launch -------------------------
extern "C" void kernel_launch(void* const* d_in, const int* in_sizes, int n_in,
                              void* d_out, int out_size) {
    const float* x   = (const float*)d_in[0];
    const float* lu  = (const float*)d_in[1];
    const float* tv  = (const float*)d_in[2];
    const float* msg = (const float*)d_in[3];
    const int*   ei  = (const int*)d_in[4];
    const float* tw  = (const float*)d_in[5];
    const float* tb  = (const float*)d_in[6];
    const float* Wq  = (const float*)d_in[7];
    const float* bq  = (const float*)d_in[8];
    const float* Wk  = (const float*)d_in[9];
    const float* bk  = (const float*)d_in[10];
    const float* Wv  = (const float*)d_in[11];
    const float* bv  = (const float*)d_in[12];
    const float* We  = (const float*)d_in[13];
    const float* Ws  = (const float*)d_in[14];
    const float* bs  = (const float*)d_in[15];
    float* out = (float*)d_out;

    static bool attr_done = false;
    if (!attr_done) {
        cudaFuncSetAttribute(k_gemm_mma, cudaFuncAttributeMaxDynamicSharedMemorySize, SM_TOT);
        cudaFuncSetAttribute(k_final, cudaFuncAttributeMaxDynamicSharedMemorySize,
                             (96 * 256 + 96 * 128) * 4);
        attr_done = true;
    }

    // 1) init scratch (m=-inf, denom=0, s=0)
    k_init<<<(NN * 192 + 255) / 256, 256>>>();
    // 2) fused weights (transposed, bf16 hi/lo split)
    k_prep<<<128, 256>>>(Wq, bq, Wk, bk, Wv, bv, We, Ws, bs);
    // 3) HMMA node GEMM (writes g_dst q/p, g_src k/v, skip->out)
    k_gemm_mma<<<(NN + 127) / 128, 256, SM_TOT>>>(x, out);
    // 4) logits + segment max
    k_alpha<<<EE / 8, 256>>>(ei, lu, tv, msg, tw, tb);
    // 5) exp + denom
    k_expdenom<<<(EE * 2 + 255) / 256, 256>>>(ei);
    // 6) scatter
    k_scatter<<<EE / 8, 256>>>(ei, lu, tv, msg, tw, tb, out);
    // 7) out += s @ We
    k_final<<<(NN + 127) / 128, 256, (96 * 256 + 96 * 128) * 4>>>(We, out);
}

// round 4
// speedup vs baseline: 1.6728x; 1.0945x over previous
#include <cuda_runtime.h>
#include <cuda_bf16.h>
#include <math_constants.h>
#include <cstdint>

// Problem constants (fixed shapes)
#define NN 100000
#define EE 800000
#define WC 768   // fused weight cols: [q 128][k 128][v 128][skip 128][p0 96][p1 96][pad 64]

// ------------------------- device scratch -------------------------
__device__ float g_dst[(size_t)NN * 320];            // per-node dst data: q[128], p[192]
__device__ float g_src[(size_t)NN * 256];            // per-node src data: k[128], v[128]
__device__ __nv_bfloat16 g_whT[WC * 128];            // W^T hi (bf16), [col][k]
__device__ __nv_bfloat16 g_wlT[WC * 128];            // W^T lo (bf16)
__device__ float g_bias[WC];
__device__ float g_s[(size_t)NN * 192];              // s[n][d][h], d<96, h<2
// sort scratch
__device__ int g_cnt[NN];
__device__ int g_off[NN + 1];
__device__ int g_cursor[NN];
__device__ int g_perm[EE];
__device__ int g_bsum[512];

// ------------------------- generic helpers -------------------------
__device__ __forceinline__ unsigned long long pk2(float lo, float hi) {
    unsigned long long r;
    asm("mov.b64 %0, {%1,%2};" : "=l"(r) : "f"(lo), "f"(hi));
    return r;
}
__device__ __forceinline__ float2 upk2(unsigned long long v) {
    float2 r;
    asm("mov.b64 {%0,%1}, %2;" : "=f"(r.x), "=f"(r.y) : "l"(v));
    return r;
}
__device__ __forceinline__ unsigned long long ffma2(unsigned long long a, unsigned long long b,
                                                    unsigned long long c) {
    unsigned long long d;
    asm("fma.rn.f32x2 %0, %1, %2, %3;" : "=l"(d) : "l"(a), "l"(b), "l"(c));
    return d;
}
__device__ __forceinline__ uint32_t smem_u32(const void* p) {
    uint32_t a;
    asm("{ .reg .u64 t; cvta.to.shared.u64 t, %1; cvt.u32.u64 %0, t; }" : "=r"(a) : "l"(p));
    return a;
}
__device__ __forceinline__ void ldsm4(uint32_t* r, uint32_t addr) {
    asm volatile("ldmatrix.sync.aligned.m8n8.x4.shared.b16 {%0,%1,%2,%3}, [%4];"
                 : "=r"(r[0]), "=r"(r[1]), "=r"(r[2]), "=r"(r[3]) : "r"(addr));
}
__device__ __forceinline__ void mma16816(float* c, const uint32_t* a, uint32_t b0, uint32_t b1) {
    asm volatile(
        "mma.sync.aligned.m16n8k16.row.col.f32.bf16.bf16.f32 "
        "{%0,%1,%2,%3}, {%4,%5,%6,%7}, {%8,%9}, {%0,%1,%2,%3};"
        : "+f"(c[0]), "+f"(c[1]), "+f"(c[2]), "+f"(c[3])
        : "r"(a[0]), "r"(a[1]), "r"(a[2]), "r"(a[3]), "r"(b0), "r"(b1));
}

// ------------------------- kernel 0: init sort scratch -------------------------
__global__ void k_init() {
    int i = blockIdx.x * blockDim.x + threadIdx.x;
    if (i < NN) {
        g_cnt[i] = 0;
        g_cursor[i] = 0;
    }
}

// ------------------------- kernel 1: fused weights (transposed, bf16 hi/lo) ----
__global__ void k_prep(const float* __restrict__ Wq, const float* __restrict__ bq,
                       const float* __restrict__ Wk, const float* __restrict__ bk,
                       const float* __restrict__ Wv, const float* __restrict__ bv,
                       const float* __restrict__ We,
                       const float* __restrict__ Ws, const float* __restrict__ bs) {
    int i = blockIdx.x;  // 0..127 (input dim k)
    for (int c = threadIdx.x; c < WC; c += blockDim.x) {
        float w = 0.0f, b = 0.0f;
        if (c < 128)      { w = Wq[i * 128 + c];         b = bq[c]; }
        else if (c < 256) { w = Wk[i * 128 + (c - 128)]; b = bk[c - 128]; }
        else if (c < 384) { w = Wv[i * 128 + (c - 256)]; b = bv[c - 256]; }
        else if (c < 512) { w = Ws[i * 128 + (c - 384)]; b = bs[c - 384]; }
        else if (c < 704) {
            int hd = c - 512;
            int h = hd / 96, d = hd % 96;
            float acc = 0.0f, accb = 0.0f;
            #pragma unroll 8
            for (int cc = 0; cc < 64; ++cc) {
                float we = We[d * 128 + h * 64 + cc];
                acc = fmaf(Wq[i * 128 + h * 64 + cc], we, acc);
                accb = fmaf(bq[h * 64 + cc], we, accb);
            }
            w = acc; b = accb;
        }
        __nv_bfloat16 hi = __float2bfloat16(w);
        __nv_bfloat16 lo = __float2bfloat16(w - __bfloat162float(hi));
        g_whT[c * 128 + i] = hi;
        g_wlT[c * 128 + i] = lo;
        if (i == 0) g_bias[c] = b;
    }
}

// ------------------------- kernel 2: HMMA node GEMM -------------------------
#define A_STRIDE 136
#define B_STRIDE 72
#define SZ_A (128 * A_STRIDE * 2)
#define SZ_B (128 * B_STRIDE * 2)
#define SM_A_HI 0
#define SM_A_LO (SZ_A)
#define SM_B_HI (2 * SZ_A)
#define SM_B_LO (2 * SZ_A + SZ_B)
#define SM_BIAS (2 * SZ_A + 2 * SZ_B)
#define SM_TOT  (SM_BIAS + WC * 4)

__global__ void __launch_bounds__(256, 1) k_gemm_mma(const float* __restrict__ x,
                                                     float* __restrict__ out) {
    extern __shared__ char smem[];
    const uint32_t sb = smem_u32(smem);
    const int tid = threadIdx.x, wid = tid >> 5, lane = tid & 31;
    const int row0 = blockIdx.x * 128;

    float* sbias = (float*)(smem + SM_BIAS);
    for (int i = tid; i < WC; i += 256) sbias[i] = g_bias[i];

    for (int i = tid; i < 128 * 32; i += 256) {
        int r = i >> 5, k4 = (i & 31) << 2;
        int row = row0 + r;
        float4 v = (row < NN) ? *(const float4*)(x + (size_t)row * 128 + k4)
                              : make_float4(0.f, 0.f, 0.f, 0.f);
        __nv_bfloat16 h0 = __float2bfloat16(v.x), h1 = __float2bfloat16(v.y);
        __nv_bfloat16 h2 = __float2bfloat16(v.z), h3 = __float2bfloat16(v.w);
        __nv_bfloat16 l0 = __float2bfloat16(v.x - __bfloat162float(h0));
        __nv_bfloat16 l1 = __float2bfloat16(v.y - __bfloat162float(h1));
        __nv_bfloat16 l2 = __float2bfloat16(v.z - __bfloat162float(h2));
        __nv_bfloat16 l3 = __float2bfloat16(v.w - __bfloat162float(h3));
        __nv_bfloat162 ph0(h0, h1), ph1(h2, h3), pl0(l0, l1), pl1(l2, l3);
        uint32_t off = (uint32_t)(r * (A_STRIDE * 2) + k4 * 2);
        *(uint2*)(smem + SM_A_HI + off) = make_uint2(*(uint32_t*)&ph0, *(uint32_t*)&ph1);
        *(uint2*)(smem + SM_A_LO + off) = make_uint2(*(uint32_t*)&pl0, *(uint32_t*)&pl1);
    }

    const int wm = wid & 1, wn = wid >> 1;
    const int rw = wm * 64, cw = wn * 32;
    const uint32_t a_off = (uint32_t)((rw + (lane & 15)) * (A_STRIDE * 2) + (lane >> 4) * 16);
    const uint32_t b_off = (uint32_t)((cw + (lane & 15)) * (B_STRIDE * 2) + (lane >> 4) * 16);
    const int trow = lane >> 2;
    const int tcol = (lane & 3) * 2;

    for (int chunk = 0; chunk < 6; ++chunk) {
        float acc[4][4][4];
        #pragma unroll
        for (int i = 0; i < 4; ++i)
            #pragma unroll
            for (int j = 0; j < 4; ++j)
                #pragma unroll
                for (int q = 0; q < 4; ++q) acc[i][j][q] = 0.0f;

        #pragma unroll
        for (int kh = 0; kh < 2; ++kh) {
            __syncthreads();
            for (int i = tid; i < 128 * 8; i += 256) {
                int c = i >> 3, seg = i & 7;
                size_t gsrc = (size_t)(chunk * 128 + c) * 128 + kh * 64 + seg * 8;
                uint32_t doff = (uint32_t)(c * (B_STRIDE * 2) + seg * 16);
                *(uint4*)(smem + SM_B_HI + doff) = *(const uint4*)(g_whT + gsrc);
                *(uint4*)(smem + SM_B_LO + doff) = *(const uint4*)(g_wlT + gsrc);
            }
            __syncthreads();

            #pragma unroll
            for (int term = 0; term < 3; ++term) {
                const uint32_t sA = sb + ((term == 2) ? SM_A_LO : SM_A_HI) + kh * 128;
                const uint32_t sB = sb + ((term == 1) ? SM_B_LO : SM_B_HI);
                #pragma unroll
                for (int ks = 0; ks < 4; ++ks) {
                    uint32_t a[4][4], b[2][4];
                    #pragma unroll
                    for (int i = 0; i < 4; ++i)
                        ldsm4(a[i], sA + a_off + i * (16 * A_STRIDE * 2) + ks * 32);
                    #pragma unroll
                    for (int j16 = 0; j16 < 2; ++j16)
                        ldsm4(b[j16], sB + b_off + j16 * (16 * B_STRIDE * 2) + ks * 32);
                    #pragma unroll
                    for (int i = 0; i < 4; ++i) {
                        mma16816(acc[i][0], a[i], b[0][0], b[0][2]);
                        mma16816(acc[i][1], a[i], b[0][1], b[0][3]);
                        mma16816(acc[i][2], a[i], b[1][0], b[1][2]);
                        mma16816(acc[i][3], a[i], b[1][1], b[1][3]);
                    }
                }
            }
        }

        float* bp; int stride, sub;
        switch (chunk) {
            case 0:  bp = g_dst; stride = 320; sub = 0;   break;
            case 1:
            case 2:  bp = g_src; stride = 256; sub = 128; break;
            case 3:  bp = out;   stride = 128; sub = 384; break;
            default: bp = g_dst; stride = 320; sub = 384; break;
        }
        #pragma unroll
        for (int i = 0; i < 4; ++i) {
            int r = row0 + rw + i * 16 + trow;
            #pragma unroll
            for (int j = 0; j < 4; ++j) {
                int G = chunk * 128 + cw + j * 8 + tcol;
                if (G >= 704) continue;
                float b0 = sbias[G], b1 = sbias[G + 1];
                if (r < NN) {
                    float2 v = make_float2(acc[i][j][0] + b0, acc[i][j][1] + b1);
                    *(float2*)(bp + (size_t)r * stride + (G - sub)) = v;
                }
                if (r + 8 < NN) {
                    float2 v = make_float2(acc[i][j][2] + b0, acc[i][j][3] + b1);
                    *(float2*)(bp + (size_t)(r + 8) * stride + (G - sub)) = v;
                }
            }
        }
    }
}

// ------------------------- sort: histogram, scan, permute -------------------------
__global__ void k_hist(const int* __restrict__ ei) {
    int i = blockIdx.x * blockDim.x + threadIdx.x;
    if (i < EE) atomicAdd(&g_cnt[ei[EE + i]], 1);
}

__global__ void k_scan_a() {
    __shared__ int sm[256];
    int t = threadIdx.x;
    int gid = blockIdx.x * 256 + t;
    int val = (gid < NN) ? g_cnt[gid] : 0;
    sm[t] = val;
    __syncthreads();
    #pragma unroll
    for (int o = 1; o < 256; o <<= 1) {
        int add = (t >= o) ? sm[t - o] : 0;
        __syncthreads();
        sm[t] += add;
        __syncthreads();
    }
    if (gid < NN) g_off[gid] = sm[t] - val;   // exclusive within block
    if (t == 255) g_bsum[blockIdx.x] = sm[255];
}

__global__ void k_scan_b(int nblk) {
    __shared__ int sm[512];
    int t = threadIdx.x;
    int val = (t < nblk) ? g_bsum[t] : 0;
    sm[t] = val;
    __syncthreads();
    #pragma unroll
    for (int o = 1; o < 512; o <<= 1) {
        int add = (t >= o) ? sm[t - o] : 0;
        __syncthreads();
        sm[t] += add;
        __syncthreads();
    }
    if (t < nblk) g_bsum[t] = sm[t] - val;    // exclusive block bases
}

__global__ void k_scan_c() {
    int gid = blockIdx.x * 256 + threadIdx.x;
    if (gid < NN) g_off[gid] += g_bsum[blockIdx.x];
    if (gid == 0) g_off[NN] = EE;
}

__global__ void k_permute(const int* __restrict__ ei) {
    int i = blockIdx.x * blockDim.x + threadIdx.x;
    if (i >= EE) return;
    int d = ei[EE + i];
    int pos = g_off[d] + atomicAdd(&g_cursor[d], 1);
    g_perm[pos] = i;
}

// ------------------------- kernel 3: fused edge pass (warp per dst node) -------
// Online softmax + aggregation; no atomics.
__global__ void __launch_bounds__(256) k_edge(const int* __restrict__ ei,
                                              const float* __restrict__ last_update,
                                              const float* __restrict__ tvec,
                                              const float* __restrict__ msg,
                                              const float* __restrict__ time_w,
                                              const float* __restrict__ time_b,
                                              float* __restrict__ out) {
    int n = (blockIdx.x * blockDim.x + threadIdx.x) >> 5;
    int lane = threadIdx.x & 31;
    if (n >= NN) return;
    const int off0 = g_off[n];
    const int deg = g_off[n + 1] - off0;

    const float* dp = g_dst + (size_t)n * 320;
    const float4 q4 = *(const float4*)(dp + lane * 4);
    const float p00 = dp[128 + lane], p01 = dp[160 + lane], p02 = dp[192 + lane];
    const float p10 = dp[224 + lane], p11 = dp[256 + lane], p12 = dp[288 + lane];
    const float tww = time_w[lane], tbb = time_b[lane];

    float m0 = -CUDART_INF_F, m1 = -CUDART_INF_F, den0 = 0.f, den1 = 0.f;
    float4 aco = make_float4(0.f, 0.f, 0.f, 0.f);
    float2 as0 = make_float2(0.f, 0.f), as1 = as0, as2 = as0;

    for (int e = 0; e < deg; ++e) {
        int i = g_perm[off0 + e];
        int src = ei[i];
        float rel = last_update[src] - tvec[i];
        const float* sp = g_src + (size_t)src * 256;
        float4 k4 = *(const float4*)(sp + lane * 4);
        float4 v4 = *(const float4*)(sp + 128 + lane * 4);

        float qk = q4.x * k4.x + q4.y * k4.y + q4.z * k4.z + q4.w * k4.w;
        #pragma unroll
        for (int o = 8; o; o >>= 1) qk += __shfl_xor_sync(0xffffffffu, qk, o);

        float ea0 = cosf(fmaf(rel, tww, tbb));
        float ea1 = msg[(size_t)i * 64 + lane];
        float ea2 = msg[(size_t)i * 64 + 32 + lane];

        float pe0 = ea0 * p00 + ea1 * p01 + ea2 * p02;
        float pe1 = ea0 * p10 + ea1 * p11 + ea2 * p12;
        #pragma unroll
        for (int o = 16; o; o >>= 1) {
            pe0 += __shfl_xor_sync(0xffffffffu, pe0, o);
            pe1 += __shfl_xor_sync(0xffffffffu, pe1, o);
        }

        float a0 = (__shfl_sync(0xffffffffu, qk, 0)  + pe0) * 0.125f;
        float a1 = (__shfl_sync(0xffffffffu, qk, 16) + pe1) * 0.125f;

        float n0 = fmaxf(m0, a0), n1 = fmaxf(m1, a1);
        float r0 = __expf(m0 - n0), r1 = __expf(m1 - n1);
        float s0 = __expf(a0 - n0), s1 = __expf(a1 - n1);
        den0 = den0 * r0 + s0;
        den1 = den1 * r1 + s1;
        m0 = n0; m1 = n1;

        float rh = (lane < 16) ? r0 : r1;
        float sh = (lane < 16) ? s0 : s1;
        aco.x = aco.x * rh + v4.x * sh;
        aco.y = aco.y * rh + v4.y * sh;
        aco.z = aco.z * rh + v4.z * sh;
        aco.w = aco.w * rh + v4.w * sh;
        as0.x = as0.x * r0 + ea0 * s0;  as0.y = as0.y * r1 + ea0 * s1;
        as1.x = as1.x * r0 + ea1 * s0;  as1.y = as1.y * r1 + ea1 * s1;
        as2.x = as2.x * r0 + ea2 * s0;  as2.y = as2.y * r1 + ea2 * s1;
    }

    float i0 = 1.0f / (den0 + 1e-16f);
    float i1 = 1.0f / (den1 + 1e-16f);

    if (deg > 0) {
        float ih = (lane < 16) ? i0 : i1;
        float4 o4 = *(const float4*)(out + (size_t)n * 128 + lane * 4);
        o4.x += aco.x * ih; o4.y += aco.y * ih;
        o4.z += aco.z * ih; o4.w += aco.w * ih;
        *(float4*)(out + (size_t)n * 128 + lane * 4) = o4;
        float2* sp2 = (float2*)(g_s + (size_t)n * 192);
        sp2[lane]      = make_float2(as0.x * i0, as0.y * i1);
        sp2[lane + 32] = make_float2(as1.x * i0, as1.y * i1);
        sp2[lane + 64] = make_float2(as2.x * i0, as2.y * i1);
    } else {
        float2* sp2 = (float2*)(g_s + (size_t)n * 192);
        float2 z = make_float2(0.f, 0.f);
        sp2[lane] = z; sp2[lane + 32] = z; sp2[lane + 64] = z;
    }
}

// ------------------------- kernel 4: out += s @ We -------------------------
__global__ void k_final(const float* __restrict__ We, float* __restrict__ out) {
    extern __shared__ float sm[];
    float* sS = sm;              // [d][h][r]: 96*2*128
    float* sW = sm + 96 * 256;   // [d][c]:   96*128
    const int row0 = blockIdx.x * 128;
    const int t = threadIdx.x;

    for (int i = t; i < 96 * 32; i += 256) {
        int d = i >> 5, c4 = (i & 31) << 2;
        *(float4*)(sW + d * 128 + c4) = *(const float4*)(We + d * 128 + c4);
    }
    for (int i = t; i < 128 * 96; i += 256) {
        int r = i / 96, d = i % 96;
        int row = row0 + r;
        float2 v = (row < NN) ? *(const float2*)(g_s + (size_t)row * 192 + d * 2)
                              : make_float2(0.f, 0.f);
        sS[d * 256 + r] = v.x;
        sS[d * 256 + 128 + r] = v.y;
    }
    __syncthreads();

    const int tx = t & 15, ty = t >> 4;
    const int r0 = ty * 8, c0 = tx * 8;
    const int h = c0 >> 6;

    unsigned long long acc[4][8];
    #pragma unroll
    for (int i = 0; i < 4; ++i)
        #pragma unroll
        for (int j = 0; j < 8; ++j) acc[i][j] = 0ULL;

    #pragma unroll 4
    for (int d = 0; d < 96; ++d) {
        float4 a0 = *(float4*)(sS + d * 256 + h * 128 + r0);
        float4 a1 = *(float4*)(sS + d * 256 + h * 128 + r0 + 4);
        float4 b0 = *(float4*)(sW + d * 128 + c0);
        float4 b1 = *(float4*)(sW + d * 128 + c0 + 4);
        unsigned long long A[4] = {pk2(a0.x, a0.y), pk2(a0.z, a0.w),
                                   pk2(a1.x, a1.y), pk2(a1.z, a1.w)};
        float bs8[8] = {b0.x, b0.y, b0.z, b0.w, b1.x, b1.y, b1.z, b1.w};
        #pragma unroll
        for (int j = 0; j < 8; ++j) {
            unsigned long long B = pk2(bs8[j], bs8[j]);
            #pragma unroll
            for (int i = 0; i < 4; ++i) acc[i][j] = ffma2(A[i], B, acc[i][j]);
        }
    }

    #pragma unroll
    for (int j = 0; j < 8; ++j) {
        int col = c0 + j;
        #pragma unroll
        for (int i = 0; i < 4; ++i) {
            float2 v = upk2(acc[i][j]);
            int r = row0 + r0 + 2 * i;
            if (r < NN)     out[(size_t)r * 128 + col] += v.x;
            if (r + 1 < NN) out[(size_t)(r + 1) * 128 + col] += v.y;
        }
    }
}

// ------------------------- launch -------------------------
extern "C" void kernel_launch(void* const* d_in, const int* in_sizes, int n_in,
                              void* d_out, int out_size) {
    const float* x   = (const float*)d_in[0];
    const float* lu  = (const float*)d_in[1];
    const float* tv  = (const float*)d_in[2];
    const float* msg = (const float*)d_in[3];
    const int*   ei  = (const int*)d_in[4];
    const float* tw  = (const float*)d_in[5];
    const float* tb  = (const float*)d_in[6];
    const float* Wq  = (const float*)d_in[7];
    const float* bq  = (const float*)d_in[8];
    const float* Wk  = (const float*)d_in[9];
    const float* bk  = (const float*)d_in[10];
    const float* Wv  = (const float*)d_in[11];
    const float* bv  = (const float*)d_in[12];
    const float* We  = (const float*)d_in[13];
    const float* Ws  = (const float*)d_in[14];
    const float* bs  = (const float*)d_in[15];
    float* out = (float*)d_out;

    static bool attr_done = false;
    if (!attr_done) {
        cudaFuncSetAttribute(k_gemm_mma, cudaFuncAttributeMaxDynamicSharedMemorySize, SM_TOT);
        cudaFuncSetAttribute(k_final, cudaFuncAttributeMaxDynamicSharedMemorySize,
                             (96 * 256 + 96 * 128) * 4);
        attr_done = true;
    }

    const int nblk = (NN + 255) / 256;  // 391

    // 1) init sort counters
    k_init<<<nblk, 256>>>();
    // 2) fused weights (transposed, bf16 hi/lo split)
    k_prep<<<128, 256>>>(Wq, bq, Wk, bk, Wv, bv, We, Ws, bs);
    // 3) HMMA node GEMM (writes g_dst q/p, g_src k/v, skip->out)
    k_gemm_mma<<<(NN + 127) / 128, 256, SM_TOT>>>(x, out);
    // 4) counting sort of edges by dst
    k_hist<<<(EE + 255) / 256, 256>>>(ei);
    k_scan_a<<<nblk, 256>>>();
    k_scan_b<<<1, 512>>>(nblk);
    k_scan_c<<<nblk, 256>>>();
    k_permute<<<(EE + 255) / 256, 256>>>(ei);
    // 5) fused edge pass: online softmax + aggregation, warp per node
    k_edge<<<(NN * 32 + 255) / 256, 256>>>(ei, lu, tv, msg, tw, tb, out);
    // 6) out += s @ We
    k_final<<<(NN + 127) / 128, 256, (96 * 256 + 96 * 128) * 4>>>(We, out);
}

// round 5
// speedup vs baseline: 1.9052x; 1.1389x over previous
#include <cuda_runtime.h>
#include <cuda_bf16.h>
#include <math_constants.h>
#include <cstdint>

// Problem constants (fixed shapes)
#define NN 100000
#define EE 800000
#define WC 768   // fused weight cols: [q 128][k 128][v 128][skip 128][p0 96][p1 96][pad 64]

// ------------------------- device scratch -------------------------
__device__ float g_dst[(size_t)NN * 320];            // per-node dst data: q[128], p[192]
__device__ float g_src[(size_t)NN * 256];            // per-node src data: k[128], v[128]
__device__ __nv_bfloat16 g_whT[WC * 128];            // W^T hi (bf16), [col][k]
__device__ __nv_bfloat16 g_wlT[WC * 128];            // W^T lo (bf16)
__device__ float g_bias[WC];
__device__ float g_s[(size_t)NN * 192];              // s[n][d][h], d<96, h<2
// sort scratch (SoA sorted edge data)
__device__ int g_cnt[NN];
__device__ int g_off[NN + 1];
__device__ int g_cursor[NN];
__device__ int g_esrc[EE];
__device__ int g_eidx[EE];
__device__ float g_erel[EE];
__device__ int g_bsum[512];

// ------------------------- generic helpers -------------------------
__device__ __forceinline__ unsigned long long pk2(float lo, float hi) {
    unsigned long long r;
    asm("mov.b64 %0, {%1,%2};" : "=l"(r) : "f"(lo), "f"(hi));
    return r;
}
__device__ __forceinline__ float2 upk2(unsigned long long v) {
    float2 r;
    asm("mov.b64 {%0,%1}, %2;" : "=f"(r.x), "=f"(r.y) : "l"(v));
    return r;
}
__device__ __forceinline__ unsigned long long ffma2(unsigned long long a, unsigned long long b,
                                                    unsigned long long c) {
    unsigned long long d;
    asm("fma.rn.f32x2 %0, %1, %2, %3;" : "=l"(d) : "l"(a), "l"(b), "l"(c));
    return d;
}
__device__ __forceinline__ uint32_t smem_u32(const void* p) {
    uint32_t a;
    asm("{ .reg .u64 t; cvta.to.shared.u64 t, %1; cvt.u32.u64 %0, t; }" : "=r"(a) : "l"(p));
    return a;
}
__device__ __forceinline__ void ldsm4(uint32_t* r, uint32_t addr) {
    asm volatile("ldmatrix.sync.aligned.m8n8.x4.shared.b16 {%0,%1,%2,%3}, [%4];"
                 : "=r"(r[0]), "=r"(r[1]), "=r"(r[2]), "=r"(r[3]) : "r"(addr));
}
__device__ __forceinline__ void mma16816(float* c, const uint32_t* a, uint32_t b0, uint32_t b1) {
    asm volatile(
        "mma.sync.aligned.m16n8k16.row.col.f32.bf16.bf16.f32 "
        "{%0,%1,%2,%3}, {%4,%5,%6,%7}, {%8,%9}, {%0,%1,%2,%3};"
        : "+f"(c[0]), "+f"(c[1]), "+f"(c[2]), "+f"(c[3])
        : "r"(a[0]), "r"(a[1]), "r"(a[2]), "r"(a[3]), "r"(b0), "r"(b1));
}
__device__ __forceinline__ void cp16(uint32_t saddr, const void* g) {
    asm volatile("cp.async.cg.shared.global [%0], [%1], 16;" :: "r"(saddr), "l"(g));
}
#define CP_COMMIT() asm volatile("cp.async.commit_group;" ::: "memory")
#define CP_WAIT1()  asm volatile("cp.async.wait_group 1;" ::: "memory")
#define CP_WAIT0()  asm volatile("cp.async.wait_group 0;" ::: "memory")

// ------------------------- kernel 0: init sort scratch -------------------------
__global__ void k_init() {
    int i = blockIdx.x * blockDim.x + threadIdx.x;
    if (i < NN) {
        g_cnt[i] = 0;
        g_cursor[i] = 0;
    }
}

// ------------------------- kernel 1: fused weights (transposed, bf16 hi/lo) ----
__global__ void k_prep(const float* __restrict__ Wq, const float* __restrict__ bq,
                       const float* __restrict__ Wk, const float* __restrict__ bk,
                       const float* __restrict__ Wv, const float* __restrict__ bv,
                       const float* __restrict__ We,
                       const float* __restrict__ Ws, const float* __restrict__ bs) {
    int i = blockIdx.x;  // 0..127 (input dim k)
    for (int c = threadIdx.x; c < WC; c += blockDim.x) {
        float w = 0.0f, b = 0.0f;
        if (c < 128)      { w = Wq[i * 128 + c];         b = bq[c]; }
        else if (c < 256) { w = Wk[i * 128 + (c - 128)]; b = bk[c - 128]; }
        else if (c < 384) { w = Wv[i * 128 + (c - 256)]; b = bv[c - 256]; }
        else if (c < 512) { w = Ws[i * 128 + (c - 384)]; b = bs[c - 384]; }
        else if (c < 704) {
            int hd = c - 512;
            int h = hd / 96, d = hd % 96;
            float acc = 0.0f, accb = 0.0f;
            #pragma unroll 8
            for (int cc = 0; cc < 64; ++cc) {
                float we = We[d * 128 + h * 64 + cc];
                acc = fmaf(Wq[i * 128 + h * 64 + cc], we, acc);
                accb = fmaf(bq[h * 64 + cc], we, accb);
            }
            w = acc; b = accb;
        }
        __nv_bfloat16 hi = __float2bfloat16(w);
        __nv_bfloat16 lo = __float2bfloat16(w - __bfloat162float(hi));
        g_whT[c * 128 + i] = hi;
        g_wlT[c * 128 + i] = lo;
        if (i == 0) g_bias[c] = b;
    }
}

// ------------------------- kernel 2: HMMA node GEMM (cp.async pipelined B) -----
#define A_STRIDE 136
#define B_STRIDE 72
#define SZ_A (128 * A_STRIDE * 2)         // 34816
#define SZ_B (128 * B_STRIDE * 2)         // 18432
#define SM_A_HI 0
#define SM_A_LO (SZ_A)
#define SM_B    (2 * SZ_A)                // 2 buffers x (hi, lo)
#define SM_BIAS (2 * SZ_A + 4 * SZ_B)
#define SM_TOT  (SM_BIAS + WC * 4)        // 146432

__device__ __forceinline__ void load_B_async(uint32_t sb, int s, int tid) {
    const int chunk = s >> 1, kh = s & 1;
    const uint32_t bbase = SM_B + (uint32_t)(s & 1) * (2 * SZ_B);
    for (int i = tid; i < 128 * 8; i += 256) {
        int c = i >> 3, seg = i & 7;
        size_t gsrc = (size_t)(chunk * 128 + c) * 128 + kh * 64 + seg * 8;
        uint32_t doff = (uint32_t)(c * (B_STRIDE * 2) + seg * 16);
        cp16(sb + bbase + doff, g_whT + gsrc);
        cp16(sb + bbase + SZ_B + doff, g_wlT + gsrc);
    }
}

__global__ void __launch_bounds__(256, 1) k_gemm_mma(const float* __restrict__ x,
                                                     float* __restrict__ out) {
    extern __shared__ char smem[];
    const uint32_t sb = smem_u32(smem);
    const int tid = threadIdx.x, wid = tid >> 5, lane = tid & 31;
    const int row0 = blockIdx.x * 128;

    // kick off first B chunk load
    load_B_async(sb, 0, tid);
    CP_COMMIT();

    float* sbias = (float*)(smem + SM_BIAS);
    for (int i = tid; i < WC; i += 256) sbias[i] = g_bias[i];

    // load A tile [128x128], split bf16 hi/lo
    for (int i = tid; i < 128 * 32; i += 256) {
        int r = i >> 5, k4 = (i & 31) << 2;
        int row = row0 + r;
        float4 v = (row < NN) ? *(const float4*)(x + (size_t)row * 128 + k4)
                              : make_float4(0.f, 0.f, 0.f, 0.f);
        __nv_bfloat16 h0 = __float2bfloat16(v.x), h1 = __float2bfloat16(v.y);
        __nv_bfloat16 h2 = __float2bfloat16(v.z), h3 = __float2bfloat16(v.w);
        __nv_bfloat16 l0 = __float2bfloat16(v.x - __bfloat162float(h0));
        __nv_bfloat16 l1 = __float2bfloat16(v.y - __bfloat162float(h1));
        __nv_bfloat16 l2 = __float2bfloat16(v.z - __bfloat162float(h2));
        __nv_bfloat16 l3 = __float2bfloat16(v.w - __bfloat162float(h3));
        __nv_bfloat162 ph0(h0, h1), ph1(h2, h3), pl0(l0, l1), pl1(l2, l3);
        uint32_t off = (uint32_t)(r * (A_STRIDE * 2) + k4 * 2);
        *(uint2*)(smem + SM_A_HI + off) = make_uint2(*(uint32_t*)&ph0, *(uint32_t*)&ph1);
        *(uint2*)(smem + SM_A_LO + off) = make_uint2(*(uint32_t*)&pl0, *(uint32_t*)&pl1);
    }

    const int wm = wid & 1, wn = wid >> 1;
    const int rw = wm * 64, cw = wn * 32;
    const uint32_t a_off = (uint32_t)((rw + (lane & 15)) * (A_STRIDE * 2) + (lane >> 4) * 16);
    const uint32_t b_off = (uint32_t)((cw + (lane & 15)) * (B_STRIDE * 2) + (lane >> 4) * 16);
    const int trow = lane >> 2;
    const int tcol = (lane & 3) * 2;

    float acc[4][4][4];

    for (int s = 0; s < 12; ++s) {
        const int chunk = s >> 1, kh = s & 1;
        if (kh == 0) {
            #pragma unroll
            for (int i = 0; i < 4; ++i)
                #pragma unroll
                for (int j = 0; j < 4; ++j)
                    #pragma unroll
                    for (int q = 0; q < 4; ++q) acc[i][j][q] = 0.0f;
        }
        if (s + 1 < 12) {
            load_B_async(sb, s + 1, tid);
            CP_COMMIT();
            CP_WAIT1();
        } else {
            CP_WAIT0();
        }
        __syncthreads();

        const uint32_t bbase = SM_B + (uint32_t)(s & 1) * (2 * SZ_B);
        #pragma unroll
        for (int term = 0; term < 3; ++term) {
            const uint32_t sA = sb + ((term == 2) ? SM_A_LO : SM_A_HI) + kh * 128;
            const uint32_t sB = sb + bbase + ((term == 1) ? SZ_B : 0);
            #pragma unroll
            for (int ks = 0; ks < 4; ++ks) {
                uint32_t a[4][4], b[2][4];
                #pragma unroll
                for (int i = 0; i < 4; ++i)
                    ldsm4(a[i], sA + a_off + i * (16 * A_STRIDE * 2) + ks * 32);
                #pragma unroll
                for (int j16 = 0; j16 < 2; ++j16)
                    ldsm4(b[j16], sB + b_off + j16 * (16 * B_STRIDE * 2) + ks * 32);
                #pragma unroll
                for (int i = 0; i < 4; ++i) {
                    mma16816(acc[i][0], a[i], b[0][0], b[0][2]);
                    mma16816(acc[i][1], a[i], b[0][1], b[0][3]);
                    mma16816(acc[i][2], a[i], b[1][0], b[1][2]);
                    mma16816(acc[i][3], a[i], b[1][1], b[1][3]);
                }
            }
        }
        __syncthreads();

        if (kh == 1) {
            float* bp; int stride, sub;
            switch (chunk) {
                case 0:  bp = g_dst; stride = 320; sub = 0;   break;
                case 1:
                case 2:  bp = g_src; stride = 256; sub = 128; break;
                case 3:  bp = out;   stride = 128; sub = 384; break;
                default: bp = g_dst; stride = 320; sub = 384; break;
            }
            #pragma unroll
            for (int i = 0; i < 4; ++i) {
                int r = row0 + rw + i * 16 + trow;
                #pragma unroll
                for (int j = 0; j < 4; ++j) {
                    int G = chunk * 128 + cw + j * 8 + tcol;
                    if (G >= 704) continue;
                    float b0 = sbias[G], b1 = sbias[G + 1];
                    if (r < NN) {
                        float2 v = make_float2(acc[i][j][0] + b0, acc[i][j][1] + b1);
                        *(float2*)(bp + (size_t)r * stride + (G - sub)) = v;
                    }
                    if (r + 8 < NN) {
                        float2 v = make_float2(acc[i][j][2] + b0, acc[i][j][3] + b1);
                        *(float2*)(bp + (size_t)(r + 8) * stride + (G - sub)) = v;
                    }
                }
            }
        }
    }
}

// ------------------------- sort: histogram, scan, permute -------------------------
__global__ void k_hist(const int* __restrict__ ei) {
    int i = blockIdx.x * blockDim.x + threadIdx.x;
    if (i < EE) atomicAdd(&g_cnt[ei[EE + i]], 1);
}

__global__ void k_scan_a() {
    __shared__ int sm[256];
    int t = threadIdx.x;
    int gid = blockIdx.x * 256 + t;
    int val = (gid < NN) ? g_cnt[gid] : 0;
    sm[t] = val;
    __syncthreads();
    #pragma unroll
    for (int o = 1; o < 256; o <<= 1) {
        int add = (t >= o) ? sm[t - o] : 0;
        __syncthreads();
        sm[t] += add;
        __syncthreads();
    }
    if (gid < NN) g_off[gid] = sm[t] - val;
    if (t == 255) g_bsum[blockIdx.x] = sm[255];
}

__global__ void k_scan_b(int nblk) {
    __shared__ int sm[512];
    int t = threadIdx.x;
    int val = (t < nblk) ? g_bsum[t] : 0;
    sm[t] = val;
    __syncthreads();
    #pragma unroll
    for (int o = 1; o < 512; o <<= 1) {
        int add = (t >= o) ? sm[t - o] : 0;
        __syncthreads();
        sm[t] += add;
        __syncthreads();
    }
    if (t < nblk) g_bsum[t] = sm[t] - val;
}

__global__ void k_scan_c() {
    int gid = blockIdx.x * 256 + threadIdx.x;
    if (gid < NN) g_off[gid] += g_bsum[blockIdx.x];
    if (gid == 0) g_off[NN] = EE;
}

__global__ void k_permute(const int* __restrict__ ei, const float* __restrict__ lu,
                          const float* __restrict__ tv) {
    int i = blockIdx.x * blockDim.x + threadIdx.x;
    if (i >= EE) return;
    int d = ei[EE + i];
    int s = ei[i];
    int pos = g_off[d] + atomicAdd(&g_cursor[d], 1);
    g_esrc[pos] = s;
    g_eidx[pos] = i;
    g_erel[pos] = lu[s] - tv[i];
}

// ------------------------- kernel 3: fused edge pass (warp per dst node) -------
// Online softmax + aggregation; batched MLP-4 gathers; no atomics.
__global__ void __launch_bounds__(256) k_edge(const float* __restrict__ msg,
                                              const float* __restrict__ time_w,
                                              const float* __restrict__ time_b,
                                              float* __restrict__ out) {
    int n = (blockIdx.x * blockDim.x + threadIdx.x) >> 5;
    int lane = threadIdx.x & 31;
    if (n >= NN) return;
    const int off0 = g_off[n];
    const int deg = g_off[n + 1] - off0;

    const float* dp = g_dst + (size_t)n * 320;
    const float4 q4 = *(const float4*)(dp + lane * 4);
    const float p00 = dp[128 + lane], p01 = dp[160 + lane], p02 = dp[192 + lane];
    const float p10 = dp[224 + lane], p11 = dp[256 + lane], p12 = dp[288 + lane];
    const float tww = time_w[lane], tbb = time_b[lane];

    float m0 = -CUDART_INF_F, m1 = -CUDART_INF_F, den0 = 0.f, den1 = 0.f;
    float4 aco = make_float4(0.f, 0.f, 0.f, 0.f);
    float2 as0 = make_float2(0.f, 0.f), as1 = as0, as2 = as0;

    for (int eb = 0; eb < deg; eb += 4) {
        const int nb = deg - eb;
        int srcj[4], idxj[4];
        float relj[4], ea1[4], ea2[4];
        float4 k4[4], v4[4];
        #pragma unroll
        for (int j = 0; j < 4; ++j) {
            int pos = off0 + eb + ((j < nb) ? j : 0);
            srcj[j] = g_esrc[pos];
            idxj[j] = g_eidx[pos];
            relj[j] = g_erel[pos];
        }
        #pragma unroll
        for (int j = 0; j < 4; ++j) {
            const float* sp = g_src + (size_t)srcj[j] * 256;
            k4[j] = *(const float4*)(sp + lane * 4);
            v4[j] = *(const float4*)(sp + 128 + lane * 4);
            ea1[j] = msg[(size_t)idxj[j] * 64 + lane];
            ea2[j] = msg[(size_t)idxj[j] * 64 + 32 + lane];
        }
        #pragma unroll
        for (int j = 0; j < 4; ++j) {
            if (j < nb) {
                float qk = q4.x * k4[j].x + q4.y * k4[j].y + q4.z * k4[j].z + q4.w * k4[j].w;
                #pragma unroll
                for (int o = 8; o; o >>= 1) qk += __shfl_xor_sync(0xffffffffu, qk, o);

                float ea0 = cosf(fmaf(relj[j], tww, tbb));
                float pe0 = ea0 * p00 + ea1[j] * p01 + ea2[j] * p02;
                float pe1 = ea0 * p10 + ea1[j] * p11 + ea2[j] * p12;
                #pragma unroll
                for (int o = 16; o; o >>= 1) {
                    pe0 += __shfl_xor_sync(0xffffffffu, pe0, o);
                    pe1 += __shfl_xor_sync(0xffffffffu, pe1, o);
                }

                float a0 = (__shfl_sync(0xffffffffu, qk, 0)  + pe0) * 0.125f;
                float a1 = (__shfl_sync(0xffffffffu, qk, 16) + pe1) * 0.125f;

                float n0 = fmaxf(m0, a0), n1 = fmaxf(m1, a1);
                float r0 = __expf(m0 - n0), r1 = __expf(m1 - n1);
                float s0 = __expf(a0 - n0), s1 = __expf(a1 - n1);
                den0 = den0 * r0 + s0;
                den1 = den1 * r1 + s1;
                m0 = n0; m1 = n1;

                float rh = (lane < 16) ? r0 : r1;
                float sh = (lane < 16) ? s0 : s1;
                aco.x = aco.x * rh + v4[j].x * sh;
                aco.y = aco.y * rh + v4[j].y * sh;
                aco.z = aco.z * rh + v4[j].z * sh;
                aco.w = aco.w * rh + v4[j].w * sh;
                as0.x = as0.x * r0 + ea0 * s0;     as0.y = as0.y * r1 + ea0 * s1;
                as1.x = as1.x * r0 + ea1[j] * s0;  as1.y = as1.y * r1 + ea1[j] * s1;
                as2.x = as2.x * r0 + ea2[j] * s0;  as2.y = as2.y * r1 + ea2[j] * s1;
            }
        }
    }

    float i0 = 1.0f / (den0 + 1e-16f);
    float i1 = 1.0f / (den1 + 1e-16f);

    if (deg > 0) {
        float ih = (lane < 16) ? i0 : i1;
        float4 o4 = *(const float4*)(out + (size_t)n * 128 + lane * 4);
        o4.x += aco.x * ih; o4.y += aco.y * ih;
        o4.z += aco.z * ih; o4.w += aco.w * ih;
        *(float4*)(out + (size_t)n * 128 + lane * 4) = o4;
        float2* sp2 = (float2*)(g_s + (size_t)n * 192);
        sp2[lane]      = make_float2(as0.x * i0, as0.y * i1);
        sp2[lane + 32] = make_float2(as1.x * i0, as1.y * i1);
        sp2[lane + 64] = make_float2(as2.x * i0, as2.y * i1);
    } else {
        float2* sp2 = (float2*)(g_s + (size_t)n * 192);
        float2 z = make_float2(0.f, 0.f);
        sp2[lane] = z; sp2[lane + 32] = z; sp2[lane + 64] = z;
    }
}

// ------------------------- kernel 4: out += s @ We -------------------------
__global__ void k_final(const float* __restrict__ We, float* __restrict__ out) {
    extern __shared__ float sm[];
    float* sS = sm;              // [d][h][r]: 96*2*128
    float* sW = sm + 96 * 256;   // [d][c]:   96*128
    const int row0 = blockIdx.x * 128;
    const int t = threadIdx.x;

    for (int i = t; i < 96 * 32; i += 256) {
        int d = i >> 5, c4 = (i & 31) << 2;
        *(float4*)(sW + d * 128 + c4) = *(const float4*)(We + d * 128 + c4);
    }
    for (int i = t; i < 128 * 96; i += 256) {
        int r = i / 96, d = i % 96;
        int row = row0 + r;
        float2 v = (row < NN) ? *(const float2*)(g_s + (size_t)row * 192 + d * 2)
                              : make_float2(0.f, 0.f);
        sS[d * 256 + r] = v.x;
        sS[d * 256 + 128 + r] = v.y;
    }
    __syncthreads();

    const int tx = t & 15, ty = t >> 4;
    const int r0 = ty * 8, c0 = tx * 8;
    const int h = c0 >> 6;

    unsigned long long acc[4][8];
    #pragma unroll
    for (int i = 0; i < 4; ++i)
        #pragma unroll
        for (int j = 0; j < 8; ++j) acc[i][j] = 0ULL;

    #pragma unroll 4
    for (int d = 0; d < 96; ++d) {
        float4 a0 = *(float4*)(sS + d * 256 + h * 128 + r0);
        float4 a1 = *(float4*)(sS + d * 256 + h * 128 + r0 + 4);
        float4 b0 = *(float4*)(sW + d * 128 + c0);
        float4 b1 = *(float4*)(sW + d * 128 + c0 + 4);
        unsigned long long A[4] = {pk2(a0.x, a0.y), pk2(a0.z, a0.w),
                                   pk2(a1.x, a1.y), pk2(a1.z, a1.w)};
        float bs8[8] = {b0.x, b0.y, b0.z, b0.w, b1.x, b1.y, b1.z, b1.w};
        #pragma unroll
        for (int j = 0; j < 8; ++j) {
            unsigned long long B = pk2(bs8[j], bs8[j]);
            #pragma unroll
            for (int i = 0; i < 4; ++i) acc[i][j] = ffma2(A[i], B, acc[i][j]);
        }
    }

    #pragma unroll
    for (int j = 0; j < 8; ++j) {
        int col = c0 + j;
        #pragma unroll
        for (int i = 0; i < 4; ++i) {
            float2 v = upk2(acc[i][j]);
            int r = row0 + r0 + 2 * i;
            if (r < NN)     out[(size_t)r * 128 + col] += v.x;
            if (r + 1 < NN) out[(size_t)(r + 1) * 128 + col] += v.y;
        }
    }
}

// ------------------------- launch -------------------------
extern "C" void kernel_launch(void* const* d_in, const int* in_sizes, int n_in,
                              void* d_out, int out_size) {
    const float* x   = (const float*)d_in[0];
    const float* lu  = (const float*)d_in[1];
    const float* tv  = (const float*)d_in[2];
    const float* msg = (const float*)d_in[3];
    const int*   ei  = (const int*)d_in[4];
    const float* tw  = (const float*)d_in[5];
    const float* tb  = (const float*)d_in[6];
    const float* Wq  = (const float*)d_in[7];
    const float* bq  = (const float*)d_in[8];
    const float* Wk  = (const float*)d_in[9];
    const float* bk  = (const float*)d_in[10];
    const float* Wv  = (const float*)d_in[11];
    const float* bv  = (const float*)d_in[12];
    const float* We  = (const float*)d_in[13];
    const float* Ws  = (const float*)d_in[14];
    const float* bs  = (const float*)d_in[15];
    float* out = (float*)d_out;

    static bool attr_done = false;
    if (!attr_done) {
        cudaFuncSetAttribute(k_gemm_mma, cudaFuncAttributeMaxDynamicSharedMemorySize, SM_TOT);
        cudaFuncSetAttribute(k_final, cudaFuncAttributeMaxDynamicSharedMemorySize,
                             (96 * 256 + 96 * 128) * 4);
        attr_done = true;
    }

    const int nblk = (NN + 255) / 256;  // 391

    // 1) init sort counters
    k_init<<<nblk, 256>>>();
    // 2) fused weights (transposed, bf16 hi/lo split)
    k_prep<<<128, 256>>>(Wq, bq, Wk, bk, Wv, bv, We, Ws, bs);
    // 3) HMMA node GEMM (writes g_dst q/p, g_src k/v, skip->out)
    k_gemm_mma<<<(NN + 127) / 128, 256, SM_TOT>>>(x, out);
    // 4) counting sort of edges by dst -> SoA (src, idx, rel_t)
    k_hist<<<(EE + 255) / 256, 256>>>(ei);
    k_scan_a<<<nblk, 256>>>();
    k_scan_b<<<1, 512>>>(nblk);
    k_scan_c<<<nblk, 256>>>();
    k_permute<<<(EE + 255) / 256, 256>>>(ei, lu, tv);
    // 5) fused edge pass: online softmax + aggregation, warp per node, MLP-4
    k_edge<<<(NN * 32 + 255) / 256, 256>>>(msg, tw, tb, out);
    // 6) out += s @ We
    k_final<<<(NN + 127) / 128, 256, (96 * 256 + 96 * 128) * 4>>>(We, out);
}

// round 6
// speedup vs baseline: 2.0719x; 1.0875x over previous
#include <cuda_runtime.h>
#include <cuda_bf16.h>
#include <math_constants.h>
#include <cstdint>

// Problem constants (fixed shapes)
#define NN 100000
#define EE 800000
#define WC 768   // fused weight cols: [q 128][k 128][v 128][skip 128][p0 96][p1 96][pad 64]

// ------------------------- device scratch -------------------------
__device__ float g_dst[(size_t)NN * 320];            // per-node dst data: q[128], p[192]
__device__ float g_src[(size_t)NN * 256];            // per-node src data: k[128], v[128]
__device__ __nv_bfloat16 g_whT[WC * 128];            // W^T hi (bf16), [col][k]
__device__ __nv_bfloat16 g_wlT[WC * 128];            // W^T lo (bf16)
__device__ float g_bias[WC];
__device__ float g_s[(size_t)NN * 192];              // s[n][d][h], d<96, h<2
// sort scratch (SoA sorted edge data)
__device__ int g_cnt[NN];
__device__ int g_off[NN + 1];
__device__ int g_cursor[NN];
__device__ int g_esrc[EE];
__device__ int g_eidx[EE];
__device__ float g_erel[EE];
__device__ int g_bsum[512];

// ------------------------- generic helpers -------------------------
__device__ __forceinline__ unsigned long long pk2(float lo, float hi) {
    unsigned long long r;
    asm("mov.b64 %0, {%1,%2};" : "=l"(r) : "f"(lo), "f"(hi));
    return r;
}
__device__ __forceinline__ float2 upk2(unsigned long long v) {
    float2 r;
    asm("mov.b64 {%0,%1}, %2;" : "=f"(r.x), "=f"(r.y) : "l"(v));
    return r;
}
__device__ __forceinline__ unsigned long long ffma2(unsigned long long a, unsigned long long b,
                                                    unsigned long long c) {
    unsigned long long d;
    asm("fma.rn.f32x2 %0, %1, %2, %3;" : "=l"(d) : "l"(a), "l"(b), "l"(c));
    return d;
}
__device__ __forceinline__ uint32_t smem_u32(const void* p) {
    uint32_t a;
    asm("{ .reg .u64 t; cvta.to.shared.u64 t, %1; cvt.u32.u64 %0, t; }" : "=r"(a) : "l"(p));
    return a;
}
__device__ __forceinline__ void ldsm4(uint32_t* r, uint32_t addr) {
    asm volatile("ldmatrix.sync.aligned.m8n8.x4.shared.b16 {%0,%1,%2,%3}, [%4];"
                 : "=r"(r[0]), "=r"(r[1]), "=r"(r[2]), "=r"(r[3]) : "r"(addr));
}
__device__ __forceinline__ void mma16816(float* c, const uint32_t* a, uint32_t b0, uint32_t b1) {
    asm volatile(
        "mma.sync.aligned.m16n8k16.row.col.f32.bf16.bf16.f32 "
        "{%0,%1,%2,%3}, {%4,%5,%6,%7}, {%8,%9}, {%0,%1,%2,%3};"
        : "+f"(c[0]), "+f"(c[1]), "+f"(c[2]), "+f"(c[3])
        : "r"(a[0]), "r"(a[1]), "r"(a[2]), "r"(a[3]), "r"(b0), "r"(b1));
}
__device__ __forceinline__ void cp16(uint32_t saddr, const void* g) {
    asm volatile("cp.async.cg.shared.global [%0], [%1], 16;" :: "r"(saddr), "l"(g));
}
#define CP_COMMIT() asm volatile("cp.async.commit_group;" ::: "memory")
#define CP_WAIT1()  asm volatile("cp.async.wait_group 1;" ::: "memory")
#define CP_WAIT0()  asm volatile("cp.async.wait_group 0;" ::: "memory")

// ------------------------- kernel 0: init sort scratch -------------------------
__global__ void k_init() {
    int i = blockIdx.x * blockDim.x + threadIdx.x;
    if (i < NN) {
        g_cnt[i] = 0;
        g_cursor[i] = 0;
    }
}

// ------------------------- kernel 1: fused weights (transposed, bf16 hi/lo) ----
__global__ void k_prep(const float* __restrict__ Wq, const float* __restrict__ bq,
                       const float* __restrict__ Wk, const float* __restrict__ bk,
                       const float* __restrict__ Wv, const float* __restrict__ bv,
                       const float* __restrict__ We,
                       const float* __restrict__ Ws, const float* __restrict__ bs) {
    int i = blockIdx.x;  // 0..127 (input dim k)
    for (int c = threadIdx.x; c < WC; c += blockDim.x) {
        float w = 0.0f, b = 0.0f;
        if (c < 128)      { w = Wq[i * 128 + c];         b = bq[c]; }
        else if (c < 256) { w = Wk[i * 128 + (c - 128)]; b = bk[c - 128]; }
        else if (c < 384) { w = Wv[i * 128 + (c - 256)]; b = bv[c - 256]; }
        else if (c < 512) { w = Ws[i * 128 + (c - 384)]; b = bs[c - 384]; }
        else if (c < 704) {
            int hd = c - 512;
            int h = hd / 96, d = hd % 96;
            float acc = 0.0f, accb = 0.0f;
            #pragma unroll 8
            for (int cc = 0; cc < 64; ++cc) {
                float we = We[d * 128 + h * 64 + cc];
                acc = fmaf(Wq[i * 128 + h * 64 + cc], we, acc);
                accb = fmaf(bq[h * 64 + cc], we, accb);
            }
            w = acc; b = accb;
        }
        __nv_bfloat16 hi = __float2bfloat16(w);
        __nv_bfloat16 lo = __float2bfloat16(w - __bfloat162float(hi));
        g_whT[c * 128 + i] = hi;
        g_wlT[c * 128 + i] = lo;
        if (i == 0) g_bias[c] = b;
    }
}

// ------------------------- kernel 2: HMMA node GEMM (cp.async pipelined B) -----
#define A_STRIDE 136
#define B_STRIDE 72
#define SZ_A (128 * A_STRIDE * 2)         // 34816
#define SZ_B (128 * B_STRIDE * 2)         // 18432
#define SM_A_HI 0
#define SM_A_LO (SZ_A)
#define SM_B    (2 * SZ_A)                // 2 buffers x (hi, lo)
#define SM_BIAS (2 * SZ_A + 4 * SZ_B)
#define SM_TOT  (SM_BIAS + WC * 4)        // 146432

__device__ __forceinline__ void load_B_async(uint32_t sb, int s, int tid) {
    const int chunk = s >> 1, kh = s & 1;
    const uint32_t bbase = SM_B + (uint32_t)(s & 1) * (2 * SZ_B);
    for (int i = tid; i < 128 * 8; i += 256) {
        int c = i >> 3, seg = i & 7;
        size_t gsrc = (size_t)(chunk * 128 + c) * 128 + kh * 64 + seg * 8;
        uint32_t doff = (uint32_t)(c * (B_STRIDE * 2) + seg * 16);
        cp16(sb + bbase + doff, g_whT + gsrc);
        cp16(sb + bbase + SZ_B + doff, g_wlT + gsrc);
    }
}

__global__ void __launch_bounds__(256, 1) k_gemm_mma(const float* __restrict__ x,
                                                     float* __restrict__ out) {
    extern __shared__ char smem[];
    const uint32_t sb = smem_u32(smem);
    const int tid = threadIdx.x, wid = tid >> 5, lane = tid & 31;
    const int row0 = blockIdx.x * 128;

    load_B_async(sb, 0, tid);
    CP_COMMIT();

    float* sbias = (float*)(smem + SM_BIAS);
    for (int i = tid; i < WC; i += 256) sbias[i] = g_bias[i];

    for (int i = tid; i < 128 * 32; i += 256) {
        int r = i >> 5, k4 = (i & 31) << 2;
        int row = row0 + r;
        float4 v = (row < NN) ? *(const float4*)(x + (size_t)row * 128 + k4)
                              : make_float4(0.f, 0.f, 0.f, 0.f);
        __nv_bfloat16 h0 = __float2bfloat16(v.x), h1 = __float2bfloat16(v.y);
        __nv_bfloat16 h2 = __float2bfloat16(v.z), h3 = __float2bfloat16(v.w);
        __nv_bfloat16 l0 = __float2bfloat16(v.x - __bfloat162float(h0));
        __nv_bfloat16 l1 = __float2bfloat16(v.y - __bfloat162float(h1));
        __nv_bfloat16 l2 = __float2bfloat16(v.z - __bfloat162float(h2));
        __nv_bfloat16 l3 = __float2bfloat16(v.w - __bfloat162float(h3));
        __nv_bfloat162 ph0(h0, h1), ph1(h2, h3), pl0(l0, l1), pl1(l2, l3);
        uint32_t off = (uint32_t)(r * (A_STRIDE * 2) + k4 * 2);
        *(uint2*)(smem + SM_A_HI + off) = make_uint2(*(uint32_t*)&ph0, *(uint32_t*)&ph1);
        *(uint2*)(smem + SM_A_LO + off) = make_uint2(*(uint32_t*)&pl0, *(uint32_t*)&pl1);
    }

    const int wm = wid & 1, wn = wid >> 1;
    const int rw = wm * 64, cw = wn * 32;
    const uint32_t a_off = (uint32_t)((rw + (lane & 15)) * (A_STRIDE * 2) + (lane >> 4) * 16);
    const uint32_t b_off = (uint32_t)((cw + (lane & 15)) * (B_STRIDE * 2) + (lane >> 4) * 16);
    const int trow = lane >> 2;
    const int tcol = (lane & 3) * 2;

    float acc[4][4][4];

    for (int s = 0; s < 12; ++s) {
        const int chunk = s >> 1, kh = s & 1;
        if (kh == 0) {
            #pragma unroll
            for (int i = 0; i < 4; ++i)
                #pragma unroll
                for (int j = 0; j < 4; ++j)
                    #pragma unroll
                    for (int q = 0; q < 4; ++q) acc[i][j][q] = 0.0f;
        }
        if (s + 1 < 12) {
            load_B_async(sb, s + 1, tid);
            CP_COMMIT();
            CP_WAIT1();
        } else {
            CP_WAIT0();
        }
        __syncthreads();

        const uint32_t bbase = SM_B + (uint32_t)(s & 1) * (2 * SZ_B);
        #pragma unroll
        for (int term = 0; term < 3; ++term) {
            const uint32_t sA = sb + ((term == 2) ? SM_A_LO : SM_A_HI) + kh * 128;
            const uint32_t sB = sb + bbase + ((term == 1) ? SZ_B : 0);
            #pragma unroll
            for (int ks = 0; ks < 4; ++ks) {
                uint32_t a[4][4], b[2][4];
                #pragma unroll
                for (int i = 0; i < 4; ++i)
                    ldsm4(a[i], sA + a_off + i * (16 * A_STRIDE * 2) + ks * 32);
                #pragma unroll
                for (int j16 = 0; j16 < 2; ++j16)
                    ldsm4(b[j16], sB + b_off + j16 * (16 * B_STRIDE * 2) + ks * 32);
                #pragma unroll
                for (int i = 0; i < 4; ++i) {
                    mma16816(acc[i][0], a[i], b[0][0], b[0][2]);
                    mma16816(acc[i][1], a[i], b[0][1], b[0][3]);
                    mma16816(acc[i][2], a[i], b[1][0], b[1][2]);
                    mma16816(acc[i][3], a[i], b[1][1], b[1][3]);
                }
            }
        }
        __syncthreads();

        if (kh == 1) {
            float* bp; int stride, sub;
            switch (chunk) {
                case 0:  bp = g_dst; stride = 320; sub = 0;   break;
                case 1:
                case 2:  bp = g_src; stride = 256; sub = 128; break;
                case 3:  bp = out;   stride = 128; sub = 384; break;
                default: bp = g_dst; stride = 320; sub = 384; break;
            }
            #pragma unroll
            for (int i = 0; i < 4; ++i) {
                int r = row0 + rw + i * 16 + trow;
                #pragma unroll
                for (int j = 0; j < 4; ++j) {
                    int G = chunk * 128 + cw + j * 8 + tcol;
                    if (G >= 704) continue;
                    float b0 = sbias[G], b1 = sbias[G + 1];
                    if (r < NN) {
                        float2 v = make_float2(acc[i][j][0] + b0, acc[i][j][1] + b1);
                        *(float2*)(bp + (size_t)r * stride + (G - sub)) = v;
                    }
                    if (r + 8 < NN) {
                        float2 v = make_float2(acc[i][j][2] + b0, acc[i][j][3] + b1);
                        *(float2*)(bp + (size_t)(r + 8) * stride + (G - sub)) = v;
                    }
                }
            }
        }
    }
}

// ------------------------- sort: histogram, scan, permute -------------------------
__global__ void k_hist(const int* __restrict__ ei) {
    int i = blockIdx.x * blockDim.x + threadIdx.x;
    if (i < EE) atomicAdd(&g_cnt[ei[EE + i]], 1);
}

__global__ void k_scan_a() {
    __shared__ int sm[256];
    int t = threadIdx.x;
    int gid = blockIdx.x * 256 + t;
    int val = (gid < NN) ? g_cnt[gid] : 0;
    sm[t] = val;
    __syncthreads();
    #pragma unroll
    for (int o = 1; o < 256; o <<= 1) {
        int add = (t >= o) ? sm[t - o] : 0;
        __syncthreads();
        sm[t] += add;
        __syncthreads();
    }
    if (gid < NN) g_off[gid] = sm[t] - val;
    if (t == 255) g_bsum[blockIdx.x] = sm[255];
}

__global__ void k_scan_b(int nblk) {
    __shared__ int sm[512];
    int t = threadIdx.x;
    int val = (t < nblk) ? g_bsum[t] : 0;
    sm[t] = val;
    __syncthreads();
    #pragma unroll
    for (int o = 1; o < 512; o <<= 1) {
        int add = (t >= o) ? sm[t - o] : 0;
        __syncthreads();
        sm[t] += add;
        __syncthreads();
    }
    if (t < nblk) g_bsum[t] = sm[t] - val;
}

__global__ void k_scan_c() {
    int gid = blockIdx.x * 256 + threadIdx.x;
    if (gid < NN) g_off[gid] += g_bsum[blockIdx.x];
    if (gid == 0) g_off[NN] = EE;
}

__global__ void k_permute(const int* __restrict__ ei, const float* __restrict__ lu,
                          const float* __restrict__ tv) {
    int i = blockIdx.x * blockDim.x + threadIdx.x;
    if (i >= EE) return;
    int d = ei[EE + i];
    int s = ei[i];
    int pos = g_off[d] + atomicAdd(&g_cursor[d], 1);
    g_esrc[pos] = s;
    g_eidx[pos] = i;
    g_erel[pos] = lu[s] - tv[i];
}

// ------------------------- kernel 3: fused edge pass (warp per dst node) -------
// Direct softmax (no running max — logits bounded ~|11| << 88), joint folded
// reductions, MLP-4 batches, no atomics.
__global__ void __launch_bounds__(256) k_edge(const float* __restrict__ msg,
                                              const float* __restrict__ time_w,
                                              const float* __restrict__ time_b,
                                              float* __restrict__ out) {
    int n = (blockIdx.x * blockDim.x + threadIdx.x) >> 5;
    int lane = threadIdx.x & 31;
    if (n >= NN) return;
    const int off0 = g_off[n];
    const int deg = g_off[n + 1] - off0;

    const float* dp = g_dst + (size_t)n * 320;
    const float4 q4 = *(const float4*)(dp + lane * 4);
    const float p00 = dp[128 + lane], p01 = dp[160 + lane], p02 = dp[192 + lane];
    const float p10 = dp[224 + lane], p11 = dp[256 + lane], p12 = dp[288 + lane];
    const float tww = time_w[lane], tbb = time_b[lane];
    const bool h0lane = (lane < 16);

    float den0 = 0.f, den1 = 0.f;
    float4 aco = make_float4(0.f, 0.f, 0.f, 0.f);
    float2 as0 = make_float2(0.f, 0.f), as1 = as0, as2 = as0;

    for (int eb = 0; eb < deg; eb += 4) {
        const int nb = deg - eb;
        int srcj[4], idxj[4];
        float relj[4], ea0[4], ea1[4], ea2[4], u0[4], u1[4];
        float4 k4[4], v4[4];
        #pragma unroll
        for (int j = 0; j < 4; ++j) {
            int pos = off0 + eb + ((j < nb) ? j : 0);
            srcj[j] = g_esrc[pos];
            idxj[j] = g_eidx[pos];
            relj[j] = g_erel[pos];
        }
        #pragma unroll
        for (int j = 0; j < 4; ++j) {
            const float* sp = g_src + (size_t)srcj[j] * 256;
            k4[j] = *(const float4*)(sp + lane * 4);
            v4[j] = *(const float4*)(sp + 128 + lane * 4);
            ea1[j] = msg[(size_t)idxj[j] * 64 + lane];
            ea2[j] = msg[(size_t)idxj[j] * 64 + 32 + lane];
        }
        // fold per-lane qk partial into head-wise reduction operands
        #pragma unroll
        for (int j = 0; j < 4; ++j) {
            float qk = q4.x * k4[j].x + q4.y * k4[j].y + q4.z * k4[j].z + q4.w * k4[j].w;
            ea0[j] = cosf(fmaf(relj[j], tww, tbb));
            u0[j] = ea0[j] * p00 + ea1[j] * p01 + ea2[j] * p02 + (h0lane ? qk : 0.f);
            u1[j] = ea0[j] * p10 + ea1[j] * p11 + ea2[j] * p12 + (h0lane ? 0.f : qk);
        }
        // joint butterfly reduction: 8 independent chains
        #pragma unroll
        for (int o = 16; o; o >>= 1) {
            #pragma unroll
            for (int j = 0; j < 4; ++j) {
                u0[j] += __shfl_xor_sync(0xffffffffu, u0[j], o);
                u1[j] += __shfl_xor_sync(0xffffffffu, u1[j], o);
            }
        }
        #pragma unroll
        for (int j = 0; j < 4; ++j) {
            if (j < nb) {
                float e0 = __expf(u0[j] * 0.125f);
                float e1 = __expf(u1[j] * 0.125f);
                den0 += e0; den1 += e1;
                float eh = h0lane ? e0 : e1;
                aco.x = fmaf(v4[j].x, eh, aco.x);
                aco.y = fmaf(v4[j].y, eh, aco.y);
                aco.z = fmaf(v4[j].z, eh, aco.z);
                aco.w = fmaf(v4[j].w, eh, aco.w);
                as0.x = fmaf(ea0[j], e0, as0.x);  as0.y = fmaf(ea0[j], e1, as0.y);
                as1.x = fmaf(ea1[j], e0, as1.x);  as1.y = fmaf(ea1[j], e1, as1.y);
                as2.x = fmaf(ea2[j], e0, as2.x);  as2.y = fmaf(ea2[j], e1, as2.y);
            }
        }
    }

    if (deg > 0) {
        float i0 = 1.0f / (den0 + 1e-16f);
        float i1 = 1.0f / (den1 + 1e-16f);
        float ih = h0lane ? i0 : i1;
        float4 o4 = *(const float4*)(out + (size_t)n * 128 + lane * 4);
        o4.x += aco.x * ih; o4.y += aco.y * ih;
        o4.z += aco.z * ih; o4.w += aco.w * ih;
        *(float4*)(out + (size_t)n * 128 + lane * 4) = o4;
        float2* sp2 = (float2*)(g_s + (size_t)n * 192);
        sp2[lane]      = make_float2(as0.x * i0, as0.y * i1);
        sp2[lane + 32] = make_float2(as1.x * i0, as1.y * i1);
        sp2[lane + 64] = make_float2(as2.x * i0, as2.y * i1);
    } else {
        float2* sp2 = (float2*)(g_s + (size_t)n * 192);
        float2 z = make_float2(0.f, 0.f);
        sp2[lane] = z; sp2[lane + 32] = z; sp2[lane + 64] = z;
    }
}

// ------------------------- kernel 4: out += s @ We -------------------------
__global__ void k_final(const float* __restrict__ We, float* __restrict__ out) {
    extern __shared__ float sm[];
    float* sS = sm;              // [d][h][r]: 96*2*128
    float* sW = sm + 96 * 256;   // [d][c]:   96*128
    const int row0 = blockIdx.x * 128;
    const int t = threadIdx.x;

    for (int i = t; i < 96 * 32; i += 256) {
        int d = i >> 5, c4 = (i & 31) << 2;
        *(float4*)(sW + d * 128 + c4) = *(const float4*)(We + d * 128 + c4);
    }
    for (int i = t; i < 128 * 96; i += 256) {
        int r = i / 96, d = i % 96;
        int row = row0 + r;
        float2 v = (row < NN) ? *(const float2*)(g_s + (size_t)row * 192 + d * 2)
                              : make_float2(0.f, 0.f);
        sS[d * 256 + r] = v.x;
        sS[d * 256 + 128 + r] = v.y;
    }
    __syncthreads();

    const int tx = t & 15, ty = t >> 4;
    const int r0 = ty * 8, c0 = tx * 8;
    const int h = c0 >> 6;

    unsigned long long acc[4][8];
    #pragma unroll
    for (int i = 0; i < 4; ++i)
        #pragma unroll
        for (int j = 0; j < 8; ++j) acc[i][j] = 0ULL;

    #pragma unroll 4
    for (int d = 0; d < 96; ++d) {
        float4 a0 = *(float4*)(sS + d * 256 + h * 128 + r0);
        float4 a1 = *(float4*)(sS + d * 256 + h * 128 + r0 + 4);
        float4 b0 = *(float4*)(sW + d * 128 + c0);
        float4 b1 = *(float4*)(sW + d * 128 + c0 + 4);
        unsigned long long A[4] = {pk2(a0.x, a0.y), pk2(a0.z, a0.w),
                                   pk2(a1.x, a1.y), pk2(a1.z, a1.w)};
        float bs8[8] = {b0.x, b0.y, b0.z, b0.w, b1.x, b1.y, b1.z, b1.w};
        #pragma unroll
        for (int j = 0; j < 8; ++j) {
            unsigned long long B = pk2(bs8[j], bs8[j]);
            #pragma unroll
            for (int i = 0; i < 4; ++i) acc[i][j] = ffma2(A[i], B, acc[i][j]);
        }
    }

    #pragma unroll
    for (int j = 0; j < 8; ++j) {
        int col = c0 + j;
        #pragma unroll
        for (int i = 0; i < 4; ++i) {
            float2 v = upk2(acc[i][j]);
            int r = row0 + r0 + 2 * i;
            if (r < NN)     out[(size_t)r * 128 + col] += v.x;
            if (r + 1 < NN) out[(size_t)(r + 1) * 128 + col] += v.y;
        }
    }
}

// ------------------------- launch -------------------------
extern "C" void kernel_launch(void* const* d_in, const int* in_sizes, int n_in,
                              void* d_out, int out_size) {
    const float* x   = (const float*)d_in[0];
    const float* lu  = (const float*)d_in[1];
    const float* tv  = (const float*)d_in[2];
    const float* msg = (const float*)d_in[3];
    const int*   ei  = (const int*)d_in[4];
    const float* tw  = (const float*)d_in[5];
    const float* tb  = (const float*)d_in[6];
    const float* Wq  = (const float*)d_in[7];
    const float* bq  = (const float*)d_in[8];
    const float* Wk  = (const float*)d_in[9];
    const float* bk  = (const float*)d_in[10];
    const float* Wv  = (const float*)d_in[11];
    const float* bv  = (const float*)d_in[12];
    const float* We  = (const float*)d_in[13];
    const float* Ws  = (const float*)d_in[14];
    const float* bs  = (const float*)d_in[15];
    float* out = (float*)d_out;

    static cudaStream_t s2 = nullptr;
    static cudaEvent_t evFork = nullptr, evJoin = nullptr;
    if (!s2) {
        cudaFuncSetAttribute(k_gemm_mma, cudaFuncAttributeMaxDynamicSharedMemorySize, SM_TOT);
        cudaFuncSetAttribute(k_final, cudaFuncAttributeMaxDynamicSharedMemorySize,
                             (96 * 256 + 96 * 128) * 4);
        cudaStreamCreateWithFlags(&s2, cudaStreamNonBlocking);
        cudaEventCreateWithFlags(&evFork, cudaEventDisableTiming);
        cudaEventCreateWithFlags(&evJoin, cudaEventDisableTiming);
    }

    const int nblk = (NN + 255) / 256;  // 391

    // Fork: sort chain on s2, concurrent with weight prep + node GEMM.
    cudaEventRecord(evFork, 0);
    cudaStreamWaitEvent(s2, evFork, 0);

    k_init<<<nblk, 256, 0, s2>>>();
    k_hist<<<(EE + 255) / 256, 256, 0, s2>>>(ei);
    k_scan_a<<<nblk, 256, 0, s2>>>();
    k_scan_b<<<1, 512, 0, s2>>>(nblk);
    k_scan_c<<<nblk, 256, 0, s2>>>();
    k_permute<<<(EE + 255) / 256, 256, 0, s2>>>(ei, lu, tv);
    cudaEventRecord(evJoin, s2);

    // Main stream: weights -> node GEMM (writes g_dst q/p, g_src k/v, skip->out)
    k_prep<<<128, 256>>>(Wq, bq, Wk, bk, Wv, bv, We, Ws, bs);
    k_gemm_mma<<<(NN + 127) / 128, 256, SM_TOT>>>(x, out);

    // Join, then fused edge pass + final GEMM.
    cudaStreamWaitEvent(0, evJoin, 0);
    k_edge<<<(NN * 32 + 255) / 256, 256>>>(msg, tw, tb, out);
    k_final<<<(NN + 127) / 128, 256, (96 * 256 + 96 * 128) * 4>>>(We, out);
}

// round 7
// speedup vs baseline: 2.2402x; 1.0812x over previous
#include <cuda_runtime.h>
#include <cuda_bf16.h>
#include <math_constants.h>
#include <cstdint>

// Problem constants (fixed shapes)
#define NN 100000
#define EE 800000
#define WC 768   // fused weight cols: [q 128][k 128][v 128][skip 128][p0 96][p1 96][pad 64]

// ------------------------- device scratch -------------------------
__device__ float g_dst[(size_t)NN * 320];            // per-node dst data: q[128], p[192]
__device__ float g_src[(size_t)NN * 256];            // per-node src data: k[128], v[128]
__device__ __nv_bfloat16 g_whT[WC * 128];            // W^T hi (bf16), [col][k]
__device__ __nv_bfloat16 g_wlT[WC * 128];            // W^T lo (bf16)
__device__ float g_bias[WC];
__device__ float g_s[(size_t)NN * 192];              // s[n][d][h], d<96, h<2
// sort scratch (SoA sorted edge data)
__device__ int g_cnt[NN];
__device__ int g_off[NN + 1];
__device__ int g_cursor[NN];
__device__ int g_esrc[EE];
__device__ int g_eidx[EE];
__device__ float g_erel[EE];
__device__ int g_bsum[512];

// ------------------------- generic helpers -------------------------
__device__ __forceinline__ unsigned long long pk2(float lo, float hi) {
    unsigned long long r;
    asm("mov.b64 %0, {%1,%2};" : "=l"(r) : "f"(lo), "f"(hi));
    return r;
}
__device__ __forceinline__ float2 upk2(unsigned long long v) {
    float2 r;
    asm("mov.b64 {%0,%1}, %2;" : "=f"(r.x), "=f"(r.y) : "l"(v));
    return r;
}
__device__ __forceinline__ unsigned long long ffma2(unsigned long long a, unsigned long long b,
                                                    unsigned long long c) {
    unsigned long long d;
    asm("fma.rn.f32x2 %0, %1, %2, %3;" : "=l"(d) : "l"(a), "l"(b), "l"(c));
    return d;
}
__device__ __forceinline__ uint32_t smem_u32(const void* p) {
    uint32_t a;
    asm("{ .reg .u64 t; cvta.to.shared.u64 t, %1; cvt.u32.u64 %0, t; }" : "=r"(a) : "l"(p));
    return a;
}
__device__ __forceinline__ void ldsm4(uint32_t* r, uint32_t addr) {
    asm volatile("ldmatrix.sync.aligned.m8n8.x4.shared.b16 {%0,%1,%2,%3}, [%4];"
                 : "=r"(r[0]), "=r"(r[1]), "=r"(r[2]), "=r"(r[3]) : "r"(addr));
}
__device__ __forceinline__ void mma16816(float* c, const uint32_t* a, uint32_t b0, uint32_t b1) {
    asm volatile(
        "mma.sync.aligned.m16n8k16.row.col.f32.bf16.bf16.f32 "
        "{%0,%1,%2,%3}, {%4,%5,%6,%7}, {%8,%9}, {%0,%1,%2,%3};"
        : "+f"(c[0]), "+f"(c[1]), "+f"(c[2]), "+f"(c[3])
        : "r"(a[0]), "r"(a[1]), "r"(a[2]), "r"(a[3]), "r"(b0), "r"(b1));
}
__device__ __forceinline__ void cp16(uint32_t saddr, const void* g) {
    asm volatile("cp.async.cg.shared.global [%0], [%1], 16;" :: "r"(saddr), "l"(g));
}
#define CP_COMMIT() asm volatile("cp.async.commit_group;" ::: "memory")
#define CP_WAIT1()  asm volatile("cp.async.wait_group 1;" ::: "memory")
#define CP_WAIT0()  asm volatile("cp.async.wait_group 0;" ::: "memory")

// ------------------------- kernel 0: init sort scratch -------------------------
__global__ void k_init() {
    int i = blockIdx.x * blockDim.x + threadIdx.x;
    if (i < NN) {
        g_cnt[i] = 0;
        g_cursor[i] = 0;
    }
}

// ------------------------- kernel 1: fused weights (transposed, bf16 hi/lo) ----
__global__ void k_prep(const float* __restrict__ Wq, const float* __restrict__ bq,
                       const float* __restrict__ Wk, const float* __restrict__ bk,
                       const float* __restrict__ Wv, const float* __restrict__ bv,
                       const float* __restrict__ We,
                       const float* __restrict__ Ws, const float* __restrict__ bs) {
    int i = blockIdx.x;  // 0..127 (input dim k)
    for (int c = threadIdx.x; c < WC; c += blockDim.x) {
        float w = 0.0f, b = 0.0f;
        if (c < 128)      { w = Wq[i * 128 + c];         b = bq[c]; }
        else if (c < 256) { w = Wk[i * 128 + (c - 128)]; b = bk[c - 128]; }
        else if (c < 384) { w = Wv[i * 128 + (c - 256)]; b = bv[c - 256]; }
        else if (c < 512) { w = Ws[i * 128 + (c - 384)]; b = bs[c - 384]; }
        else if (c < 704) {
            int hd = c - 512;
            int h = hd / 96, d = hd % 96;
            float acc = 0.0f, accb = 0.0f;
            #pragma unroll 8
            for (int cc = 0; cc < 64; ++cc) {
                float we = We[d * 128 + h * 64 + cc];
                acc = fmaf(Wq[i * 128 + h * 64 + cc], we, acc);
                accb = fmaf(bq[h * 64 + cc], we, accb);
            }
            w = acc; b = accb;
        }
        __nv_bfloat16 hi = __float2bfloat16(w);
        __nv_bfloat16 lo = __float2bfloat16(w - __bfloat162float(hi));
        g_whT[c * 128 + i] = hi;
        g_wlT[c * 128 + i] = lo;
        if (i == 0) g_bias[c] = b;
    }
}

// ------------------------- kernel 2: HMMA node GEMM (64-row tiles, 2 CTA/SM) ---
#define A_ROWS 64
#define A_STRIDE 136
#define B_STRIDE 72
#define SZ_A (A_ROWS * A_STRIDE * 2)      // 17408
#define SZ_B (128 * B_STRIDE * 2)         // 18432
#define SM_A_HI 0
#define SM_A_LO (SZ_A)
#define SM_B    (2 * SZ_A)                // 2 buffers x (hi, lo)
#define SM_BIAS (2 * SZ_A + 4 * SZ_B)
#define SM_TOT  (SM_BIAS + WC * 4)        // 111616

__device__ __forceinline__ void load_B_async(uint32_t sb, int s, int tid) {
    const int chunk = s >> 1, kh = s & 1;
    const uint32_t bbase = SM_B + (uint32_t)(s & 1) * (2 * SZ_B);
    for (int i = tid; i < 128 * 8; i += 256) {
        int c = i >> 3, seg = i & 7;
        size_t gsrc = (size_t)(chunk * 128 + c) * 128 + kh * 64 + seg * 8;
        uint32_t doff = (uint32_t)(c * (B_STRIDE * 2) + seg * 16);
        cp16(sb + bbase + doff, g_whT + gsrc);
        cp16(sb + bbase + SZ_B + doff, g_wlT + gsrc);
    }
}

__global__ void __launch_bounds__(256, 2) k_gemm_mma(const float* __restrict__ x,
                                                     float* __restrict__ out) {
    extern __shared__ char smem[];
    const uint32_t sb = smem_u32(smem);
    const int tid = threadIdx.x, wid = tid >> 5, lane = tid & 31;
    const int row0 = blockIdx.x * A_ROWS;

    load_B_async(sb, 0, tid);
    CP_COMMIT();

    float* sbias = (float*)(smem + SM_BIAS);
    for (int i = tid; i < WC; i += 256) sbias[i] = g_bias[i];

    // load A tile [64x128], split bf16 hi/lo
    for (int i = tid; i < A_ROWS * 32; i += 256) {
        int r = i >> 5, k4 = (i & 31) << 2;
        int row = row0 + r;
        float4 v = (row < NN) ? __ldcs((const float4*)(x + (size_t)row * 128 + k4))
                              : make_float4(0.f, 0.f, 0.f, 0.f);
        __nv_bfloat16 h0 = __float2bfloat16(v.x), h1 = __float2bfloat16(v.y);
        __nv_bfloat16 h2 = __float2bfloat16(v.z), h3 = __float2bfloat16(v.w);
        __nv_bfloat16 l0 = __float2bfloat16(v.x - __bfloat162float(h0));
        __nv_bfloat16 l1 = __float2bfloat16(v.y - __bfloat162float(h1));
        __nv_bfloat16 l2 = __float2bfloat16(v.z - __bfloat162float(h2));
        __nv_bfloat16 l3 = __float2bfloat16(v.w - __bfloat162float(h3));
        __nv_bfloat162 ph0(h0, h1), ph1(h2, h3), pl0(l0, l1), pl1(l2, l3);
        uint32_t off = (uint32_t)(r * (A_STRIDE * 2) + k4 * 2);
        *(uint2*)(smem + SM_A_HI + off) = make_uint2(*(uint32_t*)&ph0, *(uint32_t*)&ph1);
        *(uint2*)(smem + SM_A_LO + off) = make_uint2(*(uint32_t*)&pl0, *(uint32_t*)&pl1);
    }

    const int wm = wid & 1, wn = wid >> 1;       // warp grid 2 x 4
    const int rw = wm * 32, cw = wn * 32;        // warp tile 32 x 32
    const uint32_t a_off = (uint32_t)((rw + (lane & 15)) * (A_STRIDE * 2) + (lane >> 4) * 16);
    const uint32_t b_off = (uint32_t)((cw + (lane & 15)) * (B_STRIDE * 2) + (lane >> 4) * 16);
    const int trow = lane >> 2;
    const int tcol = (lane & 3) * 2;

    float acc[2][4][4];

    for (int s = 0; s < 12; ++s) {
        const int chunk = s >> 1, kh = s & 1;
        if (kh == 0) {
            #pragma unroll
            for (int i = 0; i < 2; ++i)
                #pragma unroll
                for (int j = 0; j < 4; ++j)
                    #pragma unroll
                    for (int q = 0; q < 4; ++q) acc[i][j][q] = 0.0f;
        }
        if (s + 1 < 12) {
            load_B_async(sb, s + 1, tid);
            CP_COMMIT();
            CP_WAIT1();
        } else {
            CP_WAIT0();
        }
        __syncthreads();

        const uint32_t bbase = SM_B + (uint32_t)(s & 1) * (2 * SZ_B);
        #pragma unroll
        for (int term = 0; term < 3; ++term) {
            const uint32_t sA = sb + ((term == 2) ? SM_A_LO : SM_A_HI) + kh * 128;
            const uint32_t sB = sb + bbase + ((term == 1) ? SZ_B : 0);
            #pragma unroll
            for (int ks = 0; ks < 4; ++ks) {
                uint32_t a[2][4], b[2][4];
                #pragma unroll
                for (int i = 0; i < 2; ++i)
                    ldsm4(a[i], sA + a_off + i * (16 * A_STRIDE * 2) + ks * 32);
                #pragma unroll
                for (int j16 = 0; j16 < 2; ++j16)
                    ldsm4(b[j16], sB + b_off + j16 * (16 * B_STRIDE * 2) + ks * 32);
                #pragma unroll
                for (int i = 0; i < 2; ++i) {
                    mma16816(acc[i][0], a[i], b[0][0], b[0][2]);
                    mma16816(acc[i][1], a[i], b[0][1], b[0][3]);
                    mma16816(acc[i][2], a[i], b[1][0], b[1][2]);
                    mma16816(acc[i][3], a[i], b[1][1], b[1][3]);
                }
            }
        }
        __syncthreads();

        if (kh == 1) {
            float* bp; int stride, sub; bool stream;
            switch (chunk) {
                case 0:  bp = g_dst; stride = 320; sub = 0;   stream = true;  break;
                case 1:
                case 2:  bp = g_src; stride = 256; sub = 128; stream = false; break;
                case 3:  bp = out;   stride = 128; sub = 384; stream = true;  break;
                default: bp = g_dst; stride = 320; sub = 384; stream = true;  break;
            }
            #pragma unroll
            for (int i = 0; i < 2; ++i) {
                int r = row0 + rw + i * 16 + trow;
                #pragma unroll
                for (int j = 0; j < 4; ++j) {
                    int G = chunk * 128 + cw + j * 8 + tcol;
                    if (G >= 704) continue;
                    float b0 = sbias[G], b1 = sbias[G + 1];
                    if (r < NN) {
                        float2 v = make_float2(acc[i][j][0] + b0, acc[i][j][1] + b1);
                        float2* p = (float2*)(bp + (size_t)r * stride + (G - sub));
                        if (stream) __stcs(p, v); else *p = v;
                    }
                    if (r + 8 < NN) {
                        float2 v = make_float2(acc[i][j][2] + b0, acc[i][j][3] + b1);
                        float2* p = (float2*)(bp + (size_t)(r + 8) * stride + (G - sub));
                        if (stream) __stcs(p, v); else *p = v;
                    }
                }
            }
        }
    }
}

// ------------------------- sort: histogram, scan, permute -------------------------
__global__ void k_hist(const int* __restrict__ ei) {
    int i = blockIdx.x * blockDim.x + threadIdx.x;
    if (i < EE) atomicAdd(&g_cnt[__ldcs(ei + EE + i)], 1);
}

__global__ void k_scan_a() {
    __shared__ int sm[256];
    int t = threadIdx.x;
    int gid = blockIdx.x * 256 + t;
    int val = (gid < NN) ? g_cnt[gid] : 0;
    sm[t] = val;
    __syncthreads();
    #pragma unroll
    for (int o = 1; o < 256; o <<= 1) {
        int add = (t >= o) ? sm[t - o] : 0;
        __syncthreads();
        sm[t] += add;
        __syncthreads();
    }
    if (gid < NN) g_off[gid] = sm[t] - val;
    if (t == 255) g_bsum[blockIdx.x] = sm[255];
}

__global__ void k_scan_b(int nblk) {
    __shared__ int sm[512];
    int t = threadIdx.x;
    int val = (t < nblk) ? g_bsum[t] : 0;
    sm[t] = val;
    __syncthreads();
    #pragma unroll
    for (int o = 1; o < 512; o <<= 1) {
        int add = (t >= o) ? sm[t - o] : 0;
        __syncthreads();
        sm[t] += add;
        __syncthreads();
    }
    if (t < nblk) g_bsum[t] = sm[t] - val;
}

__global__ void k_scan_c() {
    int gid = blockIdx.x * 256 + threadIdx.x;
    if (gid < NN) g_off[gid] += g_bsum[blockIdx.x];
    if (gid == 0) g_off[NN] = EE;
}

__global__ void k_permute(const int* __restrict__ ei, const float* __restrict__ lu,
                          const float* __restrict__ tv) {
    int i = blockIdx.x * blockDim.x + threadIdx.x;
    if (i >= EE) return;
    int d = __ldcs(ei + EE + i);
    int s = __ldcs(ei + i);
    int pos = g_off[d] + atomicAdd(&g_cursor[d], 1);
    g_esrc[pos] = s;
    g_eidx[pos] = i;
    g_erel[pos] = lu[s] - __ldcs(tv + i);
}

// ------------------------- kernel 3: fused edge pass (warp per dst node) -------
// Direct softmax; streaming cache hints on all zero-reuse data so g_src (102MB,
// ~8x reuse) stays L2-resident. No atomics.
__global__ void __launch_bounds__(256) k_edge(const float* __restrict__ msg,
                                              const float* __restrict__ time_w,
                                              const float* __restrict__ time_b,
                                              float* __restrict__ out) {
    int n = (blockIdx.x * blockDim.x + threadIdx.x) >> 5;
    int lane = threadIdx.x & 31;
    if (n >= NN) return;
    const int off0 = g_off[n];
    const int deg = g_off[n + 1] - off0;

    const float* dp = g_dst + (size_t)n * 320;
    const float4 q4 = __ldcs((const float4*)(dp + lane * 4));
    const float p00 = __ldcs(dp + 128 + lane), p01 = __ldcs(dp + 160 + lane);
    const float p02 = __ldcs(dp + 192 + lane), p10 = __ldcs(dp + 224 + lane);
    const float p11 = __ldcs(dp + 256 + lane), p12 = __ldcs(dp + 288 + lane);
    const float tww = time_w[lane], tbb = time_b[lane];
    const bool h0lane = (lane < 16);

    float den0 = 0.f, den1 = 0.f;
    float4 aco = make_float4(0.f, 0.f, 0.f, 0.f);
    float2 as0 = make_float2(0.f, 0.f), as1 = as0, as2 = as0;

    for (int eb = 0; eb < deg; eb += 4) {
        const int nb = deg - eb;
        int srcj[4], idxj[4];
        float relj[4], ea0[4], ea1[4], ea2[4], u0[4], u1[4];
        float4 k4[4], v4[4];
        #pragma unroll
        for (int j = 0; j < 4; ++j) {
            int pos = off0 + eb + ((j < nb) ? j : 0);
            srcj[j] = __ldcs(g_esrc + pos);
            idxj[j] = __ldcs(g_eidx + pos);
            relj[j] = __ldcs(g_erel + pos);
        }
        #pragma unroll
        for (int j = 0; j < 4; ++j) {
            const float* sp = g_src + (size_t)srcj[j] * 256;
            k4[j] = *(const float4*)(sp + lane * 4);          // cached: reused ~8x
            v4[j] = *(const float4*)(sp + 128 + lane * 4);
            ea1[j] = __ldcs(msg + (size_t)idxj[j] * 64 + lane);
            ea2[j] = __ldcs(msg + (size_t)idxj[j] * 64 + 32 + lane);
        }
        #pragma unroll
        for (int j = 0; j < 4; ++j) {
            float qk = q4.x * k4[j].x + q4.y * k4[j].y + q4.z * k4[j].z + q4.w * k4[j].w;
            ea0[j] = cosf(fmaf(relj[j], tww, tbb));
            u0[j] = ea0[j] * p00 + ea1[j] * p01 + ea2[j] * p02 + (h0lane ? qk : 0.f);
            u1[j] = ea0[j] * p10 + ea1[j] * p11 + ea2[j] * p12 + (h0lane ? 0.f : qk);
        }
        #pragma unroll
        for (int o = 16; o; o >>= 1) {
            #pragma unroll
            for (int j = 0; j < 4; ++j) {
                u0[j] += __shfl_xor_sync(0xffffffffu, u0[j], o);
                u1[j] += __shfl_xor_sync(0xffffffffu, u1[j], o);
            }
        }
        #pragma unroll
        for (int j = 0; j < 4; ++j) {
            if (j < nb) {
                float e0 = __expf(u0[j] * 0.125f);
                float e1 = __expf(u1[j] * 0.125f);
                den0 += e0; den1 += e1;
                float eh = h0lane ? e0 : e1;
                aco.x = fmaf(v4[j].x, eh, aco.x);
                aco.y = fmaf(v4[j].y, eh, aco.y);
                aco.z = fmaf(v4[j].z, eh, aco.z);
                aco.w = fmaf(v4[j].w, eh, aco.w);
                as0.x = fmaf(ea0[j], e0, as0.x);  as0.y = fmaf(ea0[j], e1, as0.y);
                as1.x = fmaf(ea1[j], e0, as1.x);  as1.y = fmaf(ea1[j], e1, as1.y);
                as2.x = fmaf(ea2[j], e0, as2.x);  as2.y = fmaf(ea2[j], e1, as2.y);
            }
        }
    }

    float2* sp2 = (float2*)(g_s + (size_t)n * 192);
    if (deg > 0) {
        float i0 = 1.0f / (den0 + 1e-16f);
        float i1 = 1.0f / (den1 + 1e-16f);
        float ih = h0lane ? i0 : i1;
        float4* op = (float4*)(out + (size_t)n * 128 + lane * 4);
        float4 o4 = __ldcs(op);
        o4.x += aco.x * ih; o4.y += aco.y * ih;
        o4.z += aco.z * ih; o4.w += aco.w * ih;
        __stcs(op, o4);
        __stcs(sp2 + lane,      make_float2(as0.x * i0, as0.y * i1));
        __stcs(sp2 + lane + 32, make_float2(as1.x * i0, as1.y * i1));
        __stcs(sp2 + lane + 64, make_float2(as2.x * i0, as2.y * i1));
    } else {
        float2 z = make_float2(0.f, 0.f);
        __stcs(sp2 + lane, z); __stcs(sp2 + lane + 32, z); __stcs(sp2 + lane + 64, z);
    }
}

// ------------------------- kernel 4: out += s @ We -------------------------
__global__ void k_final(const float* __restrict__ We, float* __restrict__ out) {
    extern __shared__ float sm[];
    float* sS = sm;              // [d][h][r]: 96*2*128
    float* sW = sm + 96 * 256;   // [d][c]:   96*128
    const int row0 = blockIdx.x * 128;
    const int t = threadIdx.x;

    for (int i = t; i < 96 * 32; i += 256) {
        int d = i >> 5, c4 = (i & 31) << 2;
        *(float4*)(sW + d * 128 + c4) = *(const float4*)(We + d * 128 + c4);
    }
    for (int i = t; i < 128 * 96; i += 256) {
        int r = i / 96, d = i % 96;
        int row = row0 + r;
        float2 v = (row < NN) ? __ldcs((const float2*)(g_s + (size_t)row * 192 + d * 2))
                              : make_float2(0.f, 0.f);
        sS[d * 256 + r] = v.x;
        sS[d * 256 + 128 + r] = v.y;
    }
    __syncthreads();

    const int tx = t & 15, ty = t >> 4;
    const int r0 = ty * 8, c0 = tx * 8;
    const int h = c0 >> 6;

    unsigned long long acc[4][8];
    #pragma unroll
    for (int i = 0; i < 4; ++i)
        #pragma unroll
        for (int j = 0; j < 8; ++j) acc[i][j] = 0ULL;

    #pragma unroll 4
    for (int d = 0; d < 96; ++d) {
        float4 a0 = *(float4*)(sS + d * 256 + h * 128 + r0);
        float4 a1 = *(float4*)(sS + d * 256 + h * 128 + r0 + 4);
        float4 b0 = *(float4*)(sW + d * 128 + c0);
        float4 b1 = *(float4*)(sW + d * 128 + c0 + 4);
        unsigned long long A[4] = {pk2(a0.x, a0.y), pk2(a0.z, a0.w),
                                   pk2(a1.x, a1.y), pk2(a1.z, a1.w)};
        float bs8[8] = {b0.x, b0.y, b0.z, b0.w, b1.x, b1.y, b1.z, b1.w};
        #pragma unroll
        for (int j = 0; j < 8; ++j) {
            unsigned long long B = pk2(bs8[j], bs8[j]);
            #pragma unroll
            for (int i = 0; i < 4; ++i) acc[i][j] = ffma2(A[i], B, acc[i][j]);
        }
    }

    #pragma unroll
    for (int j = 0; j < 8; ++j) {
        int col = c0 + j;
        #pragma unroll
        for (int i = 0; i < 4; ++i) {
            float2 v = upk2(acc[i][j]);
            int r = row0 + r0 + 2 * i;
            if (r < NN) {
                float* p = out + (size_t)r * 128 + col;
                __stcs(p, __ldcs(p) + v.x);
            }
            if (r + 1 < NN) {
                float* p = out + (size_t)(r + 1) * 128 + col;
                __stcs(p, __ldcs(p) + v.y);
            }
        }
    }
}

// ------------------------- launch -------------------------
extern "C" void kernel_launch(void* const* d_in, const int* in_sizes, int n_in,
                              void* d_out, int out_size) {
    const float* x   = (const float*)d_in[0];
    const float* lu  = (const float*)d_in[1];
    const float* tv  = (const float*)d_in[2];
    const float* msg = (const float*)d_in[3];
    const int*   ei  = (const int*)d_in[4];
    const float* tw  = (const float*)d_in[5];
    const float* tb  = (const float*)d_in[6];
    const float* Wq  = (const float*)d_in[7];
    const float* bq  = (const float*)d_in[8];
    const float* Wk  = (const float*)d_in[9];
    const float* bk  = (const float*)d_in[10];
    const float* Wv  = (const float*)d_in[11];
    const float* bv  = (const float*)d_in[12];
    const float* We  = (const float*)d_in[13];
    const float* Ws  = (const float*)d_in[14];
    const float* bs  = (const float*)d_in[15];
    float* out = (float*)d_out;

    static cudaStream_t s2 = nullptr;
    static cudaEvent_t evFork = nullptr, evJoin = nullptr;
    if (!s2) {
        cudaFuncSetAttribute(k_gemm_mma, cudaFuncAttributeMaxDynamicSharedMemorySize, SM_TOT);
        cudaFuncSetAttribute(k_final, cudaFuncAttributeMaxDynamicSharedMemorySize,
                             (96 * 256 + 96 * 128) * 4);
        cudaStreamCreateWithFlags(&s2, cudaStreamNonBlocking);
        cudaEventCreateWithFlags(&evFork, cudaEventDisableTiming);
        cudaEventCreateWithFlags(&evJoin, cudaEventDisableTiming);
    }

    const int nblk = (NN + 255) / 256;  // 391

    // Fork: sort chain on s2, concurrent with weight prep + node GEMM.
    cudaEventRecord(evFork, 0);
    cudaStreamWaitEvent(s2, evFork, 0);

    k_init<<<nblk, 256, 0, s2>>>();
    k_hist<<<(EE + 255) / 256, 256, 0, s2>>>(ei);
    k_scan_a<<<nblk, 256, 0, s2>>>();
    k_scan_b<<<1, 512, 0, s2>>>(nblk);
    k_scan_c<<<nblk, 256, 0, s2>>>();
    k_permute<<<(EE + 255) / 256, 256, 0, s2>>>(ei, lu, tv);
    cudaEventRecord(evJoin, s2);

    // Main stream: weights -> node GEMM (writes g_dst q/p, g_src k/v, skip->out)
    k_prep<<<128, 256>>>(Wq, bq, Wk, bk, Wv, bv, We, Ws, bs);
    k_gemm_mma<<<(NN + A_ROWS - 1) / A_ROWS, 256, SM_TOT>>>(x, out);

    // Join, then fused edge pass + final GEMM.
    cudaStreamWaitEvent(0, evJoin, 0);
    k_edge<<<(NN * 32 + 255) / 256, 256>>>(msg, tw, tb, out);
    k_final<<<(NN + 127) / 128, 256, (96 * 256 + 96 * 128) * 4>>>(We, out);
}

// round 8
// speedup vs baseline: 2.2999x; 1.0267x over previous
#include <cuda_runtime.h>
#include <cuda_bf16.h>
#include <cuda_fp16.h>
#include <math_constants.h>
#include <cstdint>

// Problem constants (fixed shapes)
#define NN 100000
#define EE 800000
#define WC 768   // fused weight cols: [q 128][k 128][v 128][skip 128][p0 96][p1 96][pad 64]

// ------------------------- device scratch -------------------------
__device__ float g_dst[(size_t)NN * 320];            // per-node dst data: q[128], p[192]
__device__ __half g_src[(size_t)NN * 256];           // per-node src data: k[128], v[128] fp16
__device__ __nv_bfloat16 g_whT[WC * 128];            // W^T hi (bf16), [col][k]
__device__ __nv_bfloat16 g_wlT[WC * 128];            // W^T lo (bf16)
__device__ float g_bias[WC];
__device__ float g_s[(size_t)NN * 192];              // s[n][d][h], d<96, h<2
// sort scratch (SoA sorted edge data)
__device__ int g_cnt[NN];
__device__ int g_off[NN + 1];
__device__ int g_cursor[NN];
__device__ int g_esrc[EE];
__device__ int g_eidx[EE];
__device__ float g_erel[EE];
__device__ int g_bsum[512];

// ------------------------- generic helpers -------------------------
__device__ __forceinline__ unsigned long long pk2(float lo, float hi) {
    unsigned long long r;
    asm("mov.b64 %0, {%1,%2};" : "=l"(r) : "f"(lo), "f"(hi));
    return r;
}
__device__ __forceinline__ float2 upk2(unsigned long long v) {
    float2 r;
    asm("mov.b64 {%0,%1}, %2;" : "=f"(r.x), "=f"(r.y) : "l"(v));
    return r;
}
__device__ __forceinline__ unsigned long long ffma2(unsigned long long a, unsigned long long b,
                                                    unsigned long long c) {
    unsigned long long d;
    asm("fma.rn.f32x2 %0, %1, %2, %3;" : "=l"(d) : "l"(a), "l"(b), "l"(c));
    return d;
}
__device__ __forceinline__ uint32_t smem_u32(const void* p) {
    uint32_t a;
    asm("{ .reg .u64 t; cvta.to.shared.u64 t, %1; cvt.u32.u64 %0, t; }" : "=r"(a) : "l"(p));
    return a;
}
__device__ __forceinline__ void ldsm4(uint32_t* r, uint32_t addr) {
    asm volatile("ldmatrix.sync.aligned.m8n8.x4.shared.b16 {%0,%1,%2,%3}, [%4];"
                 : "=r"(r[0]), "=r"(r[1]), "=r"(r[2]), "=r"(r[3]) : "r"(addr));
}
__device__ __forceinline__ void mma16816(float* c, const uint32_t* a, uint32_t b0, uint32_t b1) {
    asm volatile(
        "mma.sync.aligned.m16n8k16.row.col.f32.bf16.bf16.f32 "
        "{%0,%1,%2,%3}, {%4,%5,%6,%7}, {%8,%9}, {%0,%1,%2,%3};"
        : "+f"(c[0]), "+f"(c[1]), "+f"(c[2]), "+f"(c[3])
        : "r"(a[0]), "r"(a[1]), "r"(a[2]), "r"(a[3]), "r"(b0), "r"(b1));
}
__device__ __forceinline__ void cp16(uint32_t saddr, const void* g) {
    asm volatile("cp.async.cg.shared.global [%0], [%1], 16;" :: "r"(saddr), "l"(g));
}
#define CP_COMMIT() asm volatile("cp.async.commit_group;" ::: "memory")
#define CP_WAIT1()  asm volatile("cp.async.wait_group 1;" ::: "memory")
#define CP_WAIT0()  asm volatile("cp.async.wait_group 0;" ::: "memory")

// ------------------------- kernel 0: init sort scratch -------------------------
__global__ void k_init() {
    int i = blockIdx.x * blockDim.x + threadIdx.x;
    if (i < NN) {
        g_cnt[i] = 0;
        g_cursor[i] = 0;
    }
}

// ------------------------- kernel 1: fused weights (transposed, bf16 hi/lo) ----
__global__ void k_prep(const float* __restrict__ Wq, const float* __restrict__ bq,
                       const float* __restrict__ Wk, const float* __restrict__ bk,
                       const float* __restrict__ Wv, const float* __restrict__ bv,
                       const float* __restrict__ We,
                       const float* __restrict__ Ws, const float* __restrict__ bs) {
    int i = blockIdx.x;  // 0..127 (input dim k)
    for (int c = threadIdx.x; c < WC; c += blockDim.x) {
        float w = 0.0f, b = 0.0f;
        if (c < 128)      { w = Wq[i * 128 + c];         b = bq[c]; }
        else if (c < 256) { w = Wk[i * 128 + (c - 128)]; b = bk[c - 128]; }
        else if (c < 384) { w = Wv[i * 128 + (c - 256)]; b = bv[c - 256]; }
        else if (c < 512) { w = Ws[i * 128 + (c - 384)]; b = bs[c - 384]; }
        else if (c < 704) {
            int hd = c - 512;
            int h = hd / 96, d = hd % 96;
            float acc = 0.0f, accb = 0.0f;
            #pragma unroll 8
            for (int cc = 0; cc < 64; ++cc) {
                float we = We[d * 128 + h * 64 + cc];
                acc = fmaf(Wq[i * 128 + h * 64 + cc], we, acc);
                accb = fmaf(bq[h * 64 + cc], we, accb);
            }
            w = acc; b = accb;
        }
        __nv_bfloat16 hi = __float2bfloat16(w);
        __nv_bfloat16 lo = __float2bfloat16(w - __bfloat162float(hi));
        g_whT[c * 128 + i] = hi;
        g_wlT[c * 128 + i] = lo;
        if (i == 0) g_bias[c] = b;
    }
}

// ------------------------- kernel 2: HMMA node GEMM (64-row tiles, 2 CTA/SM) ---
#define A_ROWS 64
#define A_STRIDE 136
#define B_STRIDE 72
#define SZ_A (A_ROWS * A_STRIDE * 2)      // 17408
#define SZ_B (128 * B_STRIDE * 2)         // 18432
#define SM_A_HI 0
#define SM_A_LO (SZ_A)
#define SM_B    (2 * SZ_A)                // 2 buffers x (hi, lo)
#define SM_BIAS (2 * SZ_A + 4 * SZ_B)
#define SM_TOT  (SM_BIAS + WC * 4)        // 111616

__device__ __forceinline__ void load_B_async(uint32_t sb, int s, int tid) {
    const int chunk = s >> 1, kh = s & 1;
    const uint32_t bbase = SM_B + (uint32_t)(s & 1) * (2 * SZ_B);
    for (int i = tid; i < 128 * 8; i += 256) {
        int c = i >> 3, seg = i & 7;
        size_t gsrc = (size_t)(chunk * 128 + c) * 128 + kh * 64 + seg * 8;
        uint32_t doff = (uint32_t)(c * (B_STRIDE * 2) + seg * 16);
        cp16(sb + bbase + doff, g_whT + gsrc);
        cp16(sb + bbase + SZ_B + doff, g_wlT + gsrc);
    }
}

__global__ void __launch_bounds__(256, 2) k_gemm_mma(const float* __restrict__ x,
                                                     float* __restrict__ out) {
    extern __shared__ char smem[];
    const uint32_t sb = smem_u32(smem);
    const int tid = threadIdx.x, wid = tid >> 5, lane = tid & 31;
    const int row0 = blockIdx.x * A_ROWS;

    load_B_async(sb, 0, tid);
    CP_COMMIT();

    float* sbias = (float*)(smem + SM_BIAS);
    for (int i = tid; i < WC; i += 256) sbias[i] = g_bias[i];

    // load A tile [64x128], split bf16 hi/lo
    for (int i = tid; i < A_ROWS * 32; i += 256) {
        int r = i >> 5, k4 = (i & 31) << 2;
        int row = row0 + r;
        float4 v = (row < NN) ? __ldcs((const float4*)(x + (size_t)row * 128 + k4))
                              : make_float4(0.f, 0.f, 0.f, 0.f);
        __nv_bfloat16 h0 = __float2bfloat16(v.x), h1 = __float2bfloat16(v.y);
        __nv_bfloat16 h2 = __float2bfloat16(v.z), h3 = __float2bfloat16(v.w);
        __nv_bfloat16 l0 = __float2bfloat16(v.x - __bfloat162float(h0));
        __nv_bfloat16 l1 = __float2bfloat16(v.y - __bfloat162float(h1));
        __nv_bfloat16 l2 = __float2bfloat16(v.z - __bfloat162float(h2));
        __nv_bfloat16 l3 = __float2bfloat16(v.w - __bfloat162float(h3));
        __nv_bfloat162 ph0(h0, h1), ph1(h2, h3), pl0(l0, l1), pl1(l2, l3);
        uint32_t off = (uint32_t)(r * (A_STRIDE * 2) + k4 * 2);
        *(uint2*)(smem + SM_A_HI + off) = make_uint2(*(uint32_t*)&ph0, *(uint32_t*)&ph1);
        *(uint2*)(smem + SM_A_LO + off) = make_uint2(*(uint32_t*)&pl0, *(uint32_t*)&pl1);
    }

    const int wm = wid & 1, wn = wid >> 1;       // warp grid 2 x 4
    const int rw = wm * 32, cw = wn * 32;        // warp tile 32 x 32
    const uint32_t a_off = (uint32_t)((rw + (lane & 15)) * (A_STRIDE * 2) + (lane >> 4) * 16);
    const uint32_t b_off = (uint32_t)((cw + (lane & 15)) * (B_STRIDE * 2) + (lane >> 4) * 16);
    const int trow = lane >> 2;
    const int tcol = (lane & 3) * 2;

    float acc[2][4][4];

    for (int s = 0; s < 12; ++s) {
        const int chunk = s >> 1, kh = s & 1;
        if (kh == 0) {
            #pragma unroll
            for (int i = 0; i < 2; ++i)
                #pragma unroll
                for (int j = 0; j < 4; ++j)
                    #pragma unroll
                    for (int q = 0; q < 4; ++q) acc[i][j][q] = 0.0f;
        }
        if (s + 1 < 12) {
            load_B_async(sb, s + 1, tid);
            CP_COMMIT();
            CP_WAIT1();
        } else {
            CP_WAIT0();
        }
        __syncthreads();

        const uint32_t bbase = SM_B + (uint32_t)(s & 1) * (2 * SZ_B);
        #pragma unroll
        for (int term = 0; term < 3; ++term) {
            const uint32_t sA = sb + ((term == 2) ? SM_A_LO : SM_A_HI) + kh * 128;
            const uint32_t sB = sb + bbase + ((term == 1) ? SZ_B : 0);
            #pragma unroll
            for (int ks = 0; ks < 4; ++ks) {
                uint32_t a[2][4], b[2][4];
                #pragma unroll
                for (int i = 0; i < 2; ++i)
                    ldsm4(a[i], sA + a_off + i * (16 * A_STRIDE * 2) + ks * 32);
                #pragma unroll
                for (int j16 = 0; j16 < 2; ++j16)
                    ldsm4(b[j16], sB + b_off + j16 * (16 * B_STRIDE * 2) + ks * 32);
                #pragma unroll
                for (int i = 0; i < 2; ++i) {
                    mma16816(acc[i][0], a[i], b[0][0], b[0][2]);
                    mma16816(acc[i][1], a[i], b[0][1], b[0][3]);
                    mma16816(acc[i][2], a[i], b[1][0], b[1][2]);
                    mma16816(acc[i][3], a[i], b[1][1], b[1][3]);
                }
            }
        }
        __syncthreads();

        if (kh == 1) {
            if (chunk == 1 || chunk == 2) {
                // k/v chunks -> fp16 table, normal caching (L2-warm for k_edge)
                #pragma unroll
                for (int i = 0; i < 2; ++i) {
                    int r = row0 + rw + i * 16 + trow;
                    #pragma unroll
                    for (int j = 0; j < 4; ++j) {
                        int G = chunk * 128 + cw + j * 8 + tcol;
                        float b0 = sbias[G], b1 = sbias[G + 1];
                        if (r < NN) {
                            __half2 hv = __floats2half2_rn(acc[i][j][0] + b0,
                                                           acc[i][j][1] + b1);
                            *(__half2*)(g_src + (size_t)r * 256 + (G - 128)) = hv;
                        }
                        if (r + 8 < NN) {
                            __half2 hv = __floats2half2_rn(acc[i][j][2] + b0,
                                                           acc[i][j][3] + b1);
                            *(__half2*)(g_src + (size_t)(r + 8) * 256 + (G - 128)) = hv;
                        }
                    }
                }
            } else {
                float* bp; int stride, sub;
                switch (chunk) {
                    case 0:  bp = g_dst; stride = 320; sub = 0;   break;
                    case 3:  bp = out;   stride = 128; sub = 384; break;
                    default: bp = g_dst; stride = 320; sub = 384; break;
                }
                #pragma unroll
                for (int i = 0; i < 2; ++i) {
                    int r = row0 + rw + i * 16 + trow;
                    #pragma unroll
                    for (int j = 0; j < 4; ++j) {
                        int G = chunk * 128 + cw + j * 8 + tcol;
                        if (G >= 704) continue;
                        float b0 = sbias[G], b1 = sbias[G + 1];
                        if (r < NN) {
                            float2 v = make_float2(acc[i][j][0] + b0, acc[i][j][1] + b1);
                            __stcs((float2*)(bp + (size_t)r * stride + (G - sub)), v);
                        }
                        if (r + 8 < NN) {
                            float2 v = make_float2(acc[i][j][2] + b0, acc[i][j][3] + b1);
                            __stcs((float2*)(bp + (size_t)(r + 8) * stride + (G - sub)), v);
                        }
                    }
                }
            }
        }
    }
}

// ------------------------- sort: histogram, scan, permute -------------------------
__global__ void k_hist(const int* __restrict__ ei) {
    int i = blockIdx.x * blockDim.x + threadIdx.x;
    if (i < EE) atomicAdd(&g_cnt[__ldcs(ei + EE + i)], 1);
}

__global__ void k_scan_a() {
    __shared__ int sm[256];
    int t = threadIdx.x;
    int gid = blockIdx.x * 256 + t;
    int val = (gid < NN) ? g_cnt[gid] : 0;
    sm[t] = val;
    __syncthreads();
    #pragma unroll
    for (int o = 1; o < 256; o <<= 1) {
        int add = (t >= o) ? sm[t - o] : 0;
        __syncthreads();
        sm[t] += add;
        __syncthreads();
    }
    if (gid < NN) g_off[gid] = sm[t] - val;
    if (t == 255) g_bsum[blockIdx.x] = sm[255];
}

__global__ void k_scan_b(int nblk) {
    __shared__ int sm[512];
    int t = threadIdx.x;
    int val = (t < nblk) ? g_bsum[t] : 0;
    sm[t] = val;
    __syncthreads();
    #pragma unroll
    for (int o = 1; o < 512; o <<= 1) {
        int add = (t >= o) ? sm[t - o] : 0;
        __syncthreads();
        sm[t] += add;
        __syncthreads();
    }
    if (t < nblk) g_bsum[t] = sm[t] - val;
}

__global__ void k_scan_c() {
    int gid = blockIdx.x * 256 + threadIdx.x;
    if (gid < NN) g_off[gid] += g_bsum[blockIdx.x];
    if (gid == 0) g_off[NN] = EE;
}

__global__ void k_permute(const int* __restrict__ ei, const float* __restrict__ lu,
                          const float* __restrict__ tv) {
    int i = blockIdx.x * blockDim.x + threadIdx.x;
    if (i >= EE) return;
    int d = __ldcs(ei + EE + i);
    int s = __ldcs(ei + i);
    int pos = g_off[d] + atomicAdd(&g_cursor[d], 1);
    g_esrc[pos] = s;
    g_eidx[pos] = i;
    g_erel[pos] = lu[s] - __ldcs(tv + i);
}

// ------------------------- kernel 3: fused edge pass (warp per dst node) -------
// Direct softmax; fp16 k/v table (51MB, L2-resident); streaming hints on all
// zero-reuse data. No atomics.
__global__ void __launch_bounds__(256) k_edge(const float* __restrict__ msg,
                                              const float* __restrict__ time_w,
                                              const float* __restrict__ time_b,
                                              float* __restrict__ out) {
    int n = (blockIdx.x * blockDim.x + threadIdx.x) >> 5;
    int lane = threadIdx.x & 31;
    if (n >= NN) return;
    const int off0 = g_off[n];
    const int deg = g_off[n + 1] - off0;

    const float* dp = g_dst + (size_t)n * 320;
    const float4 q4 = __ldcs((const float4*)(dp + lane * 4));
    const float p00 = __ldcs(dp + 128 + lane), p01 = __ldcs(dp + 160 + lane);
    const float p02 = __ldcs(dp + 192 + lane), p10 = __ldcs(dp + 224 + lane);
    const float p11 = __ldcs(dp + 256 + lane), p12 = __ldcs(dp + 288 + lane);
    const float tww = time_w[lane], tbb = time_b[lane];
    const bool h0lane = (lane < 16);

    float den0 = 0.f, den1 = 0.f;
    float4 aco = make_float4(0.f, 0.f, 0.f, 0.f);
    float2 as0 = make_float2(0.f, 0.f), as1 = as0, as2 = as0;

    for (int eb = 0; eb < deg; eb += 4) {
        const int nb = deg - eb;
        int srcj[4], idxj[4];
        float relj[4], ea0[4], ea1[4], ea2[4], u0[4], u1[4];
        float4 k4[4], v4[4];
        #pragma unroll
        for (int j = 0; j < 4; ++j) {
            int pos = off0 + eb + ((j < nb) ? j : 0);
            srcj[j] = __ldcs(g_esrc + pos);
            idxj[j] = __ldcs(g_eidx + pos);
            relj[j] = __ldcs(g_erel + pos);
        }
        #pragma unroll
        for (int j = 0; j < 4; ++j) {
            const __half* sp = g_src + (size_t)srcj[j] * 256;
            uint2 kr = *(const uint2*)(sp + lane * 4);        // cached: reused ~8x
            uint2 vr = *(const uint2*)(sp + 128 + lane * 4);
            float2 ka = __half22float2(*(const __half2*)&kr.x);
            float2 kb = __half22float2(*(const __half2*)&kr.y);
            k4[j] = make_float4(ka.x, ka.y, kb.x, kb.y);
            float2 va = __half22float2(*(const __half2*)&vr.x);
            float2 vb = __half22float2(*(const __half2*)&vr.y);
            v4[j] = make_float4(va.x, va.y, vb.x, vb.y);
            ea1[j] = __ldcs(msg + (size_t)idxj[j] * 64 + lane);
            ea2[j] = __ldcs(msg + (size_t)idxj[j] * 64 + 32 + lane);
        }
        #pragma unroll
        for (int j = 0; j < 4; ++j) {
            float qk = q4.x * k4[j].x + q4.y * k4[j].y + q4.z * k4[j].z + q4.w * k4[j].w;
            ea0[j] = cosf(fmaf(relj[j], tww, tbb));
            u0[j] = ea0[j] * p00 + ea1[j] * p01 + ea2[j] * p02 + (h0lane ? qk : 0.f);
            u1[j] = ea0[j] * p10 + ea1[j] * p11 + ea2[j] * p12 + (h0lane ? 0.f : qk);
        }
        #pragma unroll
        for (int o = 16; o; o >>= 1) {
            #pragma unroll
            for (int j = 0; j < 4; ++j) {
                u0[j] += __shfl_xor_sync(0xffffffffu, u0[j], o);
                u1[j] += __shfl_xor_sync(0xffffffffu, u1[j], o);
            }
        }
        #pragma unroll
        for (int j = 0; j < 4; ++j) {
            if (j < nb) {
                float e0 = __expf(u0[j] * 0.125f);
                float e1 = __expf(u1[j] * 0.125f);
                den0 += e0; den1 += e1;
                float eh = h0lane ? e0 : e1;
                aco.x = fmaf(v4[j].x, eh, aco.x);
                aco.y = fmaf(v4[j].y, eh, aco.y);
                aco.z = fmaf(v4[j].z, eh, aco.z);
                aco.w = fmaf(v4[j].w, eh, aco.w);
                as0.x = fmaf(ea0[j], e0, as0.x);  as0.y = fmaf(ea0[j], e1, as0.y);
                as1.x = fmaf(ea1[j], e0, as1.x);  as1.y = fmaf(ea1[j], e1, as1.y);
                as2.x = fmaf(ea2[j], e0, as2.x);  as2.y = fmaf(ea2[j], e1, as2.y);
            }
        }
    }

    float2* sp2 = (float2*)(g_s + (size_t)n * 192);
    if (deg > 0) {
        float i0 = 1.0f / (den0 + 1e-16f);
        float i1 = 1.0f / (den1 + 1e-16f);
        float ih = h0lane ? i0 : i1;
        float4* op = (float4*)(out + (size_t)n * 128 + lane * 4);
        float4 o4 = __ldcs(op);
        o4.x += aco.x * ih; o4.y += aco.y * ih;
        o4.z += aco.z * ih; o4.w += aco.w * ih;
        __stcs(op, o4);
        __stcs(sp2 + lane,      make_float2(as0.x * i0, as0.y * i1));
        __stcs(sp2 + lane + 32, make_float2(as1.x * i0, as1.y * i1));
        __stcs(sp2 + lane + 64, make_float2(as2.x * i0, as2.y * i1));
    } else {
        float2 z = make_float2(0.f, 0.f);
        __stcs(sp2 + lane, z); __stcs(sp2 + lane + 32, z); __stcs(sp2 + lane + 64, z);
    }
}

// ------------------------- kernel 4: out += s @ We -------------------------
__global__ void k_final(const float* __restrict__ We, float* __restrict__ out) {
    extern __shared__ float sm[];
    float* sS = sm;              // [d][h][r]: 96*2*128
    float* sW = sm + 96 * 256;   // [d][c]:   96*128
    const int row0 = blockIdx.x * 128;
    const int t = threadIdx.x;

    for (int i = t; i < 96 * 32; i += 256) {
        int d = i >> 5, c4 = (i & 31) << 2;
        *(float4*)(sW + d * 128 + c4) = *(const float4*)(We + d * 128 + c4);
    }
    for (int i = t; i < 128 * 96; i += 256) {
        int r = i / 96, d = i % 96;
        int row = row0 + r;
        float2 v = (row < NN) ? __ldcs((const float2*)(g_s + (size_t)row * 192 + d * 2))
                              : make_float2(0.f, 0.f);
        sS[d * 256 + r] = v.x;
        sS[d * 256 + 128 + r] = v.y;
    }
    __syncthreads();

    const int tx = t & 15, ty = t >> 4;
    const int r0 = ty * 8, c0 = tx * 8;
    const int h = c0 >> 6;

    unsigned long long acc[4][8];
    #pragma unroll
    for (int i = 0; i < 4; ++i)
        #pragma unroll
        for (int j = 0; j < 8; ++j) acc[i][j] = 0ULL;

    #pragma unroll 4
    for (int d = 0; d < 96; ++d) {
        float4 a0 = *(float4*)(sS + d * 256 + h * 128 + r0);
        float4 a1 = *(float4*)(sS + d * 256 + h * 128 + r0 + 4);
        float4 b0 = *(float4*)(sW + d * 128 + c0);
        float4 b1 = *(float4*)(sW + d * 128 + c0 + 4);
        unsigned long long A[4] = {pk2(a0.x, a0.y), pk2(a0.z, a0.w),
                                   pk2(a1.x, a1.y), pk2(a1.z, a1.w)};
        float bs8[8] = {b0.x, b0.y, b0.z, b0.w, b1.x, b1.y, b1.z, b1.w};
        #pragma unroll
        for (int j = 0; j < 8; ++j) {
            unsigned long long B = pk2(bs8[j], bs8[j]);
            #pragma unroll
            for (int i = 0; i < 4; ++i) acc[i][j] = ffma2(A[i], B, acc[i][j]);
        }
    }

    #pragma unroll
    for (int j = 0; j < 8; ++j) {
        int col = c0 + j;
        #pragma unroll
        for (int i = 0; i < 4; ++i) {
            float2 v = upk2(acc[i][j]);
            int r = row0 + r0 + 2 * i;
            if (r < NN) {
                float* p = out + (size_t)r * 128 + col;
                __stcs(p, __ldcs(p) + v.x);
            }
            if (r + 1 < NN) {
                float* p = out + (size_t)(r + 1) * 128 + col;
                __stcs(p, __ldcs(p) + v.y);
            }
        }
    }
}

// ------------------------- launch -------------------------
extern "C" void kernel_launch(void* const* d_in, const int* in_sizes, int n_in,
                              void* d_out, int out_size) {
    const float* x   = (const float*)d_in[0];
    const float* lu  = (const float*)d_in[1];
    const float* tv  = (const float*)d_in[2];
    const float* msg = (const float*)d_in[3];
    const int*   ei  = (const int*)d_in[4];
    const float* tw  = (const float*)d_in[5];
    const float* tb  = (const float*)d_in[6];
    const float* Wq  = (const float*)d_in[7];
    const float* bq  = (const float*)d_in[8];
    const float* Wk  = (const float*)d_in[9];
    const float* bk  = (const float*)d_in[10];
    const float* Wv  = (const float*)d_in[11];
    const float* bv  = (const float*)d_in[12];
    const float* We  = (const float*)d_in[13];
    const float* Ws  = (const float*)d_in[14];
    const float* bs  = (const float*)d_in[15];
    float* out = (float*)d_out;

    static cudaStream_t s2 = nullptr;
    static cudaEvent_t evFork = nullptr, evJoin = nullptr;
    if (!s2) {
        cudaFuncSetAttribute(k_gemm_mma, cudaFuncAttributeMaxDynamicSharedMemorySize, SM_TOT);
        cudaFuncSetAttribute(k_final, cudaFuncAttributeMaxDynamicSharedMemorySize,
                             (96 * 256 + 96 * 128) * 4);
        cudaStreamCreateWithFlags(&s2, cudaStreamNonBlocking);
        cudaEventCreateWithFlags(&evFork, cudaEventDisableTiming);
        cudaEventCreateWithFlags(&evJoin, cudaEventDisableTiming);
    }

    const int nblk = (NN + 255) / 256;  // 391

    // Fork: sort chain on s2, concurrent with weight prep + node GEMM.
    cudaEventRecord(evFork, 0);
    cudaStreamWaitEvent(s2, evFork, 0);

    k_init<<<nblk, 256, 0, s2>>>();
    k_hist<<<(EE + 255) / 256, 256, 0, s2>>>(ei);
    k_scan_a<<<nblk, 256, 0, s2>>>();
    k_scan_b<<<1, 512, 0, s2>>>(nblk);
    k_scan_c<<<nblk, 256, 0, s2>>>();
    k_permute<<<(EE + 255) / 256, 256, 0, s2>>>(ei, lu, tv);
    cudaEventRecord(evJoin, s2);

    // Main stream: weights -> node GEMM (writes g_dst q/p, g_src k/v fp16, skip->out)
    k_prep<<<128, 256>>>(Wq, bq, Wk, bk, Wv, bv, We, Ws, bs);
    k_gemm_mma<<<(NN + A_ROWS - 1) / A_ROWS, 256, SM_TOT>>>(x, out);

    // Join, then fused edge pass + final GEMM.
    cudaStreamWaitEvent(0, evJoin, 0);
    k_edge<<<(NN * 32 + 255) / 256, 256>>>(msg, tw, tb, out);
    k_final<<<(NN + 127) / 128, 256, (96 * 256 + 96 * 128) * 4>>>(We, out);
}

// round 9
// speedup vs baseline: 2.3991x; 1.0431x over previous
#include <cuda_runtime.h>
#include <cuda_fp16.h>
#include <math_constants.h>
#include <cstdint>

// Problem constants (fixed shapes)
#define NN 100000
#define EE 800000
#define WC 768   // fused weight cols: [q 128][k 128][v 128][skip 128][p0 96][p1 96][pad 64]

// ------------------------- device scratch -------------------------
__device__ __half g_dst[(size_t)NN * 320];           // per-node dst data: q[128], p[192] fp16
__device__ __half g_src[(size_t)NN * 256];           // per-node src data: k[128], v[128] fp16
__device__ __half g_whT[WC * 128];                   // W^T hi (fp16), [col][k]
__device__ __half g_wlT[WC * 128];                   // W^T lo (fp16, subnormal ok)
__device__ float g_bias[WC];
__device__ __half g_s[(size_t)NN * 192];             // s[n][d][h] fp16
// sort scratch (SoA sorted edge data)
__device__ int g_cnt[NN];
__device__ int g_off[NN + 1];
__device__ int g_cursor[NN];
__device__ int g_esrc[EE];
__device__ int g_eidx[EE];
__device__ float g_erel[EE];
__device__ int g_bsum[512];

// ------------------------- generic helpers -------------------------
__device__ __forceinline__ unsigned long long pk2(float lo, float hi) {
    unsigned long long r;
    asm("mov.b64 %0, {%1,%2};" : "=l"(r) : "f"(lo), "f"(hi));
    return r;
}
__device__ __forceinline__ float2 upk2(unsigned long long v) {
    float2 r;
    asm("mov.b64 {%0,%1}, %2;" : "=f"(r.x), "=f"(r.y) : "l"(v));
    return r;
}
__device__ __forceinline__ unsigned long long ffma2(unsigned long long a, unsigned long long b,
                                                    unsigned long long c) {
    unsigned long long d;
    asm("fma.rn.f32x2 %0, %1, %2, %3;" : "=l"(d) : "l"(a), "l"(b), "l"(c));
    return d;
}
__device__ __forceinline__ uint32_t smem_u32(const void* p) {
    uint32_t a;
    asm("{ .reg .u64 t; cvta.to.shared.u64 t, %1; cvt.u32.u64 %0, t; }" : "=r"(a) : "l"(p));
    return a;
}
__device__ __forceinline__ void ldsm4(uint32_t* r, uint32_t addr) {
    asm volatile("ldmatrix.sync.aligned.m8n8.x4.shared.b16 {%0,%1,%2,%3}, [%4];"
                 : "=r"(r[0]), "=r"(r[1]), "=r"(r[2]), "=r"(r[3]) : "r"(addr));
}
__device__ __forceinline__ void mma16816(float* c, const uint32_t* a, uint32_t b0, uint32_t b1) {
    asm volatile(
        "mma.sync.aligned.m16n8k16.row.col.f32.f16.f16.f32 "
        "{%0,%1,%2,%3}, {%4,%5,%6,%7}, {%8,%9}, {%0,%1,%2,%3};"
        : "+f"(c[0]), "+f"(c[1]), "+f"(c[2]), "+f"(c[3])
        : "r"(a[0]), "r"(a[1]), "r"(a[2]), "r"(a[3]), "r"(b0), "r"(b1));
}
__device__ __forceinline__ void cp16(uint32_t saddr, const void* g) {
    asm volatile("cp.async.cg.shared.global [%0], [%1], 16;" :: "r"(saddr), "l"(g));
}
#define CP_COMMIT() asm volatile("cp.async.commit_group;" ::: "memory")
#define CP_WAIT1()  asm volatile("cp.async.wait_group 1;" ::: "memory")
#define CP_WAIT0()  asm volatile("cp.async.wait_group 0;" ::: "memory")

// ------------------------- kernel 0: init sort scratch -------------------------
__global__ void k_init() {
    int i = blockIdx.x * blockDim.x + threadIdx.x;
    if (i < NN) {
        g_cnt[i] = 0;
        g_cursor[i] = 0;
    }
}

// ------------------------- kernel 1: fused weights (transposed, fp16 hi/lo) ----
__global__ void k_prep(const float* __restrict__ Wq, const float* __restrict__ bq,
                       const float* __restrict__ Wk, const float* __restrict__ bk,
                       const float* __restrict__ Wv, const float* __restrict__ bv,
                       const float* __restrict__ We,
                       const float* __restrict__ Ws, const float* __restrict__ bs) {
    int i = blockIdx.x;  // 0..127 (input dim k)
    for (int c = threadIdx.x; c < WC; c += blockDim.x) {
        float w = 0.0f, b = 0.0f;
        if (c < 128)      { w = Wq[i * 128 + c];         b = bq[c]; }
        else if (c < 256) { w = Wk[i * 128 + (c - 128)]; b = bk[c - 128]; }
        else if (c < 384) { w = Wv[i * 128 + (c - 256)]; b = bv[c - 256]; }
        else if (c < 512) { w = Ws[i * 128 + (c - 384)]; b = bs[c - 384]; }
        else if (c < 704) {
            int hd = c - 512;
            int h = hd / 96, d = hd % 96;
            float acc = 0.0f, accb = 0.0f;
            #pragma unroll 8
            for (int cc = 0; cc < 64; ++cc) {
                float we = We[d * 128 + h * 64 + cc];
                acc = fmaf(Wq[i * 128 + h * 64 + cc], we, acc);
                accb = fmaf(bq[h * 64 + cc], we, accb);
            }
            w = acc; b = accb;
        }
        __half hi = __float2half_rn(w);
        __half lo = __float2half_rn(w - __half2float(hi));
        g_whT[c * 128 + i] = hi;
        g_wlT[c * 128 + i] = lo;
        if (i == 0) g_bias[c] = b;
    }
}

// ------------------------- kernel 2: HMMA node GEMM (fp16 2-term) -------------
#define A_ROWS 64
#define A_STRIDE 136
#define B_STRIDE 72
#define SZ_A (A_ROWS * A_STRIDE * 2)      // 17408 (single fp16 A)
#define SZ_B (128 * B_STRIDE * 2)         // 18432 per term per half
#define SM_A    0
#define SM_B    (SZ_A)                    // 2 buffers x (hi, lo)
#define SM_BIAS (SZ_A + 4 * SZ_B)         // 91136
#define SM_TOT  (SM_BIAS + WC * 4)        // 94208

__device__ __forceinline__ void load_B_async(uint32_t sb, int s, int tid) {
    const int chunk = s >> 1, kh = s & 1;
    const uint32_t bbase = SM_B + (uint32_t)(s & 1) * (2 * SZ_B);
    for (int i = tid; i < 128 * 8; i += 256) {
        int c = i >> 3, seg = i & 7;
        size_t gsrc = (size_t)(chunk * 128 + c) * 128 + kh * 64 + seg * 8;
        uint32_t doff = (uint32_t)(c * (B_STRIDE * 2) + seg * 16);
        cp16(sb + bbase + doff, g_whT + gsrc);
        cp16(sb + bbase + SZ_B + doff, g_wlT + gsrc);
    }
}

__global__ void __launch_bounds__(256, 2) k_gemm_mma(const float* __restrict__ x,
                                                     float* __restrict__ out) {
    extern __shared__ char smem[];
    const uint32_t sb = smem_u32(smem);
    const int tid = threadIdx.x, wid = tid >> 5, lane = tid & 31;
    const int row0 = blockIdx.x * A_ROWS;

    load_B_async(sb, 0, tid);
    CP_COMMIT();

    float* sbias = (float*)(smem + SM_BIAS);
    for (int i = tid; i < WC; i += 256) sbias[i] = g_bias[i];

    // load A tile [64x128] as single fp16
    for (int i = tid; i < A_ROWS * 32; i += 256) {
        int r = i >> 5, k4 = (i & 31) << 2;
        int row = row0 + r;
        float4 v = (row < NN) ? __ldcs((const float4*)(x + (size_t)row * 128 + k4))
                              : make_float4(0.f, 0.f, 0.f, 0.f);
        __half2 h01 = __floats2half2_rn(v.x, v.y);
        __half2 h23 = __floats2half2_rn(v.z, v.w);
        uint32_t off = (uint32_t)(r * (A_STRIDE * 2) + k4 * 2);
        *(uint2*)(smem + SM_A + off) = make_uint2(*(uint32_t*)&h01, *(uint32_t*)&h23);
    }

    const int wm = wid & 1, wn = wid >> 1;       // warp grid 2 x 4
    const int rw = wm * 32, cw = wn * 32;        // warp tile 32 x 32
    const uint32_t a_off = (uint32_t)((rw + (lane & 15)) * (A_STRIDE * 2) + (lane >> 4) * 16);
    const uint32_t b_off = (uint32_t)((cw + (lane & 15)) * (B_STRIDE * 2) + (lane >> 4) * 16);
    const int trow = lane >> 2;
    const int tcol = (lane & 3) * 2;

    float acc[2][4][4];

    for (int s = 0; s < 12; ++s) {
        const int chunk = s >> 1, kh = s & 1;
        if (kh == 0) {
            #pragma unroll
            for (int i = 0; i < 2; ++i)
                #pragma unroll
                for (int j = 0; j < 4; ++j)
                    #pragma unroll
                    for (int q = 0; q < 4; ++q) acc[i][j][q] = 0.0f;
        }
        if (s + 1 < 12) {
            load_B_async(sb, s + 1, tid);
            CP_COMMIT();
            CP_WAIT1();
        } else {
            CP_WAIT0();
        }
        __syncthreads();

        const uint32_t sA = sb + SM_A + kh * 128;
        const uint32_t sBh = sb + SM_B + (uint32_t)(s & 1) * (2 * SZ_B);
        const uint32_t sBl = sBh + SZ_B;
        #pragma unroll
        for (int ks = 0; ks < 4; ++ks) {
            uint32_t a[2][4], bh[2][4], bl[2][4];
            #pragma unroll
            for (int i = 0; i < 2; ++i)
                ldsm4(a[i], sA + a_off + i * (16 * A_STRIDE * 2) + ks * 32);
            #pragma unroll
            for (int j16 = 0; j16 < 2; ++j16) {
                ldsm4(bh[j16], sBh + b_off + j16 * (16 * B_STRIDE * 2) + ks * 32);
                ldsm4(bl[j16], sBl + b_off + j16 * (16 * B_STRIDE * 2) + ks * 32);
            }
            #pragma unroll
            for (int i = 0; i < 2; ++i) {
                mma16816(acc[i][0], a[i], bh[0][0], bh[0][2]);
                mma16816(acc[i][1], a[i], bh[0][1], bh[0][3]);
                mma16816(acc[i][2], a[i], bh[1][0], bh[1][2]);
                mma16816(acc[i][3], a[i], bh[1][1], bh[1][3]);
                mma16816(acc[i][0], a[i], bl[0][0], bl[0][2]);
                mma16816(acc[i][1], a[i], bl[0][1], bl[0][3]);
                mma16816(acc[i][2], a[i], bl[1][0], bl[1][2]);
                mma16816(acc[i][3], a[i], bl[1][1], bl[1][3]);
            }
        }
        __syncthreads();

        if (kh == 1) {
            if (chunk == 3) {
                // skip -> out (fp32)
                #pragma unroll
                for (int i = 0; i < 2; ++i) {
                    int r = row0 + rw + i * 16 + trow;
                    #pragma unroll
                    for (int j = 0; j < 4; ++j) {
                        int G = 384 + cw + j * 8 + tcol;
                        float b0 = sbias[G], b1 = sbias[G + 1];
                        if (r < NN) {
                            float2 v = make_float2(acc[i][j][0] + b0, acc[i][j][1] + b1);
                            __stcs((float2*)(out + (size_t)r * 128 + (G - 384)), v);
                        }
                        if (r + 8 < NN) {
                            float2 v = make_float2(acc[i][j][2] + b0, acc[i][j][3] + b1);
                            __stcs((float2*)(out + (size_t)(r + 8) * 128 + (G - 384)), v);
                        }
                    }
                }
            } else {
                // q/p -> g_dst fp16, k/v -> g_src fp16
                __half* bp; int stride, sub;
                bool is_kv = (chunk == 1 || chunk == 2);
                if (chunk == 0)      { bp = g_dst; stride = 320; sub = 0;   }
                else if (is_kv)      { bp = g_src; stride = 256; sub = 128; }
                else                 { bp = g_dst; stride = 320; sub = 384; }
                #pragma unroll
                for (int i = 0; i < 2; ++i) {
                    int r = row0 + rw + i * 16 + trow;
                    #pragma unroll
                    for (int j = 0; j < 4; ++j) {
                        int G = chunk * 128 + cw + j * 8 + tcol;
                        if (G >= 704) continue;
                        float b0 = sbias[G], b1 = sbias[G + 1];
                        if (r < NN) {
                            __half2 hv = __floats2half2_rn(acc[i][j][0] + b0,
                                                           acc[i][j][1] + b1);
                            *(__half2*)(bp + (size_t)r * stride + (G - sub)) = hv;
                        }
                        if (r + 8 < NN) {
                            __half2 hv = __floats2half2_rn(acc[i][j][2] + b0,
                                                           acc[i][j][3] + b1);
                            *(__half2*)(bp + (size_t)(r + 8) * stride + (G - sub)) = hv;
                        }
                    }
                }
            }
        }
    }
}

// ------------------------- sort: histogram, scan, permute -------------------------
__global__ void k_hist(const int* __restrict__ ei) {
    int i = blockIdx.x * blockDim.x + threadIdx.x;
    if (i < EE) atomicAdd(&g_cnt[__ldcs(ei + EE + i)], 1);
}

__global__ void k_scan_a() {
    __shared__ int sm[256];
    int t = threadIdx.x;
    int gid = blockIdx.x * 256 + t;
    int val = (gid < NN) ? g_cnt[gid] : 0;
    sm[t] = val;
    __syncthreads();
    #pragma unroll
    for (int o = 1; o < 256; o <<= 1) {
        int add = (t >= o) ? sm[t - o] : 0;
        __syncthreads();
        sm[t] += add;
        __syncthreads();
    }
    if (gid < NN) g_off[gid] = sm[t] - val;
    if (t == 255) g_bsum[blockIdx.x] = sm[255];
}

__global__ void k_scan_b(int nblk) {
    __shared__ int sm[512];
    int t = threadIdx.x;
    int val = (t < nblk) ? g_bsum[t] : 0;
    sm[t] = val;
    __syncthreads();
    #pragma unroll
    for (int o = 1; o < 512; o <<= 1) {
        int add = (t >= o) ? sm[t - o] : 0;
        __syncthreads();
        sm[t] += add;
        __syncthreads();
    }
    if (t < nblk) g_bsum[t] = sm[t] - val;
}

__global__ void k_scan_c() {
    int gid = blockIdx.x * 256 + threadIdx.x;
    if (gid < NN) g_off[gid] += g_bsum[blockIdx.x];
    if (gid == 0) g_off[NN] = EE;
}

__global__ void k_permute(const int* __restrict__ ei, const float* __restrict__ lu,
                          const float* __restrict__ tv) {
    int i = blockIdx.x * blockDim.x + threadIdx.x;
    if (i >= EE) return;
    int d = __ldcs(ei + EE + i);
    int s = __ldcs(ei + i);
    int pos = g_off[d] + atomicAdd(&g_cursor[d], 1);
    g_esrc[pos] = s;
    g_eidx[pos] = i;
    g_erel[pos] = lu[s] - __ldcs(tv + i);
}

// ------------------------- kernel 3: fused edge pass (warp per dst node) -------
__global__ void __launch_bounds__(256) k_edge(const float* __restrict__ msg,
                                              const float* __restrict__ time_w,
                                              const float* __restrict__ time_b,
                                              float* __restrict__ out) {
    int n = (blockIdx.x * blockDim.x + threadIdx.x) >> 5;
    int lane = threadIdx.x & 31;
    if (n >= NN) return;
    const int off0 = g_off[n];
    const int deg = g_off[n + 1] - off0;

    const __half* dp = g_dst + (size_t)n * 320;
    int2 qr = __ldcs((const int2*)(dp + lane * 4));
    float2 qa = __half22float2(*(const __half2*)&qr.x);
    float2 qb = __half22float2(*(const __half2*)&qr.y);
    const float4 q4 = make_float4(qa.x, qa.y, qb.x, qb.y);
    short ps0 = __ldcs((const short*)(dp + 128 + lane));
    short ps1 = __ldcs((const short*)(dp + 160 + lane));
    short ps2 = __ldcs((const short*)(dp + 192 + lane));
    short ps3 = __ldcs((const short*)(dp + 224 + lane));
    short ps4 = __ldcs((const short*)(dp + 256 + lane));
    short ps5 = __ldcs((const short*)(dp + 288 + lane));
    const float p00 = __half2float(*(__half*)&ps0), p01 = __half2float(*(__half*)&ps1);
    const float p02 = __half2float(*(__half*)&ps2), p10 = __half2float(*(__half*)&ps3);
    const float p11 = __half2float(*(__half*)&ps4), p12 = __half2float(*(__half*)&ps5);
    const float tww = time_w[lane], tbb = time_b[lane];
    const bool h0lane = (lane < 16);

    float den0 = 0.f, den1 = 0.f;
    float4 aco = make_float4(0.f, 0.f, 0.f, 0.f);
    float2 as0 = make_float2(0.f, 0.f), as1 = as0, as2 = as0;

    for (int eb = 0; eb < deg; eb += 4) {
        const int nb = deg - eb;
        int srcj[4], idxj[4];
        float relj[4], ea0[4], ea1[4], ea2[4], u0[4], u1[4];
        float4 k4[4], v4[4];
        #pragma unroll
        for (int j = 0; j < 4; ++j) {
            int pos = off0 + eb + ((j < nb) ? j : 0);
            srcj[j] = __ldcs(g_esrc + pos);
            idxj[j] = __ldcs(g_eidx + pos);
            relj[j] = __ldcs(g_erel + pos);
        }
        #pragma unroll
        for (int j = 0; j < 4; ++j) {
            const __half* sp = g_src + (size_t)srcj[j] * 256;
            uint2 kr = *(const uint2*)(sp + lane * 4);        // cached: reused ~8x
            uint2 vr = *(const uint2*)(sp + 128 + lane * 4);
            float2 ka = __half22float2(*(const __half2*)&kr.x);
            float2 kb = __half22float2(*(const __half2*)&kr.y);
            k4[j] = make_float4(ka.x, ka.y, kb.x, kb.y);
            float2 va = __half22float2(*(const __half2*)&vr.x);
            float2 vb = __half22float2(*(const __half2*)&vr.y);
            v4[j] = make_float4(va.x, va.y, vb.x, vb.y);
            ea1[j] = __ldcs(msg + (size_t)idxj[j] * 64 + lane);
            ea2[j] = __ldcs(msg + (size_t)idxj[j] * 64 + 32 + lane);
        }
        #pragma unroll
        for (int j = 0; j < 4; ++j) {
            float qk = q4.x * k4[j].x + q4.y * k4[j].y + q4.z * k4[j].z + q4.w * k4[j].w;
            ea0[j] = cosf(fmaf(relj[j], tww, tbb));
            u0[j] = ea0[j] * p00 + ea1[j] * p01 + ea2[j] * p02 + (h0lane ? qk : 0.f);
            u1[j] = ea0[j] * p10 + ea1[j] * p11 + ea2[j] * p12 + (h0lane ? 0.f : qk);
        }
        #pragma unroll
        for (int o = 16; o; o >>= 1) {
            #pragma unroll
            for (int j = 0; j < 4; ++j) {
                u0[j] += __shfl_xor_sync(0xffffffffu, u0[j], o);
                u1[j] += __shfl_xor_sync(0xffffffffu, u1[j], o);
            }
        }
        #pragma unroll
        for (int j = 0; j < 4; ++j) {
            if (j < nb) {
                float e0 = __expf(u0[j] * 0.125f);
                float e1 = __expf(u1[j] * 0.125f);
                den0 += e0; den1 += e1;
                float eh = h0lane ? e0 : e1;
                aco.x = fmaf(v4[j].x, eh, aco.x);
                aco.y = fmaf(v4[j].y, eh, aco.y);
                aco.z = fmaf(v4[j].z, eh, aco.z);
                aco.w = fmaf(v4[j].w, eh, aco.w);
                as0.x = fmaf(ea0[j], e0, as0.x);  as0.y = fmaf(ea0[j], e1, as0.y);
                as1.x = fmaf(ea1[j], e0, as1.x);  as1.y = fmaf(ea1[j], e1, as1.y);
                as2.x = fmaf(ea2[j], e0, as2.x);  as2.y = fmaf(ea2[j], e1, as2.y);
            }
        }
    }

    __half* sp2 = g_s + (size_t)n * 192;
    if (deg > 0) {
        float i0 = 1.0f / (den0 + 1e-16f);
        float i1 = 1.0f / (den1 + 1e-16f);
        float ih = h0lane ? i0 : i1;
        float4* op = (float4*)(out + (size_t)n * 128 + lane * 4);
        float4 o4 = __ldcs(op);
        o4.x += aco.x * ih; o4.y += aco.y * ih;
        o4.z += aco.z * ih; o4.w += aco.w * ih;
        __stcs(op, o4);
        __half2 h0 = __floats2half2_rn(as0.x * i0, as0.y * i1);
        __half2 h1 = __floats2half2_rn(as1.x * i0, as1.y * i1);
        __half2 h2 = __floats2half2_rn(as2.x * i0, as2.y * i1);
        __stcs((unsigned*)(sp2 + lane * 2),        *(unsigned*)&h0);
        __stcs((unsigned*)(sp2 + (lane + 32) * 2), *(unsigned*)&h1);
        __stcs((unsigned*)(sp2 + (lane + 64) * 2), *(unsigned*)&h2);
    } else {
        __stcs((unsigned*)(sp2 + lane * 2), 0u);
        __stcs((unsigned*)(sp2 + (lane + 32) * 2), 0u);
        __stcs((unsigned*)(sp2 + (lane + 64) * 2), 0u);
    }
}

// ------------------------- kernel 4: out += s @ We -------------------------
__global__ void k_final(const float* __restrict__ We, float* __restrict__ out) {
    extern __shared__ float sm[];
    float* sS = sm;              // [d][h][r]: 96*2*128
    float* sW = sm + 96 * 256;   // [d][c]:   96*128
    const int row0 = blockIdx.x * 128;
    const int t = threadIdx.x;

    for (int i = t; i < 96 * 32; i += 256) {
        int d = i >> 5, c4 = (i & 31) << 2;
        *(float4*)(sW + d * 128 + c4) = *(const float4*)(We + d * 128 + c4);
    }
    for (int i = t; i < 128 * 96; i += 256) {
        int r = i / 96, d = i % 96;
        int row = row0 + r;
        float2 v;
        if (row < NN) {
            unsigned bits = __ldcs((const unsigned*)(g_s + (size_t)row * 192 + d * 2));
            v = __half22float2(*(const __half2*)&bits);
        } else {
            v = make_float2(0.f, 0.f);
        }
        sS[d * 256 + r] = v.x;
        sS[d * 256 + 128 + r] = v.y;
    }
    __syncthreads();

    const int tx = t & 15, ty = t >> 4;
    const int r0 = ty * 8, c0 = tx * 8;
    const int h = c0 >> 6;

    unsigned long long acc[4][8];
    #pragma unroll
    for (int i = 0; i < 4; ++i)
        #pragma unroll
        for (int j = 0; j < 8; ++j) acc[i][j] = 0ULL;

    #pragma unroll 4
    for (int d = 0; d < 96; ++d) {
        float4 a0 = *(float4*)(sS + d * 256 + h * 128 + r0);
        float4 a1 = *(float4*)(sS + d * 256 + h * 128 + r0 + 4);
        float4 b0 = *(float4*)(sW + d * 128 + c0);
        float4 b1 = *(float4*)(sW + d * 128 + c0 + 4);
        unsigned long long A[4] = {pk2(a0.x, a0.y), pk2(a0.z, a0.w),
                                   pk2(a1.x, a1.y), pk2(a1.z, a1.w)};
        float bs8[8] = {b0.x, b0.y, b0.z, b0.w, b1.x, b1.y, b1.z, b1.w};
        #pragma unroll
        for (int j = 0; j < 8; ++j) {
            unsigned long long B = pk2(bs8[j], bs8[j]);
            #pragma unroll
            for (int i = 0; i < 4; ++i) acc[i][j] = ffma2(A[i], B, acc[i][j]);
        }
    }

    #pragma unroll
    for (int j = 0; j < 8; ++j) {
        int col = c0 + j;
        #pragma unroll
        for (int i = 0; i < 4; ++i) {
            float2 v = upk2(acc[i][j]);
            int r = row0 + r0 + 2 * i;
            if (r < NN) {
                float* p = out + (size_t)r * 128 + col;
                __stcs(p, __ldcs(p) + v.x);
            }
            if (r + 1 < NN) {
                float* p = out + (size_t)(r + 1) * 128 + col;
                __stcs(p, __ldcs(p) + v.y);
            }
        }
    }
}

// ------------------------- launch -------------------------
extern "C" void kernel_launch(void* const* d_in, const int* in_sizes, int n_in,
                              void* d_out, int out_size) {
    const float* x   = (const float*)d_in[0];
    const float* lu  = (const float*)d_in[1];
    const float* tv  = (const float*)d_in[2];
    const float* msg = (const float*)d_in[3];
    const int*   ei  = (const int*)d_in[4];
    const float* tw  = (const float*)d_in[5];
    const float* tb  = (const float*)d_in[6];
    const float* Wq  = (const float*)d_in[7];
    const float* bq  = (const float*)d_in[8];
    const float* Wk  = (const float*)d_in[9];
    const float* bk  = (const float*)d_in[10];
    const float* Wv  = (const float*)d_in[11];
    const float* bv  = (const float*)d_in[12];
    const float* We  = (const float*)d_in[13];
    const float* Ws  = (const float*)d_in[14];
    const float* bs  = (const float*)d_in[15];
    float* out = (float*)d_out;

    static cudaStream_t s2 = nullptr;
    static cudaEvent_t evFork = nullptr, evJoin = nullptr;
    if (!s2) {
        cudaFuncSetAttribute(k_gemm_mma, cudaFuncAttributeMaxDynamicSharedMemorySize, SM_TOT);
        cudaFuncSetAttribute(k_final, cudaFuncAttributeMaxDynamicSharedMemorySize,
                             (96 * 256 + 96 * 128) * 4);
        cudaStreamCreateWithFlags(&s2, cudaStreamNonBlocking);
        cudaEventCreateWithFlags(&evFork, cudaEventDisableTiming);
        cudaEventCreateWithFlags(&evJoin, cudaEventDisableTiming);
    }

    const int nblk = (NN + 255) / 256;  // 391

    // Fork: sort chain on s2, concurrent with weight prep + node GEMM.
    cudaEventRecord(evFork, 0);
    cudaStreamWaitEvent(s2, evFork, 0);

    k_init<<<nblk, 256, 0, s2>>>();
    k_hist<<<(EE + 255) / 256, 256, 0, s2>>>(ei);
    k_scan_a<<<nblk, 256, 0, s2>>>();
    k_scan_b<<<1, 512, 0, s2>>>(nblk);
    k_scan_c<<<nblk, 256, 0, s2>>>();
    k_permute<<<(EE + 255) / 256, 256, 0, s2>>>(ei, lu, tv);
    cudaEventRecord(evJoin, s2);

    // Main stream: weights -> node GEMM (writes g_dst q/p fp16, g_src k/v fp16, skip->out)
    k_prep<<<128, 256>>>(Wq, bq, Wk, bk, Wv, bv, We, Ws, bs);
    k_gemm_mma<<<(NN + A_ROWS - 1) / A_ROWS, 256, SM_TOT>>>(x, out);

    // Join, then fused edge pass + final GEMM.
    cudaStreamWaitEvent(0, evJoin, 0);
    k_edge<<<(NN * 32 + 255) / 256, 256>>>(msg, tw, tb, out);
    k_final<<<(NN + 127) / 128, 256, (96 * 256 + 96 * 128) * 4>>>(We, out);
}

// round 10
// speedup vs baseline: 3.2456x; 1.3529x over previous
#include <cuda_runtime.h>
#include <cuda_fp16.h>
#include <math_constants.h>
#include <cstdint>

// Problem constants (fixed shapes)
#define NN 100000
#define EE 800000
#define WC 768   // fused weight cols: [q 128][k 128][v 128][skip 128][p0 96][p1 96][pad 64]

// ------------------------- device scratch -------------------------
__device__ __half g_dst[(size_t)NN * 320];           // per-node dst data: q[128], p[192] fp16
__device__ __half g_src[(size_t)NN * 256];           // per-node src data: k[128], v[128] fp16
__device__ __half g_whT[WC * 128];                   // W^T hi (fp16), [col][k]
__device__ __half g_wlT[WC * 128];                   // W^T lo (fp16, subnormal ok)
__device__ float g_bias[WC];
// sort scratch (SoA sorted edge data)
__device__ int g_cnt[NN];
__device__ int g_off[NN + 1];
__device__ int g_cursor[NN];
__device__ int g_esrc[EE];
__device__ int g_eidx[EE];
__device__ float g_erel[EE];
__device__ int g_bsum[512];

// ------------------------- generic helpers -------------------------
__device__ __forceinline__ unsigned long long pk2(float lo, float hi) {
    unsigned long long r;
    asm("mov.b64 %0, {%1,%2};" : "=l"(r) : "f"(lo), "f"(hi));
    return r;
}
__device__ __forceinline__ float2 upk2(unsigned long long v) {
    float2 r;
    asm("mov.b64 {%0,%1}, %2;" : "=f"(r.x), "=f"(r.y) : "l"(v));
    return r;
}
__device__ __forceinline__ unsigned long long ffma2(unsigned long long a, unsigned long long b,
                                                    unsigned long long c) {
    unsigned long long d;
    asm("fma.rn.f32x2 %0, %1, %2, %3;" : "=l"(d) : "l"(a), "l"(b), "l"(c));
    return d;
}
__device__ __forceinline__ uint32_t smem_u32(const void* p) {
    uint32_t a;
    asm("{ .reg .u64 t; cvta.to.shared.u64 t, %1; cvt.u32.u64 %0, t; }" : "=r"(a) : "l"(p));
    return a;
}
__device__ __forceinline__ void ldsm4(uint32_t* r, uint32_t addr) {
    asm volatile("ldmatrix.sync.aligned.m8n8.x4.shared.b16 {%0,%1,%2,%3}, [%4];"
                 : "=r"(r[0]), "=r"(r[1]), "=r"(r[2]), "=r"(r[3]) : "r"(addr));
}
__device__ __forceinline__ void mma16816(float* c, const uint32_t* a, uint32_t b0, uint32_t b1) {
    asm volatile(
        "mma.sync.aligned.m16n8k16.row.col.f32.f16.f16.f32 "
        "{%0,%1,%2,%3}, {%4,%5,%6,%7}, {%8,%9}, {%0,%1,%2,%3};"
        : "+f"(c[0]), "+f"(c[1]), "+f"(c[2]), "+f"(c[3])
        : "r"(a[0]), "r"(a[1]), "r"(a[2]), "r"(a[3]), "r"(b0), "r"(b1));
}
__device__ __forceinline__ void cp16(uint32_t saddr, const void* g) {
    asm volatile("cp.async.cg.shared.global [%0], [%1], 16;" :: "r"(saddr), "l"(g));
}
#define CP_COMMIT() asm volatile("cp.async.commit_group;" ::: "memory")
#define CP_WAIT1()  asm volatile("cp.async.wait_group 1;" ::: "memory")
#define CP_WAIT0()  asm volatile("cp.async.wait_group 0;" ::: "memory")

// ------------------------- kernel: init sort scratch -------------------------
__global__ void k_init() {
    int i = blockIdx.x * blockDim.x + threadIdx.x;
    if (i < NN) {
        g_cnt[i] = 0;
        g_cursor[i] = 0;
    }
}

// ------------------------- kernel: fused weights (transposed, fp16 hi/lo) ----
__global__ void k_prep(const float* __restrict__ Wq, const float* __restrict__ bq,
                       const float* __restrict__ Wk, const float* __restrict__ bk,
                       const float* __restrict__ Wv, const float* __restrict__ bv,
                       const float* __restrict__ We,
                       const float* __restrict__ Ws, const float* __restrict__ bs) {
    int i = blockIdx.x;  // 0..127 (input dim k)
    for (int c = threadIdx.x; c < WC; c += blockDim.x) {
        float w = 0.0f, b = 0.0f;
        if (c < 128)      { w = Wq[i * 128 + c];         b = bq[c]; }
        else if (c < 256) { w = Wk[i * 128 + (c - 128)]; b = bk[c - 128]; }
        else if (c < 384) { w = Wv[i * 128 + (c - 256)]; b = bv[c - 256]; }
        else if (c < 512) { w = Ws[i * 128 + (c - 384)]; b = bs[c - 384]; }
        else if (c < 704) {
            int hd = c - 512;
            int h = hd / 96, d = hd % 96;
            float acc = 0.0f, accb = 0.0f;
            #pragma unroll 8
            for (int cc = 0; cc < 64; ++cc) {
                float we = We[d * 128 + h * 64 + cc];
                acc = fmaf(Wq[i * 128 + h * 64 + cc], we, acc);
                accb = fmaf(bq[h * 64 + cc], we, accb);
            }
            w = acc; b = accb;
        }
        __half hi = __float2half_rn(w);
        __half lo = __float2half_rn(w - __half2float(hi));
        g_whT[c * 128 + i] = hi;
        g_wlT[c * 128 + i] = lo;
        if (i == 0) g_bias[c] = b;
    }
}

// ------------------------- kernel: HMMA node GEMM (fp16 2-term) -------------
#define A_ROWS 64
#define A_STRIDE 136
#define B_STRIDE 72
#define SZ_A (A_ROWS * A_STRIDE * 2)      // 17408 (single fp16 A)
#define SZ_B (128 * B_STRIDE * 2)         // 18432 per term per half
#define SM_A    0
#define SM_B    (SZ_A)                    // 2 buffers x (hi, lo)
#define SM_BIAS (SZ_A + 4 * SZ_B)         // 91136
#define SM_TOT  (SM_BIAS + WC * 4)        // 94208

__device__ __forceinline__ void load_B_async(uint32_t sb, int s, int tid) {
    const int chunk = s >> 1, kh = s & 1;
    const uint32_t bbase = SM_B + (uint32_t)(s & 1) * (2 * SZ_B);
    for (int i = tid; i < 128 * 8; i += 256) {
        int c = i >> 3, seg = i & 7;
        size_t gsrc = (size_t)(chunk * 128 + c) * 128 + kh * 64 + seg * 8;
        uint32_t doff = (uint32_t)(c * (B_STRIDE * 2) + seg * 16);
        cp16(sb + bbase + doff, g_whT + gsrc);
        cp16(sb + bbase + SZ_B + doff, g_wlT + gsrc);
    }
}

__global__ void __launch_bounds__(256, 2) k_gemm_mma(const float* __restrict__ x,
                                                     float* __restrict__ out) {
    extern __shared__ char smem[];
    const uint32_t sb = smem_u32(smem);
    const int tid = threadIdx.x, wid = tid >> 5, lane = tid & 31;
    const int row0 = blockIdx.x * A_ROWS;

    load_B_async(sb, 0, tid);
    CP_COMMIT();

    float* sbias = (float*)(smem + SM_BIAS);
    for (int i = tid; i < WC; i += 256) sbias[i] = g_bias[i];

    // load A tile [64x128] as single fp16
    for (int i = tid; i < A_ROWS * 32; i += 256) {
        int r = i >> 5, k4 = (i & 31) << 2;
        int row = row0 + r;
        float4 v = (row < NN) ? __ldcs((const float4*)(x + (size_t)row * 128 + k4))
                              : make_float4(0.f, 0.f, 0.f, 0.f);
        __half2 h01 = __floats2half2_rn(v.x, v.y);
        __half2 h23 = __floats2half2_rn(v.z, v.w);
        uint32_t off = (uint32_t)(r * (A_STRIDE * 2) + k4 * 2);
        *(uint2*)(smem + SM_A + off) = make_uint2(*(uint32_t*)&h01, *(uint32_t*)&h23);
    }

    const int wm = wid & 1, wn = wid >> 1;       // warp grid 2 x 4
    const int rw = wm * 32, cw = wn * 32;        // warp tile 32 x 32
    const uint32_t a_off = (uint32_t)((rw + (lane & 15)) * (A_STRIDE * 2) + (lane >> 4) * 16);
    const uint32_t b_off = (uint32_t)((cw + (lane & 15)) * (B_STRIDE * 2) + (lane >> 4) * 16);
    const int trow = lane >> 2;
    const int tcol = (lane & 3) * 2;

    float acc[2][4][4];

    for (int s = 0; s < 12; ++s) {
        const int chunk = s >> 1, kh = s & 1;
        if (kh == 0) {
            #pragma unroll
            for (int i = 0; i < 2; ++i)
                #pragma unroll
                for (int j = 0; j < 4; ++j)
                    #pragma unroll
                    for (int q = 0; q < 4; ++q) acc[i][j][q] = 0.0f;
        }
        if (s + 1 < 12) {
            load_B_async(sb, s + 1, tid);
            CP_COMMIT();
            CP_WAIT1();
        } else {
            CP_WAIT0();
        }
        __syncthreads();

        const uint32_t sA = sb + SM_A + kh * 128;
        const uint32_t sBh = sb + SM_B + (uint32_t)(s & 1) * (2 * SZ_B);
        const uint32_t sBl = sBh + SZ_B;
        #pragma unroll
        for (int ks = 0; ks < 4; ++ks) {
            uint32_t a[2][4], bh[2][4], bl[2][4];
            #pragma unroll
            for (int i = 0; i < 2; ++i)
                ldsm4(a[i], sA + a_off + i * (16 * A_STRIDE * 2) + ks * 32);
            #pragma unroll
            for (int j16 = 0; j16 < 2; ++j16) {
                ldsm4(bh[j16], sBh + b_off + j16 * (16 * B_STRIDE * 2) + ks * 32);
                ldsm4(bl[j16], sBl + b_off + j16 * (16 * B_STRIDE * 2) + ks * 32);
            }
            #pragma unroll
            for (int i = 0; i < 2; ++i) {
                mma16816(acc[i][0], a[i], bh[0][0], bh[0][2]);
                mma16816(acc[i][1], a[i], bh[0][1], bh[0][3]);
                mma16816(acc[i][2], a[i], bh[1][0], bh[1][2]);
                mma16816(acc[i][3], a[i], bh[1][1], bh[1][3]);
                mma16816(acc[i][0], a[i], bl[0][0], bl[0][2]);
                mma16816(acc[i][1], a[i], bl[0][1], bl[0][3]);
                mma16816(acc[i][2], a[i], bl[1][0], bl[1][2]);
                mma16816(acc[i][3], a[i], bl[1][1], bl[1][3]);
            }
        }
        __syncthreads();

        if (kh == 1) {
            if (chunk == 3) {
                // skip -> out (fp32)
                #pragma unroll
                for (int i = 0; i < 2; ++i) {
                    int r = row0 + rw + i * 16 + trow;
                    #pragma unroll
                    for (int j = 0; j < 4; ++j) {
                        int G = 384 + cw + j * 8 + tcol;
                        float b0 = sbias[G], b1 = sbias[G + 1];
                        if (r < NN) {
                            float2 v = make_float2(acc[i][j][0] + b0, acc[i][j][1] + b1);
                            __stcs((float2*)(out + (size_t)r * 128 + (G - 384)), v);
                        }
                        if (r + 8 < NN) {
                            float2 v = make_float2(acc[i][j][2] + b0, acc[i][j][3] + b1);
                            __stcs((float2*)(out + (size_t)(r + 8) * 128 + (G - 384)), v);
                        }
                    }
                }
            } else {
                // q/p -> g_dst fp16, k/v -> g_src fp16
                __half* bp; int stride, sub;
                bool is_kv = (chunk == 1 || chunk == 2);
                if (chunk == 0)      { bp = g_dst; stride = 320; sub = 0;   }
                else if (is_kv)      { bp = g_src; stride = 256; sub = 128; }
                else                 { bp = g_dst; stride = 320; sub = 384; }
                #pragma unroll
                for (int i = 0; i < 2; ++i) {
                    int r = row0 + rw + i * 16 + trow;
                    #pragma unroll
                    for (int j = 0; j < 4; ++j) {
                        int G = chunk * 128 + cw + j * 8 + tcol;
                        if (G >= 704) continue;
                        float b0 = sbias[G], b1 = sbias[G + 1];
                        if (r < NN) {
                            __half2 hv = __floats2half2_rn(acc[i][j][0] + b0,
                                                           acc[i][j][1] + b1);
                            *(__half2*)(bp + (size_t)r * stride + (G - sub)) = hv;
                        }
                        if (r + 8 < NN) {
                            __half2 hv = __floats2half2_rn(acc[i][j][2] + b0,
                                                           acc[i][j][3] + b1);
                            *(__half2*)(bp + (size_t)(r + 8) * stride + (G - sub)) = hv;
                        }
                    }
                }
            }
        }
    }
}

// ------------------------- sort: histogram, scan, permute -------------------------
__global__ void k_hist(const int* __restrict__ ei) {
    int i = blockIdx.x * blockDim.x + threadIdx.x;
    if (i < EE) atomicAdd(&g_cnt[__ldcs(ei + EE + i)], 1);
}

__global__ void k_scan_a() {
    __shared__ int sm[256];
    int t = threadIdx.x;
    int gid = blockIdx.x * 256 + t;
    int val = (gid < NN) ? g_cnt[gid] : 0;
    sm[t] = val;
    __syncthreads();
    #pragma unroll
    for (int o = 1; o < 256; o <<= 1) {
        int add = (t >= o) ? sm[t - o] : 0;
        __syncthreads();
        sm[t] += add;
        __syncthreads();
    }
    if (gid < NN) g_off[gid] = sm[t] - val;
    if (t == 255) g_bsum[blockIdx.x] = sm[255];
}

__global__ void k_scan_b(int nblk) {
    __shared__ int sm[512];
    int t = threadIdx.x;
    int val = (t < nblk) ? g_bsum[t] : 0;
    sm[t] = val;
    __syncthreads();
    #pragma unroll
    for (int o = 1; o < 512; o <<= 1) {
        int add = (t >= o) ? sm[t - o] : 0;
        __syncthreads();
        sm[t] += add;
        __syncthreads();
    }
    if (t < nblk) g_bsum[t] = sm[t] - val;
}

__global__ void k_scan_c() {
    int gid = blockIdx.x * 256 + threadIdx.x;
    if (gid < NN) g_off[gid] += g_bsum[blockIdx.x];
    if (gid == 0) g_off[NN] = EE;
}

__global__ void k_permute(const int* __restrict__ ei, const float* __restrict__ lu,
                          const float* __restrict__ tv) {
    int i = blockIdx.x * blockDim.x + threadIdx.x;
    if (i >= EE) return;
    int d = __ldcs(ei + EE + i);
    int s = __ldcs(ei + i);
    int pos = g_off[d] + atomicAdd(&g_cursor[d], 1);
    g_esrc[pos] = s;
    g_eidx[pos] = i;
    g_erel[pos] = lu[s] - __ldcs(tv + i);
}

// ------------------------- kernel: fused edge pass + s@We epilogue -------------
// Persistent: 1480 CTAs, warp-per-node strided loop. We staged in smem per CTA.
// Direct softmax; fp16 k/v; no atomics; out written once (skip + attn + s@We).
#define EDGE_CTAS 1480
#define EDGE_WARPS (EDGE_CTAS * 8)
#define SM_EDGE ((96 * 128 + 8 * 192) * 4)   // We fp32 + per-warp s: 55296 B

__global__ void __launch_bounds__(256) k_edge(const float* __restrict__ msg,
                                              const float* __restrict__ time_w,
                                              const float* __restrict__ time_b,
                                              const float* __restrict__ We,
                                              float* __restrict__ out) {
    extern __shared__ float sme[];
    float* sWe = sme;                     // [96][128]
    const int tid = threadIdx.x, wid = tid >> 5, lane = tid & 31;

    for (int i = tid; i < 96 * 128 / 4; i += 256)
        ((float4*)sWe)[i] = ((const float4*)We)[i];
    __syncthreads();

    float* sS = sme + 96 * 128 + wid * 192;   // per-warp s[d][h]
    const float tww = time_w[lane], tbb = time_b[lane];
    const bool h0lane = (lane < 16);
    const int hsel = h0lane ? 0 : 1;

    for (int n = blockIdx.x * 8 + wid; n < NN; n += EDGE_WARPS) {
        const int off0 = g_off[n];
        const int deg = g_off[n + 1] - off0;
        if (deg == 0) continue;   // out already holds skip

        const __half* dp = g_dst + (size_t)n * 320;
        int2 qr = __ldcs((const int2*)(dp + lane * 4));
        float2 qa = __half22float2(*(const __half2*)&qr.x);
        float2 qb = __half22float2(*(const __half2*)&qr.y);
        const float4 q4 = make_float4(qa.x, qa.y, qb.x, qb.y);
        short ps0 = __ldcs((const short*)(dp + 128 + lane));
        short ps1 = __ldcs((const short*)(dp + 160 + lane));
        short ps2 = __ldcs((const short*)(dp + 192 + lane));
        short ps3 = __ldcs((const short*)(dp + 224 + lane));
        short ps4 = __ldcs((const short*)(dp + 256 + lane));
        short ps5 = __ldcs((const short*)(dp + 288 + lane));
        const float p00 = __half2float(*(__half*)&ps0), p01 = __half2float(*(__half*)&ps1);
        const float p02 = __half2float(*(__half*)&ps2), p10 = __half2float(*(__half*)&ps3);
        const float p11 = __half2float(*(__half*)&ps4), p12 = __half2float(*(__half*)&ps5);

        float den0 = 0.f, den1 = 0.f;
        float4 aco = make_float4(0.f, 0.f, 0.f, 0.f);
        float2 as0 = make_float2(0.f, 0.f), as1 = as0, as2 = as0;

        for (int eb = 0; eb < deg; eb += 4) {
            const int nb = deg - eb;
            int srcj[4], idxj[4];
            float relj[4], ea0[4], ea1[4], ea2[4], u0[4], u1[4];
            float4 k4[4], v4[4];
            #pragma unroll
            for (int j = 0; j < 4; ++j) {
                int pos = off0 + eb + ((j < nb) ? j : 0);
                srcj[j] = __ldcs(g_esrc + pos);
                idxj[j] = __ldcs(g_eidx + pos);
                relj[j] = __ldcs(g_erel + pos);
            }
            #pragma unroll
            for (int j = 0; j < 4; ++j) {
                const __half* sp = g_src + (size_t)srcj[j] * 256;
                uint2 kr = *(const uint2*)(sp + lane * 4);     // cached: reused ~8x
                uint2 vr = *(const uint2*)(sp + 128 + lane * 4);
                float2 ka = __half22float2(*(const __half2*)&kr.x);
                float2 kb = __half22float2(*(const __half2*)&kr.y);
                k4[j] = make_float4(ka.x, ka.y, kb.x, kb.y);
                float2 va = __half22float2(*(const __half2*)&vr.x);
                float2 vb = __half22float2(*(const __half2*)&vr.y);
                v4[j] = make_float4(va.x, va.y, vb.x, vb.y);
                ea1[j] = __ldcs(msg + (size_t)idxj[j] * 64 + lane);
                ea2[j] = __ldcs(msg + (size_t)idxj[j] * 64 + 32 + lane);
            }
            #pragma unroll
            for (int j = 0; j < 4; ++j) {
                float qk = q4.x * k4[j].x + q4.y * k4[j].y + q4.z * k4[j].z + q4.w * k4[j].w;
                ea0[j] = cosf(fmaf(relj[j], tww, tbb));
                u0[j] = ea0[j] * p00 + ea1[j] * p01 + ea2[j] * p02 + (h0lane ? qk : 0.f);
                u1[j] = ea0[j] * p10 + ea1[j] * p11 + ea2[j] * p12 + (h0lane ? 0.f : qk);
            }
            #pragma unroll
            for (int o = 16; o; o >>= 1) {
                #pragma unroll
                for (int j = 0; j < 4; ++j) {
                    u0[j] += __shfl_xor_sync(0xffffffffu, u0[j], o);
                    u1[j] += __shfl_xor_sync(0xffffffffu, u1[j], o);
                }
            }
            #pragma unroll
            for (int j = 0; j < 4; ++j) {
                if (j < nb) {
                    float e0 = __expf(u0[j] * 0.125f);
                    float e1 = __expf(u1[j] * 0.125f);
                    den0 += e0; den1 += e1;
                    float eh = h0lane ? e0 : e1;
                    aco.x = fmaf(v4[j].x, eh, aco.x);
                    aco.y = fmaf(v4[j].y, eh, aco.y);
                    aco.z = fmaf(v4[j].z, eh, aco.z);
                    aco.w = fmaf(v4[j].w, eh, aco.w);
                    as0.x = fmaf(ea0[j], e0, as0.x);  as0.y = fmaf(ea0[j], e1, as0.y);
                    as1.x = fmaf(ea1[j], e0, as1.x);  as1.y = fmaf(ea1[j], e1, as1.y);
                    as2.x = fmaf(ea2[j], e0, as2.x);  as2.y = fmaf(ea2[j], e1, as2.y);
                }
            }
        }

        float i0 = 1.0f / (den0 + 1e-16f);
        float i1 = 1.0f / (den1 + 1e-16f);

        // stage normalized s into per-warp smem: sS[d*2 + h]
        sS[lane * 2 + 0]        = as0.x * i0;  sS[lane * 2 + 1]        = as0.y * i1;
        sS[(lane + 32) * 2 + 0] = as1.x * i0;  sS[(lane + 32) * 2 + 1] = as1.y * i1;
        sS[(lane + 64) * 2 + 0] = as2.x * i0;  sS[(lane + 64) * 2 + 1] = as2.y * i1;
        __syncwarp();

        // matvec: r[c] = sum_d s[d][h(c)] * We[d][c], cols c = lane*4..lane*4+3
        unsigned long long a01 = 0ULL, a23 = 0ULL;
        const float4* w4 = (const float4*)sWe + lane;
        #pragma unroll 8
        for (int d = 0; d < 96; ++d) {
            float sv = sS[d * 2 + hsel];
            float4 w = w4[d * 32];
            unsigned long long svp = pk2(sv, sv);
            a01 = ffma2(pk2(w.x, w.y), svp, a01);
            a23 = ffma2(pk2(w.z, w.w), svp, a23);
        }
        __syncwarp();
        float2 r01 = upk2(a01), r23 = upk2(a23);

        float ih = h0lane ? i0 : i1;
        float4* op = (float4*)(out + (size_t)n * 128 + lane * 4);
        float4 o4 = __ldcs(op);
        o4.x += aco.x * ih + r01.x;
        o4.y += aco.y * ih + r01.y;
        o4.z += aco.z * ih + r23.x;
        o4.w += aco.w * ih + r23.y;
        __stcs(op, o4);
    }
}

// ------------------------- launch -------------------------
extern "C" void kernel_launch(void* const* d_in, const int* in_sizes, int n_in,
                              void* d_out, int out_size) {
    const float* x   = (const float*)d_in[0];
    const float* lu  = (const float*)d_in[1];
    const float* tv  = (const float*)d_in[2];
    const float* msg = (const float*)d_in[3];
    const int*   ei  = (const int*)d_in[4];
    const float* tw  = (const float*)d_in[5];
    const float* tb  = (const float*)d_in[6];
    const float* Wq  = (const float*)d_in[7];
    const float* bq  = (const float*)d_in[8];
    const float* Wk  = (const float*)d_in[9];
    const float* bk  = (const float*)d_in[10];
    const float* Wv  = (const float*)d_in[11];
    const float* bv  = (const float*)d_in[12];
    const float* We  = (const float*)d_in[13];
    const float* Ws  = (const float*)d_in[14];
    const float* bs  = (const float*)d_in[15];
    float* out = (float*)d_out;

    static cudaStream_t s2 = nullptr;
    static cudaEvent_t evFork = nullptr, evJoin = nullptr;
    if (!s2) {
        cudaFuncSetAttribute(k_gemm_mma, cudaFuncAttributeMaxDynamicSharedMemorySize, SM_TOT);
        cudaFuncSetAttribute(k_edge, cudaFuncAttributeMaxDynamicSharedMemorySize, SM_EDGE);
        cudaStreamCreateWithFlags(&s2, cudaStreamNonBlocking);
        cudaEventCreateWithFlags(&evFork, cudaEventDisableTiming);
        cudaEventCreateWithFlags(&evJoin, cudaEventDisableTiming);
    }

    const int nblk = (NN + 255) / 256;  // 391

    // Fork s2 off the main stream.
    cudaEventRecord(evFork, 0);
    cudaStreamWaitEvent(s2, evFork, 0);

    // Submission order chosen so index 3 = k_gemm_mma (ncu -s5 profiles idx 3).
    k_prep<<<128, 256>>>(Wq, bq, Wk, bk, Wv, bv, We, Ws, bs);         // idx 0 (main)
    k_init<<<nblk, 256, 0, s2>>>();                                   // idx 1 (s2)
    k_hist<<<(EE + 255) / 256, 256, 0, s2>>>(ei);                     // idx 2 (s2)
    k_gemm_mma<<<(NN + A_ROWS - 1) / A_ROWS, 256, SM_TOT>>>(x, out);  // idx 3 (main)
    k_scan_a<<<nblk, 256, 0, s2>>>();                                 // idx 4
    k_scan_b<<<1, 512, 0, s2>>>(nblk);                                // idx 5
    k_scan_c<<<nblk, 256, 0, s2>>>();                                 // idx 6
    k_permute<<<(EE + 255) / 256, 256, 0, s2>>>(ei, lu, tv);          // idx 7
    cudaEventRecord(evJoin, s2);

    // Join, then fused edge pass (attn + skip + s@We epilogue).
    cudaStreamWaitEvent(0, evJoin, 0);
    k_edge<<<EDGE_CTAS, 256, SM_EDGE>>>(msg, tw, tb, We, out);        // idx 8
}